// round 7
// baseline (speedup 1.0000x reference)
#include <cuda_runtime.h>
#include <cuda_bf16.h>
#include <math.h>
#include <stdint.h>

// ---------------- constants ----------------
#define BATCH   128
#define DIM     384
#define RES     14
#define NPIX    196
#define KEY_DIM 32
#define NHEADS  12
#define NH_KD   384
#define DH      1536
#define HQKV    2304
#define BN_EPS  1e-5f
#define NPAD    208     // NPIX padded to mult of 16

// ---------------- scratch ----------------
__device__ float g_qkv [ (size_t)BATCH * 768 * NPIX ];            // q+k fp32 only
__device__ float g_qdw [ (size_t)BATCH * NH_KD * NPIX ];
__device__ float g_bias[ (size_t)NHEADS * NPIX * NPIX ];

__device__ __nv_bfloat16 g_qw_h[ HQKV * DIM ],  g_qw_l[ HQKV * DIM ];
__device__ __nv_bfloat16 g_pw_h[ DIM * DH ],    g_pw_l[ DIM * DH ];
__device__ __nv_bfloat16 g_xT_h[ (size_t)BATCH * NPIX * DIM ],  g_xT_l[ (size_t)BATCH * NPIX * DIM ];
__device__ __nv_bfloat16 g_v_h [ (size_t)BATCH * DH * NPAD ],   g_v_l [ (size_t)BATCH * DH * NPAD ];
__device__ __nv_bfloat16 g_p_h [ (size_t)BATCH * NHEADS * NPIX * NPAD ],
                         g_p_l [ (size_t)BATCH * NHEADS * NPIX * NPAD ];
__device__ __nv_bfloat16 g_at_h[ (size_t)BATCH * NPIX * DH ],   g_at_l[ (size_t)BATCH * NPIX * DH ];

// ---------------- helpers ----------------
__device__ __forceinline__ uint32_t smem_u32(const void* p) {
    uint32_t a;
    asm("{ .reg .u64 t; cvta.to.shared.u64 t, %1; cvt.u32.u64 %0, t; }"
        : "=r"(a) : "l"(p));
    return a;
}
#define LDSM4(r, addr) \
    asm volatile("ldmatrix.sync.aligned.m8n8.x4.shared.b16 {%0,%1,%2,%3}, [%4];" \
        : "=r"((r)[0]), "=r"((r)[1]), "=r"((r)[2]), "=r"((r)[3]) : "r"(addr))
#define MMA_BF16(d, a, bb) \
    asm volatile("mma.sync.aligned.m16n8k16.row.col.f32.bf16.bf16.f32 " \
        "{%0,%1,%2,%3}, {%4,%5,%6,%7}, {%8,%9}, {%0,%1,%2,%3};" \
        : "+f"((d)[0]), "+f"((d)[1]), "+f"((d)[2]), "+f"((d)[3]) \
        : "r"((a)[0]), "r"((a)[1]), "r"((a)[2]), "r"((a)[3]), \
          "r"((bb)[0]), "r"((bb)[1]))
#define CP_ASYNC16(dst, src, sz) \
    asm volatile("cp.async.cg.shared.global [%0], [%1], 16, %2;" \
                 :: "r"(dst), "l"(src), "r"(sz))
#define CP_COMMIT() asm volatile("cp.async.commit_group;" ::: "memory")
#define CP_WAIT(n)  asm volatile("cp.async.wait_group %0;" :: "n"(n) : "memory")

__device__ __forceinline__ void split_bf16(float v, __nv_bfloat16& h, __nv_bfloat16& l) {
    h = __float2bfloat16(v);
    l = __float2bfloat16(v - __bfloat162float(h));
}

// ================= pipelined bf16-plane GEMM =================
// C[m,n] = act(BN_m( sum_k A[m,k]*B[n,k] ))  -- both operands k-contig planes.
// CTA 128x128, 8 warps (4m x 2n), K-chunk 16, 2-stage cp.async.
// Per-warp jlim skips MMA/LDSM for column tiles entirely beyond nrowsB (=N).
// OUTMODE: 0 = fp32 out; 1 = fp32 if m0<mSplit else bf16 planes (pad cols zeroed);
//          2 = transposed bf16 planes  C^T[n][zi*128 + m]  (K5 -> attT).
template<int OUTMODE, bool HASBN, bool RELU>
__global__ void __launch_bounds__(256, 2)
gemm_bf16(const __nv_bfloat16* __restrict__ Ah, const __nv_bfloat16* __restrict__ Al,
          const __nv_bfloat16* __restrict__ Bh, const __nv_bfloat16* __restrict__ Bl,
          float* __restrict__ Cf, __nv_bfloat16* __restrict__ Ch, __nv_bfloat16* __restrict__ Cl,
          int nchunks, int lda, int ldb,
          long aOuter, long aInner, int innerCnt,
          long bStride, long cfStride, long cpStride,
          int ldcF, int ldcP, int nrowsB, int mSplit,
          const float* __restrict__ bng, const float* __restrict__ bnb,
          const float* __restrict__ bnm, const float* __restrict__ bnv)
{
    constexpr int KP = 24;
    constexpr uint32_t PL = 128 * KP * 2;          // plane bytes
    __shared__ __align__(16) __nv_bfloat16 smbuf[2 * 4 * 128 * KP];  // 49152 B

    const int tid  = threadIdx.x;
    const int wid  = tid >> 5;
    const int lane = tid & 31;
    const int warp_m = wid & 3;
    const int warp_n = wid >> 2;
    const int n0 = blockIdx.x * 128;
    const int m0 = blockIdx.y * 128;
    const int z  = blockIdx.z;
    const int zb = z / innerCnt, zi = z - zb * innerCnt;

    const __nv_bfloat16* Agh = Ah + (size_t)zb * aOuter + (size_t)zi * aInner + (size_t)m0 * lda;
    const __nv_bfloat16* Agl = Al + (size_t)zb * aOuter + (size_t)zi * aInner + (size_t)m0 * lda;
    const __nv_bfloat16* Bgh = Bh + (size_t)z * bStride;
    const __nv_bfloat16* Bgl = Bl + (size_t)z * bStride;

    const uint32_t smb = smem_u32(smbuf);

    // valid j-tile count for this warp (skip column tiles fully beyond N)
    int jlim = nrowsB - (n0 + warp_n * 64);
    jlim = jlim <= 0 ? 0 : ((jlim + 7) >> 3);
    if (jlim > 8) jlim = 8;

    // --- staging: 4 x cp.async 16B per thread per chunk
    auto stage = [&](int ch, int s) {
        const int k0 = ch * 16;
#pragma unroll
        for (int i = 0; i < 4; i++) {
            int c    = i * 256 + tid;
            int p    = c >> 8;           // plane 0..3
            int row  = (c >> 1) & 127;
            int half = c & 1;
            uint32_t dst = smb + (uint32_t)(s * 4 + p) * PL + (uint32_t)(row * KP + half * 8) * 2;
            const __nv_bfloat16* src;
            unsigned sz = 16;
            if (p < 2) {
                src = (p == 0 ? Agh : Agl) + (size_t)row * lda + k0 + half * 8;
            } else {
                int rowg = n0 + row;
                bool ok = rowg < nrowsB;
                if (!ok) { rowg = 0; sz = 0; }
                src = (p == 2 ? Bgh : Bgl) + (size_t)rowg * ldb + k0 + half * 8;
            }
            CP_ASYNC16(dst, src, sz);
        }
        CP_COMMIT();
    };

    float acc[2][8][4];
#pragma unroll
    for (int t = 0; t < 2; t++)
#pragma unroll
        for (int j = 0; j < 8; j++)
#pragma unroll
            for (int c = 0; c < 4; c++) acc[t][j][c] = 0.f;

    stage(0, 0);

    for (int ch = 0; ch < nchunks; ch++) {
        const int s = ch & 1;
        if (ch + 1 < nchunks) { stage(ch + 1, s ^ 1); CP_WAIT(1); }
        else                  { CP_WAIT(0); }
        __syncthreads();

        const uint32_t base = smb + (uint32_t)s * 4 * PL;
        const uint32_t aHi = base, aLo = base + PL, bHi = base + 2 * PL, bLo = base + 3 * PL;

        uint32_t a_hi[2][4], a_lo[2][4];
#pragma unroll
        for (int t = 0; t < 2; t++) {
            int row = warp_m * 32 + t * 16 + (lane & 15);
            int col = (lane >> 4) << 3;
            uint32_t off = (uint32_t)(row * KP + col) * 2;
            LDSM4(a_hi[t], aHi + off);
            LDSM4(a_lo[t], aLo + off);
        }
        int nrow = warp_n * 64 + (lane & 7) + ((lane >> 4) << 3);
        int bcol = ((lane >> 3) & 1) << 3;
        uint32_t boff = (uint32_t)(nrow * KP + bcol) * 2;

        uint32_t b[8][2];
#pragma unroll
        for (int j = 0; j < 4; j++) {
            if (2 * j < jlim) {
                uint32_t r[4];
                LDSM4(r, bHi + boff + (uint32_t)(j * 16 * KP) * 2);
                b[2 * j][0] = r[0]; b[2 * j][1] = r[1];
                b[2 * j + 1][0] = r[2]; b[2 * j + 1][1] = r[3];
            }
        }
#pragma unroll
        for (int t = 0; t < 2; t++)
#pragma unroll
            for (int j = 0; j < 8; j++)
                if (j < jlim) MMA_BF16(acc[t][j], a_hi[t], b[j]);
#pragma unroll
        for (int t = 0; t < 2; t++)
#pragma unroll
            for (int j = 0; j < 8; j++)
                if (j < jlim) MMA_BF16(acc[t][j], a_lo[t], b[j]);
#pragma unroll
        for (int j = 0; j < 4; j++) {
            if (2 * j < jlim) {
                uint32_t r[4];
                LDSM4(r, bLo + boff + (uint32_t)(j * 16 * KP) * 2);
                b[2 * j][0] = r[0]; b[2 * j][1] = r[1];
                b[2 * j + 1][0] = r[2]; b[2 * j + 1][1] = r[3];
            }
        }
#pragma unroll
        for (int t = 0; t < 2; t++)
#pragma unroll
            for (int j = 0; j < 8; j++)
                if (j < jlim) MMA_BF16(acc[t][j], a_hi[t], b[j]);

        __syncthreads();   // buffer reuse safety before next stage() overwrites
    }

    // ---------------- epilogues ----------------
    if (OUTMODE == 0 || OUTMODE == 1) {
        const bool isF32 = (OUTMODE == 0) || (m0 < mSplit);
#pragma unroll
        for (int t = 0; t < 2; t++) {
            int r0 = m0 + warp_m * 32 + t * 16 + (lane >> 2);
            int r1 = r0 + 8;
            float s0 = 1.f, h0 = 0.f, s1 = 1.f, h1 = 0.f;
            if (HASBN) {
                float a = bng[r0] * rsqrtf(bnv[r0] + BN_EPS);
                s0 = a; h0 = bnb[r0] - bnm[r0] * a;
                float c = bng[r1] * rsqrtf(bnv[r1] + BN_EPS);
                s1 = c; h1 = bnb[r1] - bnm[r1] * c;
            }
#pragma unroll
            for (int j = 0; j < 8; j++) {
                int nn = n0 + warp_n * 64 + j * 8 + 2 * (lane & 3);
                float v0 = acc[t][j][0] * s0 + h0;
                float v1 = acc[t][j][1] * s0 + h0;
                float v2 = acc[t][j][2] * s1 + h1;
                float v3 = acc[t][j][3] * s1 + h1;
                if (RELU) {
                    v0 = fmaxf(v0, 0.f); v1 = fmaxf(v1, 0.f);
                    v2 = fmaxf(v2, 0.f); v3 = fmaxf(v3, 0.f);
                }
                if (isF32) {
                    if (nn < NPIX) {
                        *(float2*)(Cf + (size_t)z * cfStride + (size_t)r0 * ldcF + nn) = make_float2(v0, v1);
                        *(float2*)(Cf + (size_t)z * cfStride + (size_t)r1 * ldcF + nn) = make_float2(v2, v3);
                    }
                } else {
                    if (nn < NPAD) {
                        if (nn >= NPIX) { v0 = v1 = v2 = v3 = 0.f; }
                        __nv_bfloat16 ha, la, hb, lb;
                        size_t p0 = (size_t)z * cpStride + (size_t)(r0 - mSplit) * ldcP + nn;
                        size_t p1 = (size_t)z * cpStride + (size_t)(r1 - mSplit) * ldcP + nn;
                        split_bf16(v0, ha, la); split_bf16(v1, hb, lb);
                        *(__nv_bfloat162*)(Ch + p0) = __nv_bfloat162(ha, hb);
                        *(__nv_bfloat162*)(Cl + p0) = __nv_bfloat162(la, lb);
                        split_bf16(v2, ha, la); split_bf16(v3, hb, lb);
                        *(__nv_bfloat162*)(Ch + p1) = __nv_bfloat162(ha, hb);
                        *(__nv_bfloat162*)(Cl + p1) = __nv_bfloat162(la, lb);
                    }
                }
            }
        }
    } else {
        // OUTMODE 2: transposed plane output via smem (reuse stage buffer)
        __nv_bfloat16* ep = smbuf;   // [128 i][136 d]
#pragma unroll
        for (int plane = 0; plane < 2; plane++) {
            __syncthreads();
#pragma unroll
            for (int t = 0; t < 2; t++) {
                int d0 = warp_m * 32 + t * 16 + (lane >> 2);
                int d1 = d0 + 8;
#pragma unroll
                for (int j = 0; j < 8; j++) {
                    int il = warp_n * 64 + j * 8 + 2 * (lane & 3);
                    float v[4];
#pragma unroll
                    for (int c = 0; c < 4; c++) {
                        float x = acc[t][j][c];
                        v[c] = RELU ? fmaxf(x, 0.f) : x;
                    }
                    __nv_bfloat16 o[4];
#pragma unroll
                    for (int c = 0; c < 4; c++) {
                        __nv_bfloat16 h = __float2bfloat16(v[c]);
                        o[c] = plane == 0 ? h : __float2bfloat16(v[c] - __bfloat162float(h));
                    }
                    ep[il * 136 + d0]       = o[0];
                    ep[(il + 1) * 136 + d0] = o[1];
                    ep[il * 136 + d1]       = o[2];
                    ep[(il + 1) * 136 + d1] = o[3];
                }
            }
            __syncthreads();
            __nv_bfloat16* dst = (plane == 0 ? Ch : Cl) + (size_t)zb * cpStride + (size_t)zi * 128;
            for (int c2 = tid; c2 < 2048; c2 += 256) {
                int row = c2 >> 4, off = (c2 & 15) * 8;
                int i = n0 + row;
                if (i < NPIX) {
                    uint4 val = *(uint4*)(ep + row * 136 + off);
                    *(uint4*)(dst + (size_t)i * ldcP + off) = val;
                }
            }
        }
    }
}

// ---------------- pre-convert kernels ----------------
__global__ void convert_weights(const float* __restrict__ qw, const float* __restrict__ pw)
{
    int i = blockIdx.x * 256 + threadIdx.x;
    if (i < HQKV * DIM) split_bf16(qw[i], g_qw_h[i], g_qw_l[i]);
    if (i < DIM * DH)   split_bf16(pw[i], g_pw_h[i], g_pw_l[i]);
}

__global__ void transpose_x(const float* __restrict__ x)
{
    __shared__ float t[32][33];
    int p0 = blockIdx.x * 32, c0 = blockIdx.y * 32, b = blockIdx.z;
    for (int r = threadIdx.y; r < 32; r += 8) {
        int p = p0 + threadIdx.x;
        t[r][threadIdx.x] = (p < NPIX) ? x[((size_t)b * DIM + c0 + r) * NPIX + p] : 0.f;
    }
    __syncthreads();
    for (int r = threadIdx.y; r < 32; r += 8) {
        int p = p0 + r, c = c0 + threadIdx.x;
        if (p < NPIX) {
            size_t o = ((size_t)b * NPIX + p) * DIM + c;
            split_bf16(t[threadIdx.x][r], g_xT_h[o], g_xT_l[o]);
        }
    }
}

// ---------------- dwconv + BN: one block per (channel, batch) ---------------
__global__ void __launch_bounds__(224, 8)
dwconv_bn(const float* __restrict__ w,
          const float* __restrict__ bng,
          const float* __restrict__ bnb,
          const float* __restrict__ bnm,
          const float* __restrict__ bnv)
{
    const int c = blockIdx.x;
    const int b = blockIdx.y;
    __shared__ float t[NPIX];
    __shared__ float wgt[9];
    __shared__ float sBN[2];

    const float* src = g_qkv + (size_t)b * 768 * NPIX + (size_t)c * NPIX;
    int tid = threadIdx.x;
    if (tid < NPIX) t[tid] = src[tid];
    if (tid < 9)    wgt[tid] = w[c * 9 + tid];
    if (tid == 0) {
        float s = bng[c] * rsqrtf(bnv[c] + BN_EPS);
        sBN[0] = s;
        sBN[1] = bnb[c] - bnm[c] * s;
    }
    __syncthreads();

    if (tid < NPIX) {
        int y = tid / RES, x = tid - y * RES;
        float acc = 0.f;
#pragma unroll
        for (int ky = 0; ky < 3; ky++) {
            int yy = y + ky - 1;
            if (yy < 0 || yy >= RES) continue;
#pragma unroll
            for (int kx = 0; kx < 3; kx++) {
                int xx = x + kx - 1;
                if (xx < 0 || xx >= RES) continue;
                acc += t[yy * RES + xx] * wgt[ky * 3 + kx];
            }
        }
        g_qdw[((size_t)b * NH_KD + c) * NPIX + tid] = acc * sBN[0] + sBN[1];
    }
}

// ---------------- bias gather ----------------
__global__ void bias_gather(const float* __restrict__ ab, const int* __restrict__ idxs)
{
    int idx = blockIdx.x * 256 + threadIdx.x;
    if (idx >= NHEADS * NPIX * NPIX) return;
    int h  = idx / (NPIX * NPIX);
    int ij = idx % (NPIX * NPIX);
    g_bias[idx] = ab[h * NPIX + idxs[ij]];
}

// ---------------- softmax: pipelined QK + P bf16 planes ---------------------
__global__ void attn_softmax(void)
{
    const int h = blockIdx.x;
    const int b = blockIdx.y;
    __shared__ float k_s[32 * 224];

    const float* qg = g_qdw + (size_t)b * NH_KD * NPIX + (size_t)h * KEY_DIM * NPIX;
    const float* kg = g_qkv + (size_t)b * 768 * NPIX + (size_t)(NH_KD + h * KEY_DIM) * NPIX;

    for (int idx = threadIdx.x; idx < 32 * 224; idx += 256) {
        int d = idx / 224, j = idx % 224;
        k_s[idx] = (j < NPIX) ? kg[d * NPIX + j] : 0.f;
    }
    __syncthreads();

    const int w    = threadIdx.x >> 5;
    const int lane = threadIdx.x & 31;
    const float* bh = g_bias + (size_t)h * NPIX * NPIX;
    const size_t zoff = ((size_t)b * NHEADS + h) * NPIX * NPAD;
    const float scale = 0.17677669529663687f;

    for (int i0 = w * 8; i0 < NPIX; i0 += 64) {
        float q_reg[8];
#pragma unroll
        for (int r = 0; r < 8; r++) {
            int i = i0 + r;
            q_reg[r] = (i < NPIX) ? qg[(size_t)lane * NPIX + i] : 0.f;
        }

        float s[8][7];
#pragma unroll
        for (int r = 0; r < 8; r++)
#pragma unroll
            for (int m = 0; m < 7; m++) s[r][m] = 0.f;

        // software-pipelined: prefetch kv/qv for d+1 while FMA-ing d
        float kvA[7], qvA[8];
#pragma unroll
        for (int m = 0; m < 7; m++) kvA[m] = k_s[lane + m * 32];
#pragma unroll
        for (int r = 0; r < 8; r++) qvA[r] = __shfl_sync(0xffffffffu, q_reg[r], 0);

        for (int d = 0; d < 32; d++) {
            float kvB[7], qvB[8];
            if (d < 31) {
#pragma unroll
                for (int m = 0; m < 7; m++) kvB[m] = k_s[(d + 1) * 224 + lane + m * 32];
#pragma unroll
                for (int r = 0; r < 8; r++) qvB[r] = __shfl_sync(0xffffffffu, q_reg[r], d + 1);
            }
#pragma unroll
            for (int m = 0; m < 7; m++)
#pragma unroll
                for (int r = 0; r < 8; r++) s[r][m] += qvA[r] * kvA[m];
#pragma unroll
            for (int m = 0; m < 7; m++) kvA[m] = kvB[m];
#pragma unroll
            for (int r = 0; r < 8; r++) qvA[r] = qvB[r];
        }

#pragma unroll
        for (int r = 0; r < 8; r++) {
            int i = i0 + r;
            if (i >= NPIX) break;
            float sv[7];
            float mx = -1e30f;
#pragma unroll
            for (int m = 0; m < 7; m++) {
                int j = lane + m * 32;
                float val = (j < NPIX) ? s[r][m] * scale + bh[(size_t)i * NPIX + j]
                                       : -1e30f;
                sv[m] = val;
                mx = fmaxf(mx, val);
            }
#pragma unroll
            for (int off = 16; off; off >>= 1)
                mx = fmaxf(mx, __shfl_xor_sync(0xffffffffu, mx, off));
            float sum = 0.f;
#pragma unroll
            for (int m = 0; m < 7; m++) {
                sv[m] = __expf(sv[m] - mx);
                sum += sv[m];
            }
#pragma unroll
            for (int off = 16; off; off >>= 1)
                sum += __shfl_xor_sync(0xffffffffu, sum, off);
            float inv = 1.f / sum;
#pragma unroll
            for (int m = 0; m < 7; m++) {
                int j = lane + m * 32;
                if (j < NPIX) {
                    float val = sv[m] * inv;
                    __nv_bfloat16 hh, ll;
                    split_bf16(val, hh, ll);
                    g_p_h[zoff + (size_t)i * NPAD + j] = hh;
                    g_p_l[zoff + (size_t)i * NPAD + j] = ll;
                } else if (j < NPAD) {
                    g_p_h[zoff + (size_t)i * NPAD + j] = __float2bfloat16(0.f);
                    g_p_l[zoff + (size_t)i * NPAD + j] = __float2bfloat16(0.f);
                }
            }
        }
    }
}

// ---------------- launch ----------------------------------------------------
extern "C" void kernel_launch(void* const* d_in, const int* in_sizes, int n_in,
                              void* d_out, int out_size)
{
    const float* x      = (const float*)d_in[0];
    const float* qkv_w  = (const float*)d_in[1];
    const float* qkv_g  = (const float*)d_in[2];
    const float* qkv_b  = (const float*)d_in[3];
    const float* qkv_m  = (const float*)d_in[4];
    const float* qkv_v  = (const float*)d_in[5];
    const float* dw_w   = (const float*)d_in[6];
    const float* dw_g   = (const float*)d_in[7];
    const float* dw_b   = (const float*)d_in[8];
    const float* dw_m   = (const float*)d_in[9];
    const float* dw_v   = (const float*)d_in[10];
    const float* proj_w = (const float*)d_in[11];
    const float* proj_g = (const float*)d_in[12];
    const float* proj_b = (const float*)d_in[13];
    const float* proj_m = (const float*)d_in[14];
    const float* proj_v = (const float*)d_in[15];
    const float* ab     = (const float*)d_in[16];
    const int*   bidx   = (const int*)d_in[17];
    float* out = (float*)d_out;

    float* qkvf;  cudaGetSymbolAddress((void**)&qkvf,  g_qkv);
    __nv_bfloat16 *qwh, *qwl, *pwh, *pwl, *xth, *xtl, *vh, *vl, *ph, *pl, *ath, *atl;
    cudaGetSymbolAddress((void**)&qwh, g_qw_h);  cudaGetSymbolAddress((void**)&qwl, g_qw_l);
    cudaGetSymbolAddress((void**)&pwh, g_pw_h);  cudaGetSymbolAddress((void**)&pwl, g_pw_l);
    cudaGetSymbolAddress((void**)&xth, g_xT_h);  cudaGetSymbolAddress((void**)&xtl, g_xT_l);
    cudaGetSymbolAddress((void**)&vh,  g_v_h);   cudaGetSymbolAddress((void**)&vl,  g_v_l);
    cudaGetSymbolAddress((void**)&ph,  g_p_h);   cudaGetSymbolAddress((void**)&pl,  g_p_l);
    cudaGetSymbolAddress((void**)&ath, g_at_h);  cudaGetSymbolAddress((void**)&atl, g_at_l);

    // P0: convert weights + transpose/convert x
    convert_weights<<<(HQKV * DIM + 255) / 256, 256>>>(qkv_w, proj_w);
    transpose_x<<<dim3(7, 12, BATCH), dim3(32, 8)>>>(x);

    // K1: qkv = BN(W_qkv @ x)  -> fp32 rows<768, V planes rows>=768
    gemm_bf16<1, true, false><<<dim3(2, HQKV / 128, BATCH), 256>>>(
        qwh, qwl, xth, xtl,
        qkvf, vh, vl,
        DIM / 16, DIM, DIM,
        0L, 0L, 1,
        (long)NPIX * DIM, (long)768 * NPIX, (long)DH * NPAD,
        NPIX, NPAD, NPIX, 768,
        qkv_g, qkv_b, qkv_m, qkv_v);

    // K2: q <- BN(dwconv3x3(q))
    dwconv_bn<<<dim3(NH_KD, BATCH), 224>>>(dw_w, dw_g, dw_b, dw_m, dw_v);

    // K3: bias gather
    {
        int total = NHEADS * NPIX * NPIX;
        bias_gather<<<(total + 255) / 256, 256>>>(ab, bidx);
    }
    // K4: softmax -> P planes
    attn_softmax<<<dim3(NHEADS, BATCH), 256>>>();

    // K5: attT planes = relu(V @ P^T)^T  (per b,h)
    gemm_bf16<2, false, true><<<dim3(2, 1, BATCH * NHEADS), 256>>>(
        vh, vl, ph, pl,
        nullptr, ath, atl,
        NPAD / 16, NPAD, NPAD,
        (long)DH * NPAD, (long)128 * NPAD, NHEADS,
        (long)NPIX * NPAD, 0L, (long)NPIX * DH,
        0, DH, NPIX, 0,
        nullptr, nullptr, nullptr, nullptr);

    // K6: out = BN(W_proj @ att)  (B = attT planes, k-contig)
    gemm_bf16<0, true, false><<<dim3(2, DIM / 128, BATCH), 256>>>(
        pwh, pwl, ath, atl,
        out, nullptr, nullptr,
        DH / 16, DH, DH,
        0L, 0L, 1,
        (long)NPIX * DH, (long)DIM * NPIX, 0L,
        NPIX, 0, NPIX, DIM,
        proj_g, proj_b, proj_m, proj_v);
}

// round 8
// speedup vs baseline: 1.1360x; 1.1360x over previous
#include <cuda_runtime.h>
#include <cuda_bf16.h>
#include <math.h>
#include <stdint.h>

// ---------------- constants ----------------
#define BATCH   128
#define DIM     384
#define RES     14
#define NPIX    196
#define KEY_DIM 32
#define NHEADS  12
#define NH_KD   384
#define DH      1536
#define HQKV    2304
#define BN_EPS  1e-5f
#define NPAD    208     // NPIX padded to mult of 16

// ---------------- scratch ----------------
__device__ float g_qkv [ (size_t)BATCH * 768 * NPIX ];            // q+k fp32 only
__device__ float g_qdw [ (size_t)BATCH * NH_KD * NPIX ];
__device__ float g_bias[ (size_t)NHEADS * NPIX * NPIX ];

__device__ __nv_bfloat16 g_qw_h[ HQKV * DIM ],  g_qw_l[ HQKV * DIM ];
__device__ __nv_bfloat16 g_pw_h[ DIM * DH ],    g_pw_l[ DIM * DH ];
__device__ __nv_bfloat16 g_xT_h[ (size_t)BATCH * NPIX * DIM ],  g_xT_l[ (size_t)BATCH * NPIX * DIM ];
__device__ __nv_bfloat16 g_v_h [ (size_t)BATCH * DH * NPAD ],   g_v_l [ (size_t)BATCH * DH * NPAD ];
__device__ __nv_bfloat16 g_p_h [ (size_t)BATCH * NHEADS * NPIX * NPAD ],
                         g_p_l [ (size_t)BATCH * NHEADS * NPIX * NPAD ];
__device__ __nv_bfloat16 g_at_h[ (size_t)BATCH * NPIX * DH ],   g_at_l[ (size_t)BATCH * NPIX * DH ];

// ---------------- helpers ----------------
__device__ __forceinline__ uint32_t smem_u32(const void* p) {
    uint32_t a;
    asm("{ .reg .u64 t; cvta.to.shared.u64 t, %1; cvt.u32.u64 %0, t; }"
        : "=r"(a) : "l"(p));
    return a;
}
#define LDSM4(r, addr) \
    asm volatile("ldmatrix.sync.aligned.m8n8.x4.shared.b16 {%0,%1,%2,%3}, [%4];" \
        : "=r"((r)[0]), "=r"((r)[1]), "=r"((r)[2]), "=r"((r)[3]) : "r"(addr))
#define MMA_BF16(d, a, bb) \
    asm volatile("mma.sync.aligned.m16n8k16.row.col.f32.bf16.bf16.f32 " \
        "{%0,%1,%2,%3}, {%4,%5,%6,%7}, {%8,%9}, {%0,%1,%2,%3};" \
        : "+f"((d)[0]), "+f"((d)[1]), "+f"((d)[2]), "+f"((d)[3]) \
        : "r"((a)[0]), "r"((a)[1]), "r"((a)[2]), "r"((a)[3]), \
          "r"((bb)[0]), "r"((bb)[1]))
#define CP_ASYNC16(dst, src, sz) \
    asm volatile("cp.async.cg.shared.global [%0], [%1], 16, %2;" \
                 :: "r"(dst), "l"(src), "r"(sz))
#define CP_COMMIT() asm volatile("cp.async.commit_group;" ::: "memory")
#define CP_WAIT(n)  asm volatile("cp.async.wait_group %0;" :: "n"(n) : "memory")

__device__ __forceinline__ void split_bf16(float v, __nv_bfloat16& h, __nv_bfloat16& l) {
    h = __float2bfloat16(v);
    l = __float2bfloat16(v - __bfloat162float(h));
}

// ================= pipelined bf16-plane GEMM =================
// C[m,n] = act(BN_m( sum_k A[m,k]*B[n,k] ))  -- both operands k-contig planes.
// CTA 128x128, 8 warps (4m x 2n), K-chunk 16, 2-stage cp.async.
// Warp-uniform full/partial branch: full warps run the exact unguarded path,
// partial warps (column tiles beyond N) run only jlim tiles.
// OUTMODE: 0 = fp32 out; 1 = fp32 if m0<mSplit else bf16 planes (pad cols zeroed);
//          2 = transposed bf16 planes  C^T[n][zi*128 + m]  (K5 -> attT).
template<int OUTMODE, bool HASBN, bool RELU>
__global__ void __launch_bounds__(256, 2)
gemm_bf16(const __nv_bfloat16* __restrict__ Ah, const __nv_bfloat16* __restrict__ Al,
          const __nv_bfloat16* __restrict__ Bh, const __nv_bfloat16* __restrict__ Bl,
          float* __restrict__ Cf, __nv_bfloat16* __restrict__ Ch, __nv_bfloat16* __restrict__ Cl,
          int nchunks, int lda, int ldb,
          long aOuter, long aInner, int innerCnt,
          long bStride, long cfStride, long cpStride,
          int ldcF, int ldcP, int nrowsB, int mSplit,
          const float* __restrict__ bng, const float* __restrict__ bnb,
          const float* __restrict__ bnm, const float* __restrict__ bnv)
{
    constexpr int KP = 24;
    constexpr uint32_t PL = 128 * KP * 2;          // plane bytes
    __shared__ __align__(16) __nv_bfloat16 smbuf[2 * 4 * 128 * KP];  // 49152 B

    const int tid  = threadIdx.x;
    const int wid  = tid >> 5;
    const int lane = tid & 31;
    const int warp_m = wid & 3;
    const int warp_n = wid >> 2;
    const int n0 = blockIdx.x * 128;
    const int m0 = blockIdx.y * 128;
    const int z  = blockIdx.z;
    const int zb = z / innerCnt, zi = z - zb * innerCnt;

    const __nv_bfloat16* Agh = Ah + (size_t)zb * aOuter + (size_t)zi * aInner + (size_t)m0 * lda;
    const __nv_bfloat16* Agl = Al + (size_t)zb * aOuter + (size_t)zi * aInner + (size_t)m0 * lda;
    const __nv_bfloat16* Bgh = Bh + (size_t)z * bStride;
    const __nv_bfloat16* Bgl = Bl + (size_t)z * bStride;

    const uint32_t smb = smem_u32(smbuf);

    // warp-uniform: does this warp's 64-col slab lie fully inside N?
    const bool full = (n0 + warp_n * 64 + 64) <= nrowsB;
    int jlim = nrowsB - (n0 + warp_n * 64);
    jlim = jlim <= 0 ? 0 : ((jlim + 7) >> 3);
    if (jlim > 8) jlim = 8;

    // --- staging: 4 x cp.async 16B per thread per chunk
    auto stage = [&](int ch, int s) {
        const int k0 = ch * 16;
#pragma unroll
        for (int i = 0; i < 4; i++) {
            int c    = i * 256 + tid;
            int p    = c >> 8;           // plane 0..3
            int row  = (c >> 1) & 127;
            int half = c & 1;
            uint32_t dst = smb + (uint32_t)(s * 4 + p) * PL + (uint32_t)(row * KP + half * 8) * 2;
            const __nv_bfloat16* src;
            unsigned sz = 16;
            if (p < 2) {
                src = (p == 0 ? Agh : Agl) + (size_t)row * lda + k0 + half * 8;
            } else {
                int rowg = n0 + row;
                bool ok = rowg < nrowsB;
                if (!ok) { rowg = 0; sz = 0; }
                src = (p == 2 ? Bgh : Bgl) + (size_t)rowg * ldb + k0 + half * 8;
            }
            CP_ASYNC16(dst, src, sz);
        }
        CP_COMMIT();
    };

    float acc[2][8][4];
#pragma unroll
    for (int t = 0; t < 2; t++)
#pragma unroll
        for (int j = 0; j < 8; j++)
#pragma unroll
            for (int c = 0; c < 4; c++) acc[t][j][c] = 0.f;

    stage(0, 0);

    for (int ch = 0; ch < nchunks; ch++) {
        const int s = ch & 1;
        if (ch + 1 < nchunks) { stage(ch + 1, s ^ 1); CP_WAIT(1); }
        else                  { CP_WAIT(0); }
        __syncthreads();

        const uint32_t base = smb + (uint32_t)s * 4 * PL;
        const uint32_t aHi = base, aLo = base + PL, bHi = base + 2 * PL, bLo = base + 3 * PL;

        uint32_t a_hi[2][4], a_lo[2][4];
#pragma unroll
        for (int t = 0; t < 2; t++) {
            int row = warp_m * 32 + t * 16 + (lane & 15);
            int col = (lane >> 4) << 3;
            uint32_t off = (uint32_t)(row * KP + col) * 2;
            LDSM4(a_hi[t], aHi + off);
            LDSM4(a_lo[t], aLo + off);
        }
        int nrow = warp_n * 64 + (lane & 7) + ((lane >> 4) << 3);
        int bcol = ((lane >> 3) & 1) << 3;
        uint32_t boff = (uint32_t)(nrow * KP + bcol) * 2;

        if (full) {
            // ---- exact round-6 path: zero guard overhead
            uint32_t b[8][2];
#pragma unroll
            for (int j = 0; j < 4; j++) {
                uint32_t r[4];
                LDSM4(r, bHi + boff + (uint32_t)(j * 16 * KP) * 2);
                b[2 * j][0] = r[0]; b[2 * j][1] = r[1];
                b[2 * j + 1][0] = r[2]; b[2 * j + 1][1] = r[3];
            }
#pragma unroll
            for (int t = 0; t < 2; t++)
#pragma unroll
                for (int j = 0; j < 8; j++) MMA_BF16(acc[t][j], a_hi[t], b[j]);
#pragma unroll
            for (int t = 0; t < 2; t++)
#pragma unroll
                for (int j = 0; j < 8; j++) MMA_BF16(acc[t][j], a_lo[t], b[j]);
#pragma unroll
            for (int j = 0; j < 4; j++) {
                uint32_t r[4];
                LDSM4(r, bLo + boff + (uint32_t)(j * 16 * KP) * 2);
                b[2 * j][0] = r[0]; b[2 * j][1] = r[1];
                b[2 * j + 1][0] = r[2]; b[2 * j + 1][1] = r[3];
            }
#pragma unroll
            for (int t = 0; t < 2; t++)
#pragma unroll
                for (int j = 0; j < 8; j++) MMA_BF16(acc[t][j], a_hi[t], b[j]);
        } else if (jlim > 0) {
            // ---- partial path: only first pair of j-tiles (jlim<=2 in practice)
            uint32_t b[2][2];
            {
                uint32_t r[4];
                LDSM4(r, bHi + boff);
                b[0][0] = r[0]; b[0][1] = r[1];
                b[1][0] = r[2]; b[1][1] = r[3];
            }
#pragma unroll
            for (int t = 0; t < 2; t++)
#pragma unroll
                for (int j = 0; j < 2; j++)
                    if (j < jlim) MMA_BF16(acc[t][j], a_hi[t], b[j]);
#pragma unroll
            for (int t = 0; t < 2; t++)
#pragma unroll
                for (int j = 0; j < 2; j++)
                    if (j < jlim) MMA_BF16(acc[t][j], a_lo[t], b[j]);
            {
                uint32_t r[4];
                LDSM4(r, bLo + boff);
                b[0][0] = r[0]; b[0][1] = r[1];
                b[1][0] = r[2]; b[1][1] = r[3];
            }
#pragma unroll
            for (int t = 0; t < 2; t++)
#pragma unroll
                for (int j = 0; j < 2; j++)
                    if (j < jlim) MMA_BF16(acc[t][j], a_hi[t], b[j]);
        }

        __syncthreads();   // buffer reuse safety before next stage() overwrites
    }

    // ---------------- epilogues ----------------
    if (OUTMODE == 0 || OUTMODE == 1) {
        const bool isF32 = (OUTMODE == 0) || (m0 < mSplit);
#pragma unroll
        for (int t = 0; t < 2; t++) {
            int r0 = m0 + warp_m * 32 + t * 16 + (lane >> 2);
            int r1 = r0 + 8;
            float s0 = 1.f, h0 = 0.f, s1 = 1.f, h1 = 0.f;
            if (HASBN) {
                float a = bng[r0] * rsqrtf(bnv[r0] + BN_EPS);
                s0 = a; h0 = bnb[r0] - bnm[r0] * a;
                float c = bng[r1] * rsqrtf(bnv[r1] + BN_EPS);
                s1 = c; h1 = bnb[r1] - bnm[r1] * c;
            }
#pragma unroll
            for (int j = 0; j < 8; j++) {
                int nn = n0 + warp_n * 64 + j * 8 + 2 * (lane & 3);
                float v0 = acc[t][j][0] * s0 + h0;
                float v1 = acc[t][j][1] * s0 + h0;
                float v2 = acc[t][j][2] * s1 + h1;
                float v3 = acc[t][j][3] * s1 + h1;
                if (RELU) {
                    v0 = fmaxf(v0, 0.f); v1 = fmaxf(v1, 0.f);
                    v2 = fmaxf(v2, 0.f); v3 = fmaxf(v3, 0.f);
                }
                if (isF32) {
                    if (nn < NPIX) {
                        *(float2*)(Cf + (size_t)z * cfStride + (size_t)r0 * ldcF + nn) = make_float2(v0, v1);
                        *(float2*)(Cf + (size_t)z * cfStride + (size_t)r1 * ldcF + nn) = make_float2(v2, v3);
                    }
                } else {
                    if (nn < NPAD) {
                        if (nn >= NPIX) { v0 = v1 = v2 = v3 = 0.f; }
                        __nv_bfloat16 ha, la, hb, lb;
                        size_t p0 = (size_t)z * cpStride + (size_t)(r0 - mSplit) * ldcP + nn;
                        size_t p1 = (size_t)z * cpStride + (size_t)(r1 - mSplit) * ldcP + nn;
                        split_bf16(v0, ha, la); split_bf16(v1, hb, lb);
                        *(__nv_bfloat162*)(Ch + p0) = __nv_bfloat162(ha, hb);
                        *(__nv_bfloat162*)(Cl + p0) = __nv_bfloat162(la, lb);
                        split_bf16(v2, ha, la); split_bf16(v3, hb, lb);
                        *(__nv_bfloat162*)(Ch + p1) = __nv_bfloat162(ha, hb);
                        *(__nv_bfloat162*)(Cl + p1) = __nv_bfloat162(la, lb);
                    }
                }
            }
        }
    } else {
        // OUTMODE 2: transposed plane output via smem (reuse stage buffer)
        __nv_bfloat16* ep = smbuf;   // [128 i][136 d]
#pragma unroll
        for (int plane = 0; plane < 2; plane++) {
            __syncthreads();
#pragma unroll
            for (int t = 0; t < 2; t++) {
                int d0 = warp_m * 32 + t * 16 + (lane >> 2);
                int d1 = d0 + 8;
#pragma unroll
                for (int j = 0; j < 8; j++) {
                    int il = warp_n * 64 + j * 8 + 2 * (lane & 3);
                    float v[4];
#pragma unroll
                    for (int c = 0; c < 4; c++) {
                        float x = acc[t][j][c];
                        v[c] = RELU ? fmaxf(x, 0.f) : x;
                    }
                    __nv_bfloat16 o[4];
#pragma unroll
                    for (int c = 0; c < 4; c++) {
                        __nv_bfloat16 h = __float2bfloat16(v[c]);
                        o[c] = plane == 0 ? h : __float2bfloat16(v[c] - __bfloat162float(h));
                    }
                    ep[il * 136 + d0]       = o[0];
                    ep[(il + 1) * 136 + d0] = o[1];
                    ep[il * 136 + d1]       = o[2];
                    ep[(il + 1) * 136 + d1] = o[3];
                }
            }
            __syncthreads();
            __nv_bfloat16* dst = (plane == 0 ? Ch : Cl) + (size_t)zb * cpStride + (size_t)zi * 128;
            for (int c2 = tid; c2 < 2048; c2 += 256) {
                int row = c2 >> 4, off = (c2 & 15) * 8;
                int i = n0 + row;
                if (i < NPIX) {
                    uint4 val = *(uint4*)(ep + row * 136 + off);
                    *(uint4*)(dst + (size_t)i * ldcP + off) = val;
                }
            }
        }
    }
}

// ---------------- pre-convert kernels ----------------
__global__ void convert_weights(const float* __restrict__ qw, const float* __restrict__ pw)
{
    int i = blockIdx.x * 256 + threadIdx.x;
    if (i < HQKV * DIM) split_bf16(qw[i], g_qw_h[i], g_qw_l[i]);
    if (i < DIM * DH)   split_bf16(pw[i], g_pw_h[i], g_pw_l[i]);
}

__global__ void transpose_x(const float* __restrict__ x)
{
    __shared__ float t[32][33];
    int p0 = blockIdx.x * 32, c0 = blockIdx.y * 32, b = blockIdx.z;
    for (int r = threadIdx.y; r < 32; r += 8) {
        int p = p0 + threadIdx.x;
        t[r][threadIdx.x] = (p < NPIX) ? x[((size_t)b * DIM + c0 + r) * NPIX + p] : 0.f;
    }
    __syncthreads();
    for (int r = threadIdx.y; r < 32; r += 8) {
        int p = p0 + r, c = c0 + threadIdx.x;
        if (p < NPIX) {
            size_t o = ((size_t)b * NPIX + p) * DIM + c;
            split_bf16(t[threadIdx.x][r], g_xT_h[o], g_xT_l[o]);
        }
    }
}

// ---------------- dwconv + BN: one block per (channel, batch) ---------------
__global__ void __launch_bounds__(224, 8)
dwconv_bn(const float* __restrict__ w,
          const float* __restrict__ bng,
          const float* __restrict__ bnb,
          const float* __restrict__ bnm,
          const float* __restrict__ bnv)
{
    const int c = blockIdx.x;
    const int b = blockIdx.y;
    __shared__ float t[NPIX];
    __shared__ float wgt[9];
    __shared__ float sBN[2];

    const float* src = g_qkv + (size_t)b * 768 * NPIX + (size_t)c * NPIX;
    int tid = threadIdx.x;
    if (tid < NPIX) t[tid] = src[tid];
    if (tid < 9)    wgt[tid] = w[c * 9 + tid];
    if (tid == 0) {
        float s = bng[c] * rsqrtf(bnv[c] + BN_EPS);
        sBN[0] = s;
        sBN[1] = bnb[c] - bnm[c] * s;
    }
    __syncthreads();

    if (tid < NPIX) {
        int y = tid / RES, x = tid - y * RES;
        float acc = 0.f;
#pragma unroll
        for (int ky = 0; ky < 3; ky++) {
            int yy = y + ky - 1;
            if (yy < 0 || yy >= RES) continue;
#pragma unroll
            for (int kx = 0; kx < 3; kx++) {
                int xx = x + kx - 1;
                if (xx < 0 || xx >= RES) continue;
                acc += t[yy * RES + xx] * wgt[ky * 3 + kx];
            }
        }
        g_qdw[((size_t)b * NH_KD + c) * NPIX + tid] = acc * sBN[0] + sBN[1];
    }
}

// ---------------- bias gather ----------------
__global__ void bias_gather(const float* __restrict__ ab, const int* __restrict__ idxs)
{
    int idx = blockIdx.x * 256 + threadIdx.x;
    if (idx >= NHEADS * NPIX * NPIX) return;
    int h  = idx / (NPIX * NPIX);
    int ij = idx % (NPIX * NPIX);
    g_bias[idx] = ab[h * NPIX + idxs[ij]];
}

// ---------------- softmax (round-6 version): P bf16 planes ------------------
__global__ void attn_softmax(void)
{
    const int h = blockIdx.x;
    const int b = blockIdx.y;
    __shared__ float k_s[32 * 224];

    const float* qg = g_qdw + (size_t)b * NH_KD * NPIX + (size_t)h * KEY_DIM * NPIX;
    const float* kg = g_qkv + (size_t)b * 768 * NPIX + (size_t)(NH_KD + h * KEY_DIM) * NPIX;

    for (int idx = threadIdx.x; idx < 32 * 224; idx += 256) {
        int d = idx / 224, j = idx % 224;
        k_s[idx] = (j < NPIX) ? kg[d * NPIX + j] : 0.f;
    }
    __syncthreads();

    const int w    = threadIdx.x >> 5;
    const int lane = threadIdx.x & 31;
    const float* bh = g_bias + (size_t)h * NPIX * NPIX;
    const size_t zoff = ((size_t)b * NHEADS + h) * NPIX * NPAD;
    const float scale = 0.17677669529663687f;

    for (int i0 = w * 8; i0 < NPIX; i0 += 64) {
        float q_reg[8];
#pragma unroll
        for (int r = 0; r < 8; r++) {
            int i = i0 + r;
            q_reg[r] = (i < NPIX) ? qg[(size_t)lane * NPIX + i] : 0.f;
        }

        float s[8][7];
#pragma unroll
        for (int r = 0; r < 8; r++)
#pragma unroll
            for (int m = 0; m < 7; m++) s[r][m] = 0.f;

        for (int d = 0; d < 32; d++) {
            float qv[8];
#pragma unroll
            for (int r = 0; r < 8; r++)
                qv[r] = __shfl_sync(0xffffffffu, q_reg[r], d);
#pragma unroll
            for (int m = 0; m < 7; m++) {
                float kv = k_s[d * 224 + lane + m * 32];
#pragma unroll
                for (int r = 0; r < 8; r++) s[r][m] += qv[r] * kv;
            }
        }

#pragma unroll
        for (int r = 0; r < 8; r++) {
            int i = i0 + r;
            if (i >= NPIX) break;
            float sv[7];
            float mx = -1e30f;
#pragma unroll
            for (int m = 0; m < 7; m++) {
                int j = lane + m * 32;
                float val = (j < NPIX) ? s[r][m] * scale + bh[(size_t)i * NPIX + j]
                                       : -1e30f;
                sv[m] = val;
                mx = fmaxf(mx, val);
            }
#pragma unroll
            for (int off = 16; off; off >>= 1)
                mx = fmaxf(mx, __shfl_xor_sync(0xffffffffu, mx, off));
            float sum = 0.f;
#pragma unroll
            for (int m = 0; m < 7; m++) {
                sv[m] = __expf(sv[m] - mx);
                sum += sv[m];
            }
#pragma unroll
            for (int off = 16; off; off >>= 1)
                sum += __shfl_xor_sync(0xffffffffu, sum, off);
            float inv = 1.f / sum;
#pragma unroll
            for (int m = 0; m < 7; m++) {
                int j = lane + m * 32;
                if (j < NPIX) {
                    float val = sv[m] * inv;
                    __nv_bfloat16 hh, ll;
                    split_bf16(val, hh, ll);
                    g_p_h[zoff + (size_t)i * NPAD + j] = hh;
                    g_p_l[zoff + (size_t)i * NPAD + j] = ll;
                } else if (j < NPAD) {
                    g_p_h[zoff + (size_t)i * NPAD + j] = __float2bfloat16(0.f);
                    g_p_l[zoff + (size_t)i * NPAD + j] = __float2bfloat16(0.f);
                }
            }
        }
    }
}

// ---------------- launch ----------------------------------------------------
extern "C" void kernel_launch(void* const* d_in, const int* in_sizes, int n_in,
                              void* d_out, int out_size)
{
    const float* x      = (const float*)d_in[0];
    const float* qkv_w  = (const float*)d_in[1];
    const float* qkv_g  = (const float*)d_in[2];
    const float* qkv_b  = (const float*)d_in[3];
    const float* qkv_m  = (const float*)d_in[4];
    const float* qkv_v  = (const float*)d_in[5];
    const float* dw_w   = (const float*)d_in[6];
    const float* dw_g   = (const float*)d_in[7];
    const float* dw_b   = (const float*)d_in[8];
    const float* dw_m   = (const float*)d_in[9];
    const float* dw_v   = (const float*)d_in[10];
    const float* proj_w = (const float*)d_in[11];
    const float* proj_g = (const float*)d_in[12];
    const float* proj_b = (const float*)d_in[13];
    const float* proj_m = (const float*)d_in[14];
    const float* proj_v = (const float*)d_in[15];
    const float* ab     = (const float*)d_in[16];
    const int*   bidx   = (const int*)d_in[17];
    float* out = (float*)d_out;

    float* qkvf;  cudaGetSymbolAddress((void**)&qkvf,  g_qkv);
    __nv_bfloat16 *qwh, *qwl, *pwh, *pwl, *xth, *xtl, *vh, *vl, *ph, *pl, *ath, *atl;
    cudaGetSymbolAddress((void**)&qwh, g_qw_h);  cudaGetSymbolAddress((void**)&qwl, g_qw_l);
    cudaGetSymbolAddress((void**)&pwh, g_pw_h);  cudaGetSymbolAddress((void**)&pwl, g_pw_l);
    cudaGetSymbolAddress((void**)&xth, g_xT_h);  cudaGetSymbolAddress((void**)&xtl, g_xT_l);
    cudaGetSymbolAddress((void**)&vh,  g_v_h);   cudaGetSymbolAddress((void**)&vl,  g_v_l);
    cudaGetSymbolAddress((void**)&ph,  g_p_h);   cudaGetSymbolAddress((void**)&pl,  g_p_l);
    cudaGetSymbolAddress((void**)&ath, g_at_h);  cudaGetSymbolAddress((void**)&atl, g_at_l);

    // P0: convert weights + transpose/convert x
    convert_weights<<<(HQKV * DIM + 255) / 256, 256>>>(qkv_w, proj_w);
    transpose_x<<<dim3(7, 12, BATCH), dim3(32, 8)>>>(x);

    // K1: qkv = BN(W_qkv @ x)  -> fp32 rows<768, V planes rows>=768
    gemm_bf16<1, true, false><<<dim3(2, HQKV / 128, BATCH), 256>>>(
        qwh, qwl, xth, xtl,
        qkvf, vh, vl,
        DIM / 16, DIM, DIM,
        0L, 0L, 1,
        (long)NPIX * DIM, (long)768 * NPIX, (long)DH * NPAD,
        NPIX, NPAD, NPIX, 768,
        qkv_g, qkv_b, qkv_m, qkv_v);

    // K2: q <- BN(dwconv3x3(q))
    dwconv_bn<<<dim3(NH_KD, BATCH), 224>>>(dw_w, dw_g, dw_b, dw_m, dw_v);

    // K3: bias gather
    {
        int total = NHEADS * NPIX * NPIX;
        bias_gather<<<(total + 255) / 256, 256>>>(ab, bidx);
    }
    // K4: softmax -> P planes
    attn_softmax<<<dim3(NHEADS, BATCH), 256>>>();

    // K5: attT planes = relu(V @ P^T)^T  (per b,h)
    gemm_bf16<2, false, true><<<dim3(2, 1, BATCH * NHEADS), 256>>>(
        vh, vl, ph, pl,
        nullptr, ath, atl,
        NPAD / 16, NPAD, NPAD,
        (long)DH * NPAD, (long)128 * NPAD, NHEADS,
        (long)NPIX * NPAD, 0L, (long)NPIX * DH,
        0, DH, NPIX, 0,
        nullptr, nullptr, nullptr, nullptr);

    // K6: out = BN(W_proj @ att)  (B = attT planes, k-contig)
    gemm_bf16<0, true, false><<<dim3(2, DIM / 128, BATCH), 256>>>(
        pwh, pwl, ath, atl,
        out, nullptr, nullptr,
        DH / 16, DH, DH,
        0L, 0L, 1,
        (long)NPIX * DH, (long)DIM * NPIX, 0L,
        NPIX, 0, NPIX, DIM,
        proj_g, proj_b, proj_m, proj_v);
}

// round 9
// speedup vs baseline: 1.3065x; 1.1501x over previous
#include <cuda_runtime.h>
#include <cuda_fp16.h>
#include <math.h>
#include <stdint.h>

// ---------------- constants ----------------
#define BATCH   128
#define DIM     384
#define RES     14
#define NPIX    196
#define KEY_DIM 32
#define NHEADS  12
#define NH_KD   384
#define DH      1536
#define HQKV    2304
#define BN_EPS  1e-5f
#define NPAD    208     // NPIX padded to mult of 16

// ---------------- scratch ----------------
__device__ float g_qkv [ (size_t)BATCH * 768 * NPIX ];            // q+k fp32 only
__device__ float g_qdw [ (size_t)BATCH * NH_KD * NPIX ];
__device__ float g_bias[ (size_t)NHEADS * NPIX * NPIX ];

__device__ __half g_qw_h[ HQKV * DIM ],  g_qw_l[ HQKV * DIM ];
__device__ __half g_pw_h[ DIM * DH ],    g_pw_l[ DIM * DH ];
__device__ __half g_xT_h[ (size_t)BATCH * NPIX * DIM ],  g_xT_l[ (size_t)BATCH * NPIX * DIM ];
__device__ __half g_v_h [ (size_t)BATCH * DH * NPAD ],   g_v_l [ (size_t)BATCH * DH * NPAD ];
__device__ __half g_p_h [ (size_t)BATCH * NHEADS * NPIX * NPAD ];   // hi plane only
__device__ __half g_at_h[ (size_t)BATCH * NPIX * DH ];              // hi plane only

// ---------------- helpers ----------------
__device__ __forceinline__ uint32_t smem_u32(const void* p) {
    uint32_t a;
    asm("{ .reg .u64 t; cvta.to.shared.u64 t, %1; cvt.u32.u64 %0, t; }"
        : "=r"(a) : "l"(p));
    return a;
}
#define LDSM4(r, addr) \
    asm volatile("ldmatrix.sync.aligned.m8n8.x4.shared.b16 {%0,%1,%2,%3}, [%4];" \
        : "=r"((r)[0]), "=r"((r)[1]), "=r"((r)[2]), "=r"((r)[3]) : "r"(addr))
#define MMA_F16(d, a, bb) \
    asm volatile("mma.sync.aligned.m16n8k16.row.col.f32.f16.f16.f32 " \
        "{%0,%1,%2,%3}, {%4,%5,%6,%7}, {%8,%9}, {%0,%1,%2,%3};" \
        : "+f"((d)[0]), "+f"((d)[1]), "+f"((d)[2]), "+f"((d)[3]) \
        : "r"((a)[0]), "r"((a)[1]), "r"((a)[2]), "r"((a)[3]), \
          "r"((bb)[0]), "r"((bb)[1]))
#define CP_ASYNC16(dst, src, sz) \
    asm volatile("cp.async.cg.shared.global [%0], [%1], 16, %2;" \
                 :: "r"(dst), "l"(src), "r"(sz))
#define CP_COMMIT() asm volatile("cp.async.commit_group;" ::: "memory")
#define CP_WAIT(n)  asm volatile("cp.async.wait_group %0;" :: "n"(n) : "memory")

__device__ __forceinline__ void split_f16(float v, __half& h, __half& l) {
    h = __float2half_rn(v);
    l = __float2half_rn(v - __half2float(h));
}

// ================= pipelined fp16-plane GEMM =================
// C[m,n] = act(BN_m( sum_k A[m,k]*B[n,k] ))  -- k-contig fp16 planes.
// TERMS=3: hh + lo_A*hi_B + hi_A*lo_B  (err ~ eps^2)
// TERMS=2: hh + lo_A*hi_B              (err ~ eps_B; B-lo never staged)
// CTA 128x128, 8 warps (4m x 2n), K-chunk 16, 2-stage cp.async.
// OUTMODE: 0 = fp32 out; 1 = fp32 if m0<mSplit else fp16 h/l planes (pad zeroed);
//          2 = transposed fp16 HI plane only  C^T[n][zi*128+m].
template<int OUTMODE, bool HASBN, bool RELU, int TERMS>
__global__ void __launch_bounds__(256, 2)
gemm_f16(const __half* __restrict__ Ah, const __half* __restrict__ Al,
         const __half* __restrict__ Bh, const __half* __restrict__ Bl,
         float* __restrict__ Cf, __half* __restrict__ Ch, __half* __restrict__ Cl,
         int nchunks, int lda, int ldb,
         long aOuter, long aInner, int innerCnt,
         long bStride, long cfStride, long cpStride,
         int ldcF, int ldcP, int nrowsB, int mSplit,
         const float* __restrict__ bng, const float* __restrict__ bnb,
         const float* __restrict__ bnm, const float* __restrict__ bnv)
{
    constexpr int KP = 24;
    constexpr int NP = (TERMS == 3) ? 4 : 3;       // planes staged per chunk
    constexpr uint32_t PL = 128 * KP * 2;          // plane bytes
    __shared__ __align__(16) __half smbuf[2 * NP * 128 * KP];

    const int tid  = threadIdx.x;
    const int wid  = tid >> 5;
    const int lane = tid & 31;
    const int warp_m = wid & 3;
    const int warp_n = wid >> 2;
    const int n0 = blockIdx.x * 128;
    const int m0 = blockIdx.y * 128;
    const int z  = blockIdx.z;
    const int zb = z / innerCnt, zi = z - zb * innerCnt;

    const __half* Agh = Ah + (size_t)zb * aOuter + (size_t)zi * aInner + (size_t)m0 * lda;
    const __half* Agl = Al + (size_t)zb * aOuter + (size_t)zi * aInner + (size_t)m0 * lda;
    const __half* Bgh = Bh + (size_t)z * bStride;
    const __half* Bgl = (TERMS == 3) ? (Bl + (size_t)z * bStride) : nullptr;

    const uint32_t smb = smem_u32(smbuf);

    // warp-uniform: does this warp's 64-col slab lie fully inside N?
    const bool full = (n0 + warp_n * 64 + 64) <= nrowsB;
    int jlim = nrowsB - (n0 + warp_n * 64);
    jlim = jlim <= 0 ? 0 : ((jlim + 7) >> 3);
    if (jlim > 8) jlim = 8;

    // --- staging: NP x cp.async 16B per thread per chunk
    auto stage = [&](int ch, int s) {
        const int k0 = ch * 16;
#pragma unroll
        for (int i = 0; i < NP; i++) {
            int c    = i * 256 + tid;
            int p    = c >> 8;           // plane 0..NP-1
            int row  = (c >> 1) & 127;
            int half = c & 1;
            uint32_t dst = smb + (uint32_t)(s * NP + p) * PL + (uint32_t)(row * KP + half * 8) * 2;
            const __half* src;
            unsigned sz = 16;
            if (p < 2) {
                src = (p == 0 ? Agh : Agl) + (size_t)row * lda + k0 + half * 8;
            } else {
                int rowg = n0 + row;
                bool ok = rowg < nrowsB;
                if (!ok) { rowg = 0; sz = 0; }
                src = (p == 2 ? Bgh : Bgl) + (size_t)rowg * ldb + k0 + half * 8;
            }
            CP_ASYNC16(dst, src, sz);
        }
        CP_COMMIT();
    };

    float acc[2][8][4];
#pragma unroll
    for (int t = 0; t < 2; t++)
#pragma unroll
        for (int j = 0; j < 8; j++)
#pragma unroll
            for (int c = 0; c < 4; c++) acc[t][j][c] = 0.f;

    stage(0, 0);

    for (int ch = 0; ch < nchunks; ch++) {
        const int s = ch & 1;
        if (ch + 1 < nchunks) { stage(ch + 1, s ^ 1); CP_WAIT(1); }
        else                  { CP_WAIT(0); }
        __syncthreads();

        const uint32_t base = smb + (uint32_t)s * NP * PL;
        const uint32_t aHi = base, aLo = base + PL, bHi = base + 2 * PL;
        const uint32_t bLo = base + 3 * PL;   // valid only for TERMS==3

        uint32_t a_hi[2][4], a_lo[2][4];
#pragma unroll
        for (int t = 0; t < 2; t++) {
            int row = warp_m * 32 + t * 16 + (lane & 15);
            int col = (lane >> 4) << 3;
            uint32_t off = (uint32_t)(row * KP + col) * 2;
            LDSM4(a_hi[t], aHi + off);
            LDSM4(a_lo[t], aLo + off);
        }
        int nrow = warp_n * 64 + (lane & 7) + ((lane >> 4) << 3);
        int bcol = ((lane >> 3) & 1) << 3;
        uint32_t boff = (uint32_t)(nrow * KP + bcol) * 2;

        if (full) {
            uint32_t b[8][2];
#pragma unroll
            for (int j = 0; j < 4; j++) {
                uint32_t r[4];
                LDSM4(r, bHi + boff + (uint32_t)(j * 16 * KP) * 2);
                b[2 * j][0] = r[0]; b[2 * j][1] = r[1];
                b[2 * j + 1][0] = r[2]; b[2 * j + 1][1] = r[3];
            }
#pragma unroll
            for (int t = 0; t < 2; t++)
#pragma unroll
                for (int j = 0; j < 8; j++) MMA_F16(acc[t][j], a_hi[t], b[j]);
#pragma unroll
            for (int t = 0; t < 2; t++)
#pragma unroll
                for (int j = 0; j < 8; j++) MMA_F16(acc[t][j], a_lo[t], b[j]);
            if (TERMS == 3) {
#pragma unroll
                for (int j = 0; j < 4; j++) {
                    uint32_t r[4];
                    LDSM4(r, bLo + boff + (uint32_t)(j * 16 * KP) * 2);
                    b[2 * j][0] = r[0]; b[2 * j][1] = r[1];
                    b[2 * j + 1][0] = r[2]; b[2 * j + 1][1] = r[3];
                }
#pragma unroll
                for (int t = 0; t < 2; t++)
#pragma unroll
                    for (int j = 0; j < 8; j++) MMA_F16(acc[t][j], a_hi[t], b[j]);
            }
        } else if (jlim > 0) {
            uint32_t b2[2][2];
            {
                uint32_t r[4];
                LDSM4(r, bHi + boff);
                b2[0][0] = r[0]; b2[0][1] = r[1];
                b2[1][0] = r[2]; b2[1][1] = r[3];
            }
#pragma unroll
            for (int t = 0; t < 2; t++)
#pragma unroll
                for (int j = 0; j < 2; j++)
                    if (j < jlim) MMA_F16(acc[t][j], a_hi[t], b2[j]);
#pragma unroll
            for (int t = 0; t < 2; t++)
#pragma unroll
                for (int j = 0; j < 2; j++)
                    if (j < jlim) MMA_F16(acc[t][j], a_lo[t], b2[j]);
            if (TERMS == 3) {
                uint32_t r[4];
                LDSM4(r, bLo + boff);
                b2[0][0] = r[0]; b2[0][1] = r[1];
                b2[1][0] = r[2]; b2[1][1] = r[3];
#pragma unroll
                for (int t = 0; t < 2; t++)
#pragma unroll
                    for (int j = 0; j < 2; j++)
                        if (j < jlim) MMA_F16(acc[t][j], a_hi[t], b2[j]);
            }
        }

        __syncthreads();   // buffer reuse safety before next stage() overwrites
    }

    // ---------------- epilogues ----------------
    if (OUTMODE == 0 || OUTMODE == 1) {
        const bool isF32 = (OUTMODE == 0) || (m0 < mSplit);
#pragma unroll
        for (int t = 0; t < 2; t++) {
            int r0 = m0 + warp_m * 32 + t * 16 + (lane >> 2);
            int r1 = r0 + 8;
            float s0 = 1.f, h0 = 0.f, s1 = 1.f, h1 = 0.f;
            if (HASBN) {
                float a = bng[r0] * rsqrtf(bnv[r0] + BN_EPS);
                s0 = a; h0 = bnb[r0] - bnm[r0] * a;
                float c = bng[r1] * rsqrtf(bnv[r1] + BN_EPS);
                s1 = c; h1 = bnb[r1] - bnm[r1] * c;
            }
#pragma unroll
            for (int j = 0; j < 8; j++) {
                int nn = n0 + warp_n * 64 + j * 8 + 2 * (lane & 3);
                float v0 = acc[t][j][0] * s0 + h0;
                float v1 = acc[t][j][1] * s0 + h0;
                float v2 = acc[t][j][2] * s1 + h1;
                float v3 = acc[t][j][3] * s1 + h1;
                if (RELU) {
                    v0 = fmaxf(v0, 0.f); v1 = fmaxf(v1, 0.f);
                    v2 = fmaxf(v2, 0.f); v3 = fmaxf(v3, 0.f);
                }
                if (isF32) {
                    if (nn < NPIX) {
                        *(float2*)(Cf + (size_t)z * cfStride + (size_t)r0 * ldcF + nn) = make_float2(v0, v1);
                        *(float2*)(Cf + (size_t)z * cfStride + (size_t)r1 * ldcF + nn) = make_float2(v2, v3);
                    }
                } else {
                    if (nn < NPAD) {
                        if (nn >= NPIX) { v0 = v1 = v2 = v3 = 0.f; }
                        __half ha, la, hb, lb;
                        size_t p0 = (size_t)z * cpStride + (size_t)(r0 - mSplit) * ldcP + nn;
                        size_t p1 = (size_t)z * cpStride + (size_t)(r1 - mSplit) * ldcP + nn;
                        split_f16(v0, ha, la); split_f16(v1, hb, lb);
                        *(__half2*)(Ch + p0) = __half2(ha, hb);
                        *(__half2*)(Cl + p0) = __half2(la, lb);
                        split_f16(v2, ha, la); split_f16(v3, hb, lb);
                        *(__half2*)(Ch + p1) = __half2(ha, hb);
                        *(__half2*)(Cl + p1) = __half2(la, lb);
                    }
                }
            }
        }
    } else {
        // OUTMODE 2: transposed HI-plane output via smem (reuse stage buffer)
        __half* ep = smbuf;   // [128 i][136 d]
        __syncthreads();
#pragma unroll
        for (int t = 0; t < 2; t++) {
            int d0 = warp_m * 32 + t * 16 + (lane >> 2);
            int d1 = d0 + 8;
#pragma unroll
            for (int j = 0; j < 8; j++) {
                int il = warp_n * 64 + j * 8 + 2 * (lane & 3);
                float v0 = acc[t][j][0], v1 = acc[t][j][1];
                float v2 = acc[t][j][2], v3 = acc[t][j][3];
                if (RELU) {
                    v0 = fmaxf(v0, 0.f); v1 = fmaxf(v1, 0.f);
                    v2 = fmaxf(v2, 0.f); v3 = fmaxf(v3, 0.f);
                }
                ep[il * 136 + d0]       = __float2half_rn(v0);
                ep[(il + 1) * 136 + d0] = __float2half_rn(v1);
                ep[il * 136 + d1]       = __float2half_rn(v2);
                ep[(il + 1) * 136 + d1] = __float2half_rn(v3);
            }
        }
        __syncthreads();
        __half* dst = Ch + (size_t)zb * cpStride + (size_t)zi * 128;
        for (int c2 = tid; c2 < 2048; c2 += 256) {
            int row = c2 >> 4, off = (c2 & 15) * 8;
            int i = n0 + row;
            if (i < NPIX) {
                uint4 val = *(uint4*)(ep + row * 136 + off);
                *(uint4*)(dst + (size_t)i * ldcP + off) = val;
            }
        }
    }
}

// ---------------- pre-convert kernels ----------------
__global__ void convert_weights(const float* __restrict__ qw, const float* __restrict__ pw)
{
    int i = blockIdx.x * 256 + threadIdx.x;
    if (i < HQKV * DIM) split_f16(qw[i], g_qw_h[i], g_qw_l[i]);
    if (i < DIM * DH)   split_f16(pw[i], g_pw_h[i], g_pw_l[i]);
}

__global__ void transpose_x(const float* __restrict__ x)
{
    __shared__ float t[32][33];
    int p0 = blockIdx.x * 32, c0 = blockIdx.y * 32, b = blockIdx.z;
    for (int r = threadIdx.y; r < 32; r += 8) {
        int p = p0 + threadIdx.x;
        t[r][threadIdx.x] = (p < NPIX) ? x[((size_t)b * DIM + c0 + r) * NPIX + p] : 0.f;
    }
    __syncthreads();
    for (int r = threadIdx.y; r < 32; r += 8) {
        int p = p0 + r, c = c0 + threadIdx.x;
        if (p < NPIX) {
            size_t o = ((size_t)b * NPIX + p) * DIM + c;
            split_f16(t[threadIdx.x][r], g_xT_h[o], g_xT_l[o]);
        }
    }
}

// ---------------- dwconv + BN: one block per (channel, batch) ---------------
__global__ void __launch_bounds__(224, 8)
dwconv_bn(const float* __restrict__ w,
          const float* __restrict__ bng,
          const float* __restrict__ bnb,
          const float* __restrict__ bnm,
          const float* __restrict__ bnv)
{
    const int c = blockIdx.x;
    const int b = blockIdx.y;
    __shared__ float t[NPIX];
    __shared__ float wgt[9];
    __shared__ float sBN[2];

    const float* src = g_qkv + (size_t)b * 768 * NPIX + (size_t)c * NPIX;
    int tid = threadIdx.x;
    if (tid < NPIX) t[tid] = src[tid];
    if (tid < 9)    wgt[tid] = w[c * 9 + tid];
    if (tid == 0) {
        float s = bng[c] * rsqrtf(bnv[c] + BN_EPS);
        sBN[0] = s;
        sBN[1] = bnb[c] - bnm[c] * s;
    }
    __syncthreads();

    if (tid < NPIX) {
        int y = tid / RES, x = tid - y * RES;
        float acc = 0.f;
#pragma unroll
        for (int ky = 0; ky < 3; ky++) {
            int yy = y + ky - 1;
            if (yy < 0 || yy >= RES) continue;
#pragma unroll
            for (int kx = 0; kx < 3; kx++) {
                int xx = x + kx - 1;
                if (xx < 0 || xx >= RES) continue;
                acc += t[yy * RES + xx] * wgt[ky * 3 + kx];
            }
        }
        g_qdw[((size_t)b * NH_KD + c) * NPIX + tid] = acc * sBN[0] + sBN[1];
    }
}

// ---------------- bias gather ----------------
__global__ void bias_gather(const float* __restrict__ ab, const int* __restrict__ idxs)
{
    int idx = blockIdx.x * 256 + threadIdx.x;
    if (idx >= NHEADS * NPIX * NPIX) return;
    int h  = idx / (NPIX * NPIX);
    int ij = idx % (NPIX * NPIX);
    g_bias[idx] = ab[h * NPIX + idxs[ij]];
}

// ---------------- softmax: P written as fp16 HI plane only ------------------
__global__ void attn_softmax(void)
{
    const int h = blockIdx.x;
    const int b = blockIdx.y;
    __shared__ float k_s[32 * 224];

    const float* qg = g_qdw + (size_t)b * NH_KD * NPIX + (size_t)h * KEY_DIM * NPIX;
    const float* kg = g_qkv + (size_t)b * 768 * NPIX + (size_t)(NH_KD + h * KEY_DIM) * NPIX;

    for (int idx = threadIdx.x; idx < 32 * 224; idx += 256) {
        int d = idx / 224, j = idx % 224;
        k_s[idx] = (j < NPIX) ? kg[d * NPIX + j] : 0.f;
    }
    __syncthreads();

    const int w    = threadIdx.x >> 5;
    const int lane = threadIdx.x & 31;
    const float* bh = g_bias + (size_t)h * NPIX * NPIX;
    const size_t zoff = ((size_t)b * NHEADS + h) * NPIX * NPAD;
    const float scale = 0.17677669529663687f;

    for (int i0 = w * 8; i0 < NPIX; i0 += 64) {
        float q_reg[8];
#pragma unroll
        for (int r = 0; r < 8; r++) {
            int i = i0 + r;
            q_reg[r] = (i < NPIX) ? qg[(size_t)lane * NPIX + i] : 0.f;
        }

        float s[8][7];
#pragma unroll
        for (int r = 0; r < 8; r++)
#pragma unroll
            for (int m = 0; m < 7; m++) s[r][m] = 0.f;

        for (int d = 0; d < 32; d++) {
            float qv[8];
#pragma unroll
            for (int r = 0; r < 8; r++)
                qv[r] = __shfl_sync(0xffffffffu, q_reg[r], d);
#pragma unroll
            for (int m = 0; m < 7; m++) {
                float kv = k_s[d * 224 + lane + m * 32];
#pragma unroll
                for (int r = 0; r < 8; r++) s[r][m] += qv[r] * kv;
            }
        }

#pragma unroll
        for (int r = 0; r < 8; r++) {
            int i = i0 + r;
            if (i >= NPIX) break;
            float sv[7];
            float mx = -1e30f;
#pragma unroll
            for (int m = 0; m < 7; m++) {
                int j = lane + m * 32;
                float val = (j < NPIX) ? s[r][m] * scale + bh[(size_t)i * NPIX + j]
                                       : -1e30f;
                sv[m] = val;
                mx = fmaxf(mx, val);
            }
#pragma unroll
            for (int off = 16; off; off >>= 1)
                mx = fmaxf(mx, __shfl_xor_sync(0xffffffffu, mx, off));
            float sum = 0.f;
#pragma unroll
            for (int m = 0; m < 7; m++) {
                sv[m] = __expf(sv[m] - mx);
                sum += sv[m];
            }
#pragma unroll
            for (int off = 16; off; off >>= 1)
                sum += __shfl_xor_sync(0xffffffffu, sum, off);
            float inv = 1.f / sum;
#pragma unroll
            for (int m = 0; m < 7; m++) {
                int j = lane + m * 32;
                if (j < NPIX) {
                    g_p_h[zoff + (size_t)i * NPAD + j] = __float2half_rn(sv[m] * inv);
                } else if (j < NPAD) {
                    g_p_h[zoff + (size_t)i * NPAD + j] = __float2half_rn(0.f);
                }
            }
        }
    }
}

// ---------------- launch ----------------------------------------------------
extern "C" void kernel_launch(void* const* d_in, const int* in_sizes, int n_in,
                              void* d_out, int out_size)
{
    const float* x      = (const float*)d_in[0];
    const float* qkv_w  = (const float*)d_in[1];
    const float* qkv_g  = (const float*)d_in[2];
    const float* qkv_b  = (const float*)d_in[3];
    const float* qkv_m  = (const float*)d_in[4];
    const float* qkv_v  = (const float*)d_in[5];
    const float* dw_w   = (const float*)d_in[6];
    const float* dw_g   = (const float*)d_in[7];
    const float* dw_b   = (const float*)d_in[8];
    const float* dw_m   = (const float*)d_in[9];
    const float* dw_v   = (const float*)d_in[10];
    const float* proj_w = (const float*)d_in[11];
    const float* proj_g = (const float*)d_in[12];
    const float* proj_b = (const float*)d_in[13];
    const float* proj_m = (const float*)d_in[14];
    const float* proj_v = (const float*)d_in[15];
    const float* ab     = (const float*)d_in[16];
    const int*   bidx   = (const int*)d_in[17];
    float* out = (float*)d_out;

    float* qkvf;  cudaGetSymbolAddress((void**)&qkvf,  g_qkv);
    __half *qwh, *qwl, *pwh, *pwl, *xth, *xtl, *vh, *vl, *ph, *ath;
    cudaGetSymbolAddress((void**)&qwh, g_qw_h);  cudaGetSymbolAddress((void**)&qwl, g_qw_l);
    cudaGetSymbolAddress((void**)&pwh, g_pw_h);  cudaGetSymbolAddress((void**)&pwl, g_pw_l);
    cudaGetSymbolAddress((void**)&xth, g_xT_h);  cudaGetSymbolAddress((void**)&xtl, g_xT_l);
    cudaGetSymbolAddress((void**)&vh,  g_v_h);   cudaGetSymbolAddress((void**)&vl,  g_v_l);
    cudaGetSymbolAddress((void**)&ph,  g_p_h);
    cudaGetSymbolAddress((void**)&ath, g_at_h);

    // P0: convert weights + transpose/convert x
    convert_weights<<<(HQKV * DIM + 255) / 256, 256>>>(qkv_w, proj_w);
    transpose_x<<<dim3(7, 12, BATCH), dim3(32, 8)>>>(x);

    // K1: qkv = BN(W_qkv @ x)  3-term  -> fp32 rows<768, V planes rows>=768
    gemm_f16<1, true, false, 3><<<dim3(2, HQKV / 128, BATCH), 256>>>(
        qwh, qwl, xth, xtl,
        qkvf, vh, vl,
        DIM / 16, DIM, DIM,
        0L, 0L, 1,
        (long)NPIX * DIM, (long)768 * NPIX, (long)DH * NPAD,
        NPIX, NPAD, NPIX, 768,
        qkv_g, qkv_b, qkv_m, qkv_v);

    // K2: q <- BN(dwconv3x3(q))
    dwconv_bn<<<dim3(NH_KD, BATCH), 224>>>(dw_w, dw_g, dw_b, dw_m, dw_v);

    // K3: bias gather
    {
        int total = NHEADS * NPIX * NPIX;
        bias_gather<<<(total + 255) / 256, 256>>>(ab, bidx);
    }
    // K4: softmax -> P hi plane
    attn_softmax<<<dim3(NHEADS, BATCH), 256>>>();

    // K5: attT hi = relu(V @ P^T)^T  2-term  (per b,h)
    gemm_f16<2, false, true, 2><<<dim3(2, 1, BATCH * NHEADS), 256>>>(
        vh, vl, ph, nullptr,
        nullptr, ath, nullptr,
        NPAD / 16, NPAD, NPAD,
        (long)DH * NPAD, (long)128 * NPAD, NHEADS,
        (long)NPIX * NPAD, 0L, (long)NPIX * DH,
        0, DH, NPIX, 0,
        nullptr, nullptr, nullptr, nullptr);

    // K6: out = BN(W_proj @ att)  2-term  (B = attT hi, k-contig)
    gemm_f16<0, true, false, 2><<<dim3(2, DIM / 128, BATCH), 256>>>(
        pwh, pwl, ath, nullptr,
        out, nullptr, nullptr,
        DH / 16, DH, DH,
        0L, 0L, 1,
        (long)NPIX * DH, (long)DIM * NPIX, 0L,
        NPIX, 0, NPIX, DIM,
        proj_g, proj_b, proj_m, proj_v);
}

// round 10
// speedup vs baseline: 1.4053x; 1.0756x over previous
#include <cuda_runtime.h>
#include <cuda_fp16.h>
#include <math.h>
#include <stdint.h>

// ---------------- constants ----------------
#define BATCH   128
#define DIM     384
#define RES     14
#define NPIX    196
#define KEY_DIM 32
#define NHEADS  12
#define NH_KD   384
#define DH      1536
#define HQKV    2304
#define BN_EPS  1e-5f
#define NPAD    208     // NPIX padded to mult of 16

// ---------------- scratch ----------------
__device__ float g_qkv [ (size_t)BATCH * 768 * NPIX ];            // q+k fp32 only
__device__ float g_qdw [ (size_t)BATCH * NH_KD * NPIX ];
__device__ float g_bias[ (size_t)NHEADS * NPIX * NPIX ];

__device__ __half g_qw_h[ HQKV * DIM ],  g_qw_l[ HQKV * DIM ];
__device__ __half g_pw_h[ DIM * DH ],    g_pw_l[ DIM * DH ];
__device__ __half g_xT_h[ (size_t)BATCH * NPIX * DIM ],  g_xT_l[ (size_t)BATCH * NPIX * DIM ];
__device__ __half g_v_h [ (size_t)BATCH * DH * NPAD ],   g_v_l [ (size_t)BATCH * DH * NPAD ];
__device__ __half g_p_h [ (size_t)BATCH * NHEADS * NPIX * NPAD ];   // hi plane only
__device__ __half g_at_h[ (size_t)BATCH * NPIX * DH ];              // hi plane only

// ---------------- helpers ----------------
__device__ __forceinline__ uint32_t smem_u32(const void* p) {
    uint32_t a;
    asm("{ .reg .u64 t; cvta.to.shared.u64 t, %1; cvt.u32.u64 %0, t; }"
        : "=r"(a) : "l"(p));
    return a;
}
#define LDSM4(r, addr) \
    asm volatile("ldmatrix.sync.aligned.m8n8.x4.shared.b16 {%0,%1,%2,%3}, [%4];" \
        : "=r"((r)[0]), "=r"((r)[1]), "=r"((r)[2]), "=r"((r)[3]) : "r"(addr))
#define MMA_F16(d, a, bb) \
    asm volatile("mma.sync.aligned.m16n8k16.row.col.f32.f16.f16.f32 " \
        "{%0,%1,%2,%3}, {%4,%5,%6,%7}, {%8,%9}, {%0,%1,%2,%3};" \
        : "+f"((d)[0]), "+f"((d)[1]), "+f"((d)[2]), "+f"((d)[3]) \
        : "r"((a)[0]), "r"((a)[1]), "r"((a)[2]), "r"((a)[3]), \
          "r"((bb)[0]), "r"((bb)[1]))
#define CP_ASYNC16(dst, src, sz) \
    asm volatile("cp.async.cg.shared.global [%0], [%1], 16, %2;" \
                 :: "r"(dst), "l"(src), "r"(sz))
#define CP_COMMIT() asm volatile("cp.async.commit_group;" ::: "memory")
#define CP_WAIT(n)  asm volatile("cp.async.wait_group %0;" :: "n"(n) : "memory")

__device__ __forceinline__ void split_f16(float v, __half& h, __half& l) {
    h = __float2half_rn(v);
    l = __float2half_rn(v - __half2float(h));
}

// ================= pipelined fp16-plane GEMM (unchanged from R9) ============
template<int OUTMODE, bool HASBN, bool RELU, int TERMS>
__global__ void __launch_bounds__(256, 2)
gemm_f16(const __half* __restrict__ Ah, const __half* __restrict__ Al,
         const __half* __restrict__ Bh, const __half* __restrict__ Bl,
         float* __restrict__ Cf, __half* __restrict__ Ch, __half* __restrict__ Cl,
         int nchunks, int lda, int ldb,
         long aOuter, long aInner, int innerCnt,
         long bStride, long cfStride, long cpStride,
         int ldcF, int ldcP, int nrowsB, int mSplit,
         const float* __restrict__ bng, const float* __restrict__ bnb,
         const float* __restrict__ bnm, const float* __restrict__ bnv)
{
    constexpr int KP = 24;
    constexpr int NP = (TERMS == 3) ? 4 : 3;       // planes staged per chunk
    constexpr uint32_t PL = 128 * KP * 2;          // plane bytes
    __shared__ __align__(16) __half smbuf[2 * NP * 128 * KP];

    const int tid  = threadIdx.x;
    const int wid  = tid >> 5;
    const int lane = tid & 31;
    const int warp_m = wid & 3;
    const int warp_n = wid >> 2;
    const int n0 = blockIdx.x * 128;
    const int m0 = blockIdx.y * 128;
    const int z  = blockIdx.z;
    const int zb = z / innerCnt, zi = z - zb * innerCnt;

    const __half* Agh = Ah + (size_t)zb * aOuter + (size_t)zi * aInner + (size_t)m0 * lda;
    const __half* Agl = Al + (size_t)zb * aOuter + (size_t)zi * aInner + (size_t)m0 * lda;
    const __half* Bgh = Bh + (size_t)z * bStride;
    const __half* Bgl = (TERMS == 3) ? (Bl + (size_t)z * bStride) : nullptr;

    const uint32_t smb = smem_u32(smbuf);

    const bool full = (n0 + warp_n * 64 + 64) <= nrowsB;
    int jlim = nrowsB - (n0 + warp_n * 64);
    jlim = jlim <= 0 ? 0 : ((jlim + 7) >> 3);
    if (jlim > 8) jlim = 8;

    auto stage = [&](int ch, int s) {
        const int k0 = ch * 16;
#pragma unroll
        for (int i = 0; i < NP; i++) {
            int c    = i * 256 + tid;
            int p    = c >> 8;
            int row  = (c >> 1) & 127;
            int half = c & 1;
            uint32_t dst = smb + (uint32_t)(s * NP + p) * PL + (uint32_t)(row * KP + half * 8) * 2;
            const __half* src;
            unsigned sz = 16;
            if (p < 2) {
                src = (p == 0 ? Agh : Agl) + (size_t)row * lda + k0 + half * 8;
            } else {
                int rowg = n0 + row;
                bool ok = rowg < nrowsB;
                if (!ok) { rowg = 0; sz = 0; }
                src = (p == 2 ? Bgh : Bgl) + (size_t)rowg * ldb + k0 + half * 8;
            }
            CP_ASYNC16(dst, src, sz);
        }
        CP_COMMIT();
    };

    float acc[2][8][4];
#pragma unroll
    for (int t = 0; t < 2; t++)
#pragma unroll
        for (int j = 0; j < 8; j++)
#pragma unroll
            for (int c = 0; c < 4; c++) acc[t][j][c] = 0.f;

    stage(0, 0);

    for (int ch = 0; ch < nchunks; ch++) {
        const int s = ch & 1;
        if (ch + 1 < nchunks) { stage(ch + 1, s ^ 1); CP_WAIT(1); }
        else                  { CP_WAIT(0); }
        __syncthreads();

        const uint32_t base = smb + (uint32_t)s * NP * PL;
        const uint32_t aHi = base, aLo = base + PL, bHi = base + 2 * PL;
        const uint32_t bLo = base + 3 * PL;

        uint32_t a_hi[2][4], a_lo[2][4];
#pragma unroll
        for (int t = 0; t < 2; t++) {
            int row = warp_m * 32 + t * 16 + (lane & 15);
            int col = (lane >> 4) << 3;
            uint32_t off = (uint32_t)(row * KP + col) * 2;
            LDSM4(a_hi[t], aHi + off);
            LDSM4(a_lo[t], aLo + off);
        }
        int nrow = warp_n * 64 + (lane & 7) + ((lane >> 4) << 3);
        int bcol = ((lane >> 3) & 1) << 3;
        uint32_t boff = (uint32_t)(nrow * KP + bcol) * 2;

        if (full) {
            uint32_t b[8][2];
#pragma unroll
            for (int j = 0; j < 4; j++) {
                uint32_t r[4];
                LDSM4(r, bHi + boff + (uint32_t)(j * 16 * KP) * 2);
                b[2 * j][0] = r[0]; b[2 * j][1] = r[1];
                b[2 * j + 1][0] = r[2]; b[2 * j + 1][1] = r[3];
            }
#pragma unroll
            for (int t = 0; t < 2; t++)
#pragma unroll
                for (int j = 0; j < 8; j++) MMA_F16(acc[t][j], a_hi[t], b[j]);
#pragma unroll
            for (int t = 0; t < 2; t++)
#pragma unroll
                for (int j = 0; j < 8; j++) MMA_F16(acc[t][j], a_lo[t], b[j]);
            if (TERMS == 3) {
#pragma unroll
                for (int j = 0; j < 4; j++) {
                    uint32_t r[4];
                    LDSM4(r, bLo + boff + (uint32_t)(j * 16 * KP) * 2);
                    b[2 * j][0] = r[0]; b[2 * j][1] = r[1];
                    b[2 * j + 1][0] = r[2]; b[2 * j + 1][1] = r[3];
                }
#pragma unroll
                for (int t = 0; t < 2; t++)
#pragma unroll
                    for (int j = 0; j < 8; j++) MMA_F16(acc[t][j], a_hi[t], b[j]);
            }
        } else if (jlim > 0) {
            uint32_t b2[2][2];
            {
                uint32_t r[4];
                LDSM4(r, bHi + boff);
                b2[0][0] = r[0]; b2[0][1] = r[1];
                b2[1][0] = r[2]; b2[1][1] = r[3];
            }
#pragma unroll
            for (int t = 0; t < 2; t++)
#pragma unroll
                for (int j = 0; j < 2; j++)
                    if (j < jlim) MMA_F16(acc[t][j], a_hi[t], b2[j]);
#pragma unroll
            for (int t = 0; t < 2; t++)
#pragma unroll
                for (int j = 0; j < 2; j++)
                    if (j < jlim) MMA_F16(acc[t][j], a_lo[t], b2[j]);
            if (TERMS == 3) {
                uint32_t r[4];
                LDSM4(r, bLo + boff);
                b2[0][0] = r[0]; b2[0][1] = r[1];
                b2[1][0] = r[2]; b2[1][1] = r[3];
#pragma unroll
                for (int t = 0; t < 2; t++)
#pragma unroll
                    for (int j = 0; j < 2; j++)
                        if (j < jlim) MMA_F16(acc[t][j], a_hi[t], b2[j]);
            }
        }

        __syncthreads();
    }

    // ---------------- epilogues ----------------
    if (OUTMODE == 0 || OUTMODE == 1) {
        const bool isF32 = (OUTMODE == 0) || (m0 < mSplit);
#pragma unroll
        for (int t = 0; t < 2; t++) {
            int r0 = m0 + warp_m * 32 + t * 16 + (lane >> 2);
            int r1 = r0 + 8;
            float s0 = 1.f, h0 = 0.f, s1 = 1.f, h1 = 0.f;
            if (HASBN) {
                float a = bng[r0] * rsqrtf(bnv[r0] + BN_EPS);
                s0 = a; h0 = bnb[r0] - bnm[r0] * a;
                float c = bng[r1] * rsqrtf(bnv[r1] + BN_EPS);
                s1 = c; h1 = bnb[r1] - bnm[r1] * c;
            }
#pragma unroll
            for (int j = 0; j < 8; j++) {
                int nn = n0 + warp_n * 64 + j * 8 + 2 * (lane & 3);
                float v0 = acc[t][j][0] * s0 + h0;
                float v1 = acc[t][j][1] * s0 + h0;
                float v2 = acc[t][j][2] * s1 + h1;
                float v3 = acc[t][j][3] * s1 + h1;
                if (RELU) {
                    v0 = fmaxf(v0, 0.f); v1 = fmaxf(v1, 0.f);
                    v2 = fmaxf(v2, 0.f); v3 = fmaxf(v3, 0.f);
                }
                if (isF32) {
                    if (nn < NPIX) {
                        *(float2*)(Cf + (size_t)z * cfStride + (size_t)r0 * ldcF + nn) = make_float2(v0, v1);
                        *(float2*)(Cf + (size_t)z * cfStride + (size_t)r1 * ldcF + nn) = make_float2(v2, v3);
                    }
                } else {
                    if (nn < NPAD) {
                        if (nn >= NPIX) { v0 = v1 = v2 = v3 = 0.f; }
                        __half ha, la, hb, lb;
                        size_t p0 = (size_t)z * cpStride + (size_t)(r0 - mSplit) * ldcP + nn;
                        size_t p1 = (size_t)z * cpStride + (size_t)(r1 - mSplit) * ldcP + nn;
                        split_f16(v0, ha, la); split_f16(v1, hb, lb);
                        *(__half2*)(Ch + p0) = __half2(ha, hb);
                        *(__half2*)(Cl + p0) = __half2(la, lb);
                        split_f16(v2, ha, la); split_f16(v3, hb, lb);
                        *(__half2*)(Ch + p1) = __half2(ha, hb);
                        *(__half2*)(Cl + p1) = __half2(la, lb);
                    }
                }
            }
        }
    } else {
        __half* ep = smbuf;   // [128 i][136 d]
        __syncthreads();
#pragma unroll
        for (int t = 0; t < 2; t++) {
            int d0 = warp_m * 32 + t * 16 + (lane >> 2);
            int d1 = d0 + 8;
#pragma unroll
            for (int j = 0; j < 8; j++) {
                int il = warp_n * 64 + j * 8 + 2 * (lane & 3);
                float v0 = acc[t][j][0], v1 = acc[t][j][1];
                float v2 = acc[t][j][2], v3 = acc[t][j][3];
                if (RELU) {
                    v0 = fmaxf(v0, 0.f); v1 = fmaxf(v1, 0.f);
                    v2 = fmaxf(v2, 0.f); v3 = fmaxf(v3, 0.f);
                }
                ep[il * 136 + d0]       = __float2half_rn(v0);
                ep[(il + 1) * 136 + d0] = __float2half_rn(v1);
                ep[il * 136 + d1]       = __float2half_rn(v2);
                ep[(il + 1) * 136 + d1] = __float2half_rn(v3);
            }
        }
        __syncthreads();
        __half* dst = Ch + (size_t)zb * cpStride + (size_t)zi * 128;
        for (int c2 = tid; c2 < 2048; c2 += 256) {
            int row = c2 >> 4, off = (c2 & 15) * 8;
            int i = n0 + row;
            if (i < NPIX) {
                uint4 val = *(uint4*)(ep + row * 136 + off);
                *(uint4*)(dst + (size_t)i * ldcP + off) = val;
            }
        }
    }
}

// ---------------- pre-convert kernels ----------------
__global__ void convert_weights(const float* __restrict__ qw, const float* __restrict__ pw)
{
    int i = blockIdx.x * 256 + threadIdx.x;
    if (i < HQKV * DIM) split_f16(qw[i], g_qw_h[i], g_qw_l[i]);
    if (i < DIM * DH)   split_f16(pw[i], g_pw_h[i], g_pw_l[i]);
}

__global__ void transpose_x(const float* __restrict__ x)
{
    __shared__ float t[32][33];
    int p0 = blockIdx.x * 32, c0 = blockIdx.y * 32, b = blockIdx.z;
    for (int r = threadIdx.y; r < 32; r += 8) {
        int p = p0 + threadIdx.x;
        t[r][threadIdx.x] = (p < NPIX) ? x[((size_t)b * DIM + c0 + r) * NPIX + p] : 0.f;
    }
    __syncthreads();
    for (int r = threadIdx.y; r < 32; r += 8) {
        int p = p0 + r, c = c0 + threadIdx.x;
        if (p < NPIX) {
            size_t o = ((size_t)b * NPIX + p) * DIM + c;
            split_f16(t[threadIdx.x][r], g_xT_h[o], g_xT_l[o]);
        }
    }
}

// ---------------- dwconv + BN: 4 channels per block --------------------------
__global__ void __launch_bounds__(224, 8)
dwconv_bn(const float* __restrict__ w,
          const float* __restrict__ bng,
          const float* __restrict__ bnb,
          const float* __restrict__ bnm,
          const float* __restrict__ bnv)
{
    const int c0 = blockIdx.x * 4;
    const int b  = blockIdx.y;
    __shared__ float t[4][200];
    __shared__ float wgt[4][9];
    __shared__ float sBN[4][2];

    const float* src = g_qkv + (size_t)b * 768 * NPIX + (size_t)c0 * NPIX;
    int tid = threadIdx.x;
    for (int e = tid; e < 4 * NPIX; e += 224) {
        int ch = e / NPIX, p = e - ch * NPIX;
        t[ch][p] = src[ch * NPIX + p];
    }
    if (tid < 36) wgt[tid / 9][tid % 9] = w[c0 * 9 + tid];
    if (tid < 4) {
        int c = c0 + tid;
        float s = bng[c] * rsqrtf(bnv[c] + BN_EPS);
        sBN[tid][0] = s;
        sBN[tid][1] = bnb[c] - bnm[c] * s;
    }
    __syncthreads();

    if (tid < NPIX) {
        int y = tid / RES, x = tid - y * RES;
#pragma unroll
        for (int ch = 0; ch < 4; ch++) {
            float acc = 0.f;
#pragma unroll
            for (int ky = 0; ky < 3; ky++) {
                int yy = y + ky - 1;
                if (yy < 0 || yy >= RES) continue;
#pragma unroll
                for (int kx = 0; kx < 3; kx++) {
                    int xx = x + kx - 1;
                    if (xx < 0 || xx >= RES) continue;
                    acc += t[ch][yy * RES + xx] * wgt[ch][ky * 3 + kx];
                }
            }
            g_qdw[((size_t)b * NH_KD + c0 + ch) * NPIX + tid] = acc * sBN[ch][0] + sBN[ch][1];
        }
    }
}

// ---------------- bias gather ----------------
__global__ void bias_gather(const float* __restrict__ ab, const int* __restrict__ idxs)
{
    int idx = blockIdx.x * 256 + threadIdx.x;
    if (idx >= NHEADS * NPIX * NPIX) return;
    int h  = idx / (NPIX * NPIX);
    int ij = idx % (NPIX * NPIX);
    g_bias[idx] = ab[h * NPIX + idxs[ij]];
}

// ---------------- softmax: 4 rows/warp (low regs, high occ) -----------------
__global__ void attn_softmax(void)
{
    const int h = blockIdx.x;
    const int b = blockIdx.y;
    __shared__ float k_s[32 * 224];

    const float* qg = g_qdw + (size_t)b * NH_KD * NPIX + (size_t)h * KEY_DIM * NPIX;
    const float* kg = g_qkv + (size_t)b * 768 * NPIX + (size_t)(NH_KD + h * KEY_DIM) * NPIX;

    for (int idx = threadIdx.x; idx < 32 * 224; idx += 256) {
        int d = idx / 224, j = idx % 224;
        k_s[idx] = (j < NPIX) ? kg[d * NPIX + j] : 0.f;
    }
    __syncthreads();

    const int w    = threadIdx.x >> 5;
    const int lane = threadIdx.x & 31;
    const float* bh = g_bias + (size_t)h * NPIX * NPIX;
    const size_t zoff = ((size_t)b * NHEADS + h) * NPIX * NPAD;
    const float scale = 0.17677669529663687f;

    for (int i0 = w * 4; i0 < NPIX; i0 += 32) {
        float q_reg[4];
#pragma unroll
        for (int r = 0; r < 4; r++) {
            int i = i0 + r;
            q_reg[r] = (i < NPIX) ? qg[(size_t)lane * NPIX + i] : 0.f;
        }

        float s[4][7];
#pragma unroll
        for (int r = 0; r < 4; r++)
#pragma unroll
            for (int m = 0; m < 7; m++) s[r][m] = 0.f;

        for (int d = 0; d < 32; d++) {
            float qv[4];
#pragma unroll
            for (int r = 0; r < 4; r++)
                qv[r] = __shfl_sync(0xffffffffu, q_reg[r], d);
#pragma unroll
            for (int m = 0; m < 7; m++) {
                float kv = k_s[d * 224 + lane + m * 32];
#pragma unroll
                for (int r = 0; r < 4; r++) s[r][m] += qv[r] * kv;
            }
        }

#pragma unroll
        for (int r = 0; r < 4; r++) {
            int i = i0 + r;
            if (i >= NPIX) break;
            float sv[7];
            float mx = -1e30f;
#pragma unroll
            for (int m = 0; m < 7; m++) {
                int j = lane + m * 32;
                float val = (j < NPIX) ? s[r][m] * scale + bh[(size_t)i * NPIX + j]
                                       : -1e30f;
                sv[m] = val;
                mx = fmaxf(mx, val);
            }
#pragma unroll
            for (int off = 16; off; off >>= 1)
                mx = fmaxf(mx, __shfl_xor_sync(0xffffffffu, mx, off));
            float sum = 0.f;
#pragma unroll
            for (int m = 0; m < 7; m++) {
                sv[m] = __expf(sv[m] - mx);
                sum += sv[m];
            }
#pragma unroll
            for (int off = 16; off; off >>= 1)
                sum += __shfl_xor_sync(0xffffffffu, sum, off);
            float inv = 1.f / sum;
#pragma unroll
            for (int m = 0; m < 7; m++) {
                int j = lane + m * 32;
                if (j < NPIX) {
                    g_p_h[zoff + (size_t)i * NPAD + j] = __float2half_rn(sv[m] * inv);
                } else if (j < NPAD) {
                    g_p_h[zoff + (size_t)i * NPAD + j] = __float2half_rn(0.f);
                }
            }
        }
    }
}

// ---------------- launch ----------------------------------------------------
extern "C" void kernel_launch(void* const* d_in, const int* in_sizes, int n_in,
                              void* d_out, int out_size)
{
    const float* x      = (const float*)d_in[0];
    const float* qkv_w  = (const float*)d_in[1];
    const float* qkv_g  = (const float*)d_in[2];
    const float* qkv_b  = (const float*)d_in[3];
    const float* qkv_m  = (const float*)d_in[4];
    const float* qkv_v  = (const float*)d_in[5];
    const float* dw_w   = (const float*)d_in[6];
    const float* dw_g   = (const float*)d_in[7];
    const float* dw_b   = (const float*)d_in[8];
    const float* dw_m   = (const float*)d_in[9];
    const float* dw_v   = (const float*)d_in[10];
    const float* proj_w = (const float*)d_in[11];
    const float* proj_g = (const float*)d_in[12];
    const float* proj_b = (const float*)d_in[13];
    const float* proj_m = (const float*)d_in[14];
    const float* proj_v = (const float*)d_in[15];
    const float* ab     = (const float*)d_in[16];
    const int*   bidx   = (const int*)d_in[17];
    float* out = (float*)d_out;

    float* qkvf;  cudaGetSymbolAddress((void**)&qkvf,  g_qkv);
    __half *qwh, *qwl, *pwh, *pwl, *xth, *xtl, *vh, *vl, *ph, *ath;
    cudaGetSymbolAddress((void**)&qwh, g_qw_h);  cudaGetSymbolAddress((void**)&qwl, g_qw_l);
    cudaGetSymbolAddress((void**)&pwh, g_pw_h);  cudaGetSymbolAddress((void**)&pwl, g_pw_l);
    cudaGetSymbolAddress((void**)&xth, g_xT_h);  cudaGetSymbolAddress((void**)&xtl, g_xT_l);
    cudaGetSymbolAddress((void**)&vh,  g_v_h);   cudaGetSymbolAddress((void**)&vl,  g_v_l);
    cudaGetSymbolAddress((void**)&ph,  g_p_h);
    cudaGetSymbolAddress((void**)&ath, g_at_h);

    // P0: convert weights + transpose/convert x
    convert_weights<<<(HQKV * DIM + 255) / 256, 256>>>(qkv_w, proj_w);
    transpose_x<<<dim3(7, 12, BATCH), dim3(32, 8)>>>(x);

    // K1: qkv = BN(W_qkv @ x)  3-term  -> fp32 rows<768, V planes rows>=768
    gemm_f16<1, true, false, 3><<<dim3(2, HQKV / 128, BATCH), 256>>>(
        qwh, qwl, xth, xtl,
        qkvf, vh, vl,
        DIM / 16, DIM, DIM,
        0L, 0L, 1,
        (long)NPIX * DIM, (long)768 * NPIX, (long)DH * NPAD,
        NPIX, NPAD, NPIX, 768,
        qkv_g, qkv_b, qkv_m, qkv_v);

    // K2: q <- BN(dwconv3x3(q))  (4 channels per block)
    dwconv_bn<<<dim3(NH_KD / 4, BATCH), 224>>>(dw_w, dw_g, dw_b, dw_m, dw_v);

    // K3: bias gather
    {
        int total = NHEADS * NPIX * NPIX;
        bias_gather<<<(total + 255) / 256, 256>>>(ab, bidx);
    }
    // K4: softmax -> P hi plane
    attn_softmax<<<dim3(NHEADS, BATCH), 256>>>();

    // K5: attT hi = relu(V @ P^T)^T  2-term  (per b,h)
    gemm_f16<2, false, true, 2><<<dim3(2, 1, BATCH * NHEADS), 256>>>(
        vh, vl, ph, nullptr,
        nullptr, ath, nullptr,
        NPAD / 16, NPAD, NPAD,
        (long)DH * NPAD, (long)128 * NPAD, NHEADS,
        (long)NPIX * NPAD, 0L, (long)NPIX * DH,
        0, DH, NPIX, 0,
        nullptr, nullptr, nullptr, nullptr);

    // K6: out = BN(W_proj @ att)  2-term  (B = attT hi, k-contig)
    gemm_f16<0, true, false, 2><<<dim3(2, DIM / 128, BATCH), 256>>>(
        pwh, pwl, ath, nullptr,
        out, nullptr, nullptr,
        DH / 16, DH, DH,
        0L, 0L, 1,
        (long)NPIX * DH, (long)DIM * NPIX, 0L,
        NPIX, 0, NPIX, DIM,
        proj_g, proj_b, proj_m, proj_v);
}

// round 11
// speedup vs baseline: 1.4890x; 1.0596x over previous
#include <cuda_runtime.h>
#include <cuda_fp16.h>
#include <math.h>
#include <stdint.h>

// ---------------- constants ----------------
#define BATCH   128
#define DIM     384
#define RES     14
#define NPIX    196
#define KEY_DIM 32
#define NHEADS  12
#define NH_KD   384
#define DH      1536
#define HQKV    2304
#define BN_EPS  1e-5f
#define NPAD    208     // NPIX padded to mult of 16

// ---------------- scratch ----------------
__device__ float g_qkv [ (size_t)BATCH * 768 * NPIX ];            // q+k fp32 only
__device__ float g_qdw [ (size_t)BATCH * NH_KD * NPIX ];
__device__ float g_bias[ (size_t)NHEADS * NPIX * NPIX ];

__device__ __half g_qw_h[ HQKV * DIM ],  g_qw_l[ HQKV * DIM ];
__device__ __half g_pw_h[ DIM * DH ],    g_pw_l[ DIM * DH ];
__device__ __half g_xT_h[ (size_t)BATCH * NPIX * DIM ],  g_xT_l[ (size_t)BATCH * NPIX * DIM ];
__device__ __half g_v_h [ (size_t)BATCH * DH * NPAD ],   g_v_l [ (size_t)BATCH * DH * NPAD ];
__device__ __half g_p_h [ (size_t)BATCH * NHEADS * NPIX * NPAD ];   // hi plane only
__device__ __half g_at_h[ (size_t)BATCH * NPIX * DH ];              // hi plane only

// ---------------- helpers ----------------
__device__ __forceinline__ uint32_t smem_u32(const void* p) {
    uint32_t a;
    asm("{ .reg .u64 t; cvta.to.shared.u64 t, %1; cvt.u32.u64 %0, t; }"
        : "=r"(a) : "l"(p));
    return a;
}
#define LDSM4(r, addr) \
    asm volatile("ldmatrix.sync.aligned.m8n8.x4.shared.b16 {%0,%1,%2,%3}, [%4];" \
        : "=r"((r)[0]), "=r"((r)[1]), "=r"((r)[2]), "=r"((r)[3]) : "r"(addr))
#define MMA_F16(d, a, bb) \
    asm volatile("mma.sync.aligned.m16n8k16.row.col.f32.f16.f16.f32 " \
        "{%0,%1,%2,%3}, {%4,%5,%6,%7}, {%8,%9}, {%0,%1,%2,%3};" \
        : "+f"((d)[0]), "+f"((d)[1]), "+f"((d)[2]), "+f"((d)[3]) \
        : "r"((a)[0]), "r"((a)[1]), "r"((a)[2]), "r"((a)[3]), \
          "r"((bb)[0]), "r"((bb)[1]))
#define CP_ASYNC16(dst, src, sz) \
    asm volatile("cp.async.cg.shared.global [%0], [%1], 16, %2;" \
                 :: "r"(dst), "l"(src), "r"(sz))
#define CP_COMMIT() asm volatile("cp.async.commit_group;" ::: "memory")
#define CP_WAIT(n)  asm volatile("cp.async.wait_group %0;" :: "n"(n) : "memory")

__device__ __forceinline__ void split_f16(float v, __half& h, __half& l) {
    h = __float2half_rn(v);
    l = __float2half_rn(v - __half2float(h));
}

// ================= pipelined fp16-plane GEMM =================
// TERMS=3: hh + lo_A*hi_B + hi_A*lo_B ; TERMS=2: hh + lo_A*hi_B (B-lo never staged)
// OUTMODE: 0 = fp32 out; 1 = fp32 if m0<mSplit else fp16 h/l planes (pad zeroed);
//          2 = transposed fp16 HI plane only  C^T[n][zi*128+m].
template<int OUTMODE, bool HASBN, bool RELU, int TERMS>
__global__ void __launch_bounds__(256, 2)
gemm_f16(const __half* __restrict__ Ah, const __half* __restrict__ Al,
         const __half* __restrict__ Bh, const __half* __restrict__ Bl,
         float* __restrict__ Cf, __half* __restrict__ Ch, __half* __restrict__ Cl,
         int nchunks, int lda, int ldb,
         long aOuter, long aInner, int innerCnt,
         long bStride, long cfStride, long cpStride,
         int ldcF, int ldcP, int nrowsB, int mSplit,
         const float* __restrict__ bng, const float* __restrict__ bnb,
         const float* __restrict__ bnm, const float* __restrict__ bnv)
{
    constexpr int KP = 24;
    constexpr int NP = (TERMS == 3) ? 4 : 3;       // planes staged per chunk
    constexpr uint32_t PL = 128 * KP * 2;          // plane bytes
    __shared__ __align__(16) __half smbuf[2 * NP * 128 * KP];

    const int tid  = threadIdx.x;
    const int wid  = tid >> 5;
    const int lane = tid & 31;
    const int warp_m = wid & 3;
    const int warp_n = wid >> 2;
    const int n0 = blockIdx.x * 128;
    const int m0 = blockIdx.y * 128;
    const int z  = blockIdx.z;
    const int zb = z / innerCnt, zi = z - zb * innerCnt;

    const __half* Agh = Ah + (size_t)zb * aOuter + (size_t)zi * aInner + (size_t)m0 * lda;
    const __half* Agl = Al + (size_t)zb * aOuter + (size_t)zi * aInner + (size_t)m0 * lda;
    const __half* Bgh = Bh + (size_t)z * bStride;
    const __half* Bgl = (TERMS == 3) ? (Bl + (size_t)z * bStride) : nullptr;

    const uint32_t smb = smem_u32(smbuf);

    const bool full = (n0 + warp_n * 64 + 64) <= nrowsB;
    int jlim = nrowsB - (n0 + warp_n * 64);
    jlim = jlim <= 0 ? 0 : ((jlim + 7) >> 3);
    if (jlim > 8) jlim = 8;

    auto stage = [&](int ch, int s) {
        const int k0 = ch * 16;
#pragma unroll
        for (int i = 0; i < NP; i++) {
            int c    = i * 256 + tid;
            int p    = c >> 8;
            int row  = (c >> 1) & 127;
            int half = c & 1;
            uint32_t dst = smb + (uint32_t)(s * NP + p) * PL + (uint32_t)(row * KP + half * 8) * 2;
            const __half* src;
            unsigned sz = 16;
            if (p < 2) {
                src = (p == 0 ? Agh : Agl) + (size_t)row * lda + k0 + half * 8;
            } else {
                int rowg = n0 + row;
                bool ok = rowg < nrowsB;
                if (!ok) { rowg = 0; sz = 0; }
                src = (p == 2 ? Bgh : Bgl) + (size_t)rowg * ldb + k0 + half * 8;
            }
            CP_ASYNC16(dst, src, sz);
        }
        CP_COMMIT();
    };

    float acc[2][8][4];
#pragma unroll
    for (int t = 0; t < 2; t++)
#pragma unroll
        for (int j = 0; j < 8; j++)
#pragma unroll
            for (int c = 0; c < 4; c++) acc[t][j][c] = 0.f;

    stage(0, 0);

    for (int ch = 0; ch < nchunks; ch++) {
        const int s = ch & 1;
        if (ch + 1 < nchunks) { stage(ch + 1, s ^ 1); CP_WAIT(1); }
        else                  { CP_WAIT(0); }
        __syncthreads();

        const uint32_t base = smb + (uint32_t)s * NP * PL;
        const uint32_t aHi = base, aLo = base + PL, bHi = base + 2 * PL;
        const uint32_t bLo = base + 3 * PL;

        uint32_t a_hi[2][4], a_lo[2][4];
#pragma unroll
        for (int t = 0; t < 2; t++) {
            int row = warp_m * 32 + t * 16 + (lane & 15);
            int col = (lane >> 4) << 3;
            uint32_t off = (uint32_t)(row * KP + col) * 2;
            LDSM4(a_hi[t], aHi + off);
            LDSM4(a_lo[t], aLo + off);
        }
        int nrow = warp_n * 64 + (lane & 7) + ((lane >> 4) << 3);
        int bcol = ((lane >> 3) & 1) << 3;
        uint32_t boff = (uint32_t)(nrow * KP + bcol) * 2;

        if (full) {
            uint32_t b[8][2];
#pragma unroll
            for (int j = 0; j < 4; j++) {
                uint32_t r[4];
                LDSM4(r, bHi + boff + (uint32_t)(j * 16 * KP) * 2);
                b[2 * j][0] = r[0]; b[2 * j][1] = r[1];
                b[2 * j + 1][0] = r[2]; b[2 * j + 1][1] = r[3];
            }
#pragma unroll
            for (int t = 0; t < 2; t++)
#pragma unroll
                for (int j = 0; j < 8; j++) MMA_F16(acc[t][j], a_hi[t], b[j]);
#pragma unroll
            for (int t = 0; t < 2; t++)
#pragma unroll
                for (int j = 0; j < 8; j++) MMA_F16(acc[t][j], a_lo[t], b[j]);
            if (TERMS == 3) {
#pragma unroll
                for (int j = 0; j < 4; j++) {
                    uint32_t r[4];
                    LDSM4(r, bLo + boff + (uint32_t)(j * 16 * KP) * 2);
                    b[2 * j][0] = r[0]; b[2 * j][1] = r[1];
                    b[2 * j + 1][0] = r[2]; b[2 * j + 1][1] = r[3];
                }
#pragma unroll
                for (int t = 0; t < 2; t++)
#pragma unroll
                    for (int j = 0; j < 8; j++) MMA_F16(acc[t][j], a_hi[t], b[j]);
            }
        } else if (jlim > 0) {
            uint32_t b2[2][2];
            {
                uint32_t r[4];
                LDSM4(r, bHi + boff);
                b2[0][0] = r[0]; b2[0][1] = r[1];
                b2[1][0] = r[2]; b2[1][1] = r[3];
            }
#pragma unroll
            for (int t = 0; t < 2; t++)
#pragma unroll
                for (int j = 0; j < 2; j++)
                    if (j < jlim) MMA_F16(acc[t][j], a_hi[t], b2[j]);
#pragma unroll
            for (int t = 0; t < 2; t++)
#pragma unroll
                for (int j = 0; j < 2; j++)
                    if (j < jlim) MMA_F16(acc[t][j], a_lo[t], b2[j]);
            if (TERMS == 3) {
                uint32_t r[4];
                LDSM4(r, bLo + boff);
                b2[0][0] = r[0]; b2[0][1] = r[1];
                b2[1][0] = r[2]; b2[1][1] = r[3];
#pragma unroll
                for (int t = 0; t < 2; t++)
#pragma unroll
                    for (int j = 0; j < 2; j++)
                        if (j < jlim) MMA_F16(acc[t][j], a_hi[t], b2[j]);
            }
        }

        __syncthreads();
    }

    // ---------------- epilogues ----------------
    if (OUTMODE == 0 || OUTMODE == 1) {
        const bool isF32 = (OUTMODE == 0) || (m0 < mSplit);
#pragma unroll
        for (int t = 0; t < 2; t++) {
            int r0 = m0 + warp_m * 32 + t * 16 + (lane >> 2);
            int r1 = r0 + 8;
            float s0 = 1.f, h0 = 0.f, s1 = 1.f, h1 = 0.f;
            if (HASBN) {
                float a = bng[r0] * rsqrtf(bnv[r0] + BN_EPS);
                s0 = a; h0 = bnb[r0] - bnm[r0] * a;
                float c = bng[r1] * rsqrtf(bnv[r1] + BN_EPS);
                s1 = c; h1 = bnb[r1] - bnm[r1] * c;
            }
#pragma unroll
            for (int j = 0; j < 8; j++) {
                int nn = n0 + warp_n * 64 + j * 8 + 2 * (lane & 3);
                float v0 = acc[t][j][0] * s0 + h0;
                float v1 = acc[t][j][1] * s0 + h0;
                float v2 = acc[t][j][2] * s1 + h1;
                float v3 = acc[t][j][3] * s1 + h1;
                if (RELU) {
                    v0 = fmaxf(v0, 0.f); v1 = fmaxf(v1, 0.f);
                    v2 = fmaxf(v2, 0.f); v3 = fmaxf(v3, 0.f);
                }
                if (isF32) {
                    if (nn < NPIX) {
                        *(float2*)(Cf + (size_t)z * cfStride + (size_t)r0 * ldcF + nn) = make_float2(v0, v1);
                        *(float2*)(Cf + (size_t)z * cfStride + (size_t)r1 * ldcF + nn) = make_float2(v2, v3);
                    }
                } else {
                    if (nn < NPAD) {
                        if (nn >= NPIX) { v0 = v1 = v2 = v3 = 0.f; }
                        __half ha, la, hb, lb;
                        size_t p0 = (size_t)z * cpStride + (size_t)(r0 - mSplit) * ldcP + nn;
                        size_t p1 = (size_t)z * cpStride + (size_t)(r1 - mSplit) * ldcP + nn;
                        split_f16(v0, ha, la); split_f16(v1, hb, lb);
                        *(__half2*)(Ch + p0) = __half2(ha, hb);
                        *(__half2*)(Cl + p0) = __half2(la, lb);
                        split_f16(v2, ha, la); split_f16(v3, hb, lb);
                        *(__half2*)(Ch + p1) = __half2(ha, hb);
                        *(__half2*)(Cl + p1) = __half2(la, lb);
                    }
                }
            }
        }
    } else {
        __half* ep = smbuf;   // [128 i][136 d]
        __syncthreads();
#pragma unroll
        for (int t = 0; t < 2; t++) {
            int d0 = warp_m * 32 + t * 16 + (lane >> 2);
            int d1 = d0 + 8;
#pragma unroll
            for (int j = 0; j < 8; j++) {
                int il = warp_n * 64 + j * 8 + 2 * (lane & 3);
                float v0 = acc[t][j][0], v1 = acc[t][j][1];
                float v2 = acc[t][j][2], v3 = acc[t][j][3];
                if (RELU) {
                    v0 = fmaxf(v0, 0.f); v1 = fmaxf(v1, 0.f);
                    v2 = fmaxf(v2, 0.f); v3 = fmaxf(v3, 0.f);
                }
                ep[il * 136 + d0]       = __float2half_rn(v0);
                ep[(il + 1) * 136 + d0] = __float2half_rn(v1);
                ep[il * 136 + d1]       = __float2half_rn(v2);
                ep[(il + 1) * 136 + d1] = __float2half_rn(v3);
            }
        }
        __syncthreads();
        __half* dst = Ch + (size_t)zb * cpStride + (size_t)zi * 128;
        for (int c2 = tid; c2 < 2048; c2 += 256) {
            int row = c2 >> 4, off = (c2 & 15) * 8;
            int i = n0 + row;
            if (i < NPIX) {
                uint4 val = *(uint4*)(ep + row * 136 + off);
                *(uint4*)(dst + (size_t)i * ldcP + off) = val;
            }
        }
    }
}

// ---------------- pre-convert kernels ----------------
__global__ void convert_weights(const float* __restrict__ qw, const float* __restrict__ pw)
{
    int i = blockIdx.x * 256 + threadIdx.x;
    if (i < HQKV * DIM) split_f16(qw[i], g_qw_h[i], g_qw_l[i]);
    if (i < DIM * DH)   split_f16(pw[i], g_pw_h[i], g_pw_l[i]);
}

__global__ void transpose_x(const float* __restrict__ x)
{
    __shared__ float t[32][33];
    int p0 = blockIdx.x * 32, c0 = blockIdx.y * 32, b = blockIdx.z;
    for (int r = threadIdx.y; r < 32; r += 8) {
        int p = p0 + threadIdx.x;
        t[r][threadIdx.x] = (p < NPIX) ? x[((size_t)b * DIM + c0 + r) * NPIX + p] : 0.f;
    }
    __syncthreads();
    for (int r = threadIdx.y; r < 32; r += 8) {
        int p = p0 + r, c = c0 + threadIdx.x;
        if (p < NPIX) {
            size_t o = ((size_t)b * NPIX + p) * DIM + c;
            split_f16(t[threadIdx.x][r], g_xT_h[o], g_xT_l[o]);
        }
    }
}

// ---------------- dwconv + BN: 4 channels per block --------------------------
__global__ void __launch_bounds__(224, 8)
dwconv_bn(const float* __restrict__ w,
          const float* __restrict__ bng,
          const float* __restrict__ bnb,
          const float* __restrict__ bnm,
          const float* __restrict__ bnv)
{
    const int c0 = blockIdx.x * 4;
    const int b  = blockIdx.y;
    __shared__ float t[4][200];
    __shared__ float wgt[4][9];
    __shared__ float sBN[4][2];

    const float* src = g_qkv + (size_t)b * 768 * NPIX + (size_t)c0 * NPIX;
    int tid = threadIdx.x;
    for (int e = tid; e < 4 * NPIX; e += 224) {
        int ch = e / NPIX, p = e - ch * NPIX;
        t[ch][p] = src[ch * NPIX + p];
    }
    if (tid < 36) wgt[tid / 9][tid % 9] = w[c0 * 9 + tid];
    if (tid < 4) {
        int c = c0 + tid;
        float s = bng[c] * rsqrtf(bnv[c] + BN_EPS);
        sBN[tid][0] = s;
        sBN[tid][1] = bnb[c] - bnm[c] * s;
    }
    __syncthreads();

    if (tid < NPIX) {
        int y = tid / RES, x = tid - y * RES;
#pragma unroll
        for (int ch = 0; ch < 4; ch++) {
            float acc = 0.f;
#pragma unroll
            for (int ky = 0; ky < 3; ky++) {
                int yy = y + ky - 1;
                if (yy < 0 || yy >= RES) continue;
#pragma unroll
                for (int kx = 0; kx < 3; kx++) {
                    int xx = x + kx - 1;
                    if (xx < 0 || xx >= RES) continue;
                    acc += t[ch][yy * RES + xx] * wgt[ch][ky * 3 + kx];
                }
            }
            g_qdw[((size_t)b * NH_KD + c0 + ch) * NPIX + tid] = acc * sBN[ch][0] + sBN[ch][1];
        }
    }
}

// ---------------- bias gather ----------------
__global__ void bias_gather(const float* __restrict__ ab, const int* __restrict__ idxs)
{
    int idx = blockIdx.x * 256 + threadIdx.x;
    if (idx >= NHEADS * NPIX * NPIX) return;
    int h  = idx / (NPIX * NPIX);
    int ij = idx % (NPIX * NPIX);
    g_bias[idx] = ab[h * NPIX + idxs[ij]];
}

// ---------------- softmax: 4 rows/warp (low regs, high occ) -----------------
__global__ void attn_softmax(void)
{
    const int h = blockIdx.x;
    const int b = blockIdx.y;
    __shared__ float k_s[32 * 224];

    const float* qg = g_qdw + (size_t)b * NH_KD * NPIX + (size_t)h * KEY_DIM * NPIX;
    const float* kg = g_qkv + (size_t)b * 768 * NPIX + (size_t)(NH_KD + h * KEY_DIM) * NPIX;

    for (int idx = threadIdx.x; idx < 32 * 224; idx += 256) {
        int d = idx / 224, j = idx % 224;
        k_s[idx] = (j < NPIX) ? kg[d * NPIX + j] : 0.f;
    }
    __syncthreads();

    const int w    = threadIdx.x >> 5;
    const int lane = threadIdx.x & 31;
    const float* bh = g_bias + (size_t)h * NPIX * NPIX;
    const size_t zoff = ((size_t)b * NHEADS + h) * NPIX * NPAD;
    const float scale = 0.17677669529663687f;

    for (int i0 = w * 4; i0 < NPIX; i0 += 32) {
        float q_reg[4];
#pragma unroll
        for (int r = 0; r < 4; r++) {
            int i = i0 + r;
            q_reg[r] = (i < NPIX) ? qg[(size_t)lane * NPIX + i] : 0.f;
        }

        float s[4][7];
#pragma unroll
        for (int r = 0; r < 4; r++)
#pragma unroll
            for (int m = 0; m < 7; m++) s[r][m] = 0.f;

        for (int d = 0; d < 32; d++) {
            float qv[4];
#pragma unroll
            for (int r = 0; r < 4; r++)
                qv[r] = __shfl_sync(0xffffffffu, q_reg[r], d);
#pragma unroll
            for (int m = 0; m < 7; m++) {
                float kv = k_s[d * 224 + lane + m * 32];
#pragma unroll
                for (int r = 0; r < 4; r++) s[r][m] += qv[r] * kv;
            }
        }

#pragma unroll
        for (int r = 0; r < 4; r++) {
            int i = i0 + r;
            if (i >= NPIX) break;
            float sv[7];
            float mx = -1e30f;
#pragma unroll
            for (int m = 0; m < 7; m++) {
                int j = lane + m * 32;
                float val = (j < NPIX) ? s[r][m] * scale + bh[(size_t)i * NPIX + j]
                                       : -1e30f;
                sv[m] = val;
                mx = fmaxf(mx, val);
            }
#pragma unroll
            for (int off = 16; off; off >>= 1)
                mx = fmaxf(mx, __shfl_xor_sync(0xffffffffu, mx, off));
            float sum = 0.f;
#pragma unroll
            for (int m = 0; m < 7; m++) {
                sv[m] = __expf(sv[m] - mx);
                sum += sv[m];
            }
#pragma unroll
            for (int off = 16; off; off >>= 1)
                sum += __shfl_xor_sync(0xffffffffu, sum, off);
            float inv = 1.f / sum;
#pragma unroll
            for (int m = 0; m < 7; m++) {
                int j = lane + m * 32;
                if (j < NPIX) {
                    g_p_h[zoff + (size_t)i * NPAD + j] = __float2half_rn(sv[m] * inv);
                } else if (j < NPAD) {
                    g_p_h[zoff + (size_t)i * NPAD + j] = __float2half_rn(0.f);
                }
            }
        }
    }
}

// ---------------- launch ----------------------------------------------------
extern "C" void kernel_launch(void* const* d_in, const int* in_sizes, int n_in,
                              void* d_out, int out_size)
{
    const float* x      = (const float*)d_in[0];
    const float* qkv_w  = (const float*)d_in[1];
    const float* qkv_g  = (const float*)d_in[2];
    const float* qkv_b  = (const float*)d_in[3];
    const float* qkv_m  = (const float*)d_in[4];
    const float* qkv_v  = (const float*)d_in[5];
    const float* dw_w   = (const float*)d_in[6];
    const float* dw_g   = (const float*)d_in[7];
    const float* dw_b   = (const float*)d_in[8];
    const float* dw_m   = (const float*)d_in[9];
    const float* dw_v   = (const float*)d_in[10];
    const float* proj_w = (const float*)d_in[11];
    const float* proj_g = (const float*)d_in[12];
    const float* proj_b = (const float*)d_in[13];
    const float* proj_m = (const float*)d_in[14];
    const float* proj_v = (const float*)d_in[15];
    const float* ab     = (const float*)d_in[16];
    const int*   bidx   = (const int*)d_in[17];
    float* out = (float*)d_out;

    float* qkvf;  cudaGetSymbolAddress((void**)&qkvf,  g_qkv);
    __half *qwh, *qwl, *pwh, *pwl, *xth, *xtl, *vh, *vl, *ph, *ath;
    cudaGetSymbolAddress((void**)&qwh, g_qw_h);  cudaGetSymbolAddress((void**)&qwl, g_qw_l);
    cudaGetSymbolAddress((void**)&pwh, g_pw_h);  cudaGetSymbolAddress((void**)&pwl, g_pw_l);
    cudaGetSymbolAddress((void**)&xth, g_xT_h);  cudaGetSymbolAddress((void**)&xtl, g_xT_l);
    cudaGetSymbolAddress((void**)&vh,  g_v_h);   cudaGetSymbolAddress((void**)&vl,  g_v_l);
    cudaGetSymbolAddress((void**)&ph,  g_p_h);
    cudaGetSymbolAddress((void**)&ath, g_at_h);

    // P0: convert weights + transpose/convert x
    convert_weights<<<(HQKV * DIM + 255) / 256, 256>>>(qkv_w, proj_w);
    transpose_x<<<dim3(7, 12, BATCH), dim3(32, 8)>>>(x);

    // K1a: q,k rows = BN(W_qkv[0:768] @ x)  3-term -> fp32
    gemm_f16<0, true, false, 3><<<dim3(2, 768 / 128, BATCH), 256>>>(
        qwh, qwl, xth, xtl,
        qkvf, nullptr, nullptr,
        DIM / 16, DIM, DIM,
        0L, 0L, 1,
        (long)NPIX * DIM, (long)768 * NPIX, 0L,
        NPIX, 0, NPIX, 0,
        qkv_g, qkv_b, qkv_m, qkv_v);

    // K1b: V rows = BN(W_qkv[768:2304] @ x)  2-term -> fp16 h/l planes
    gemm_f16<1, true, false, 2><<<dim3(2, DH / 128, BATCH), 256>>>(
        qwh + (size_t)768 * DIM, qwl + (size_t)768 * DIM, xth, nullptr,
        nullptr, vh, vl,
        DIM / 16, DIM, DIM,
        0L, 0L, 1,
        (long)NPIX * DIM, 0L, (long)DH * NPAD,
        0, NPAD, NPIX, 0,
        qkv_g + 768, qkv_b + 768, qkv_m + 768, qkv_v + 768);

    // K2: q <- BN(dwconv3x3(q))  (4 channels per block)
    dwconv_bn<<<dim3(NH_KD / 4, BATCH), 224>>>(dw_w, dw_g, dw_b, dw_m, dw_v);

    // K3: bias gather
    {
        int total = NHEADS * NPIX * NPIX;
        bias_gather<<<(total + 255) / 256, 256>>>(ab, bidx);
    }
    // K4: softmax -> P hi plane
    attn_softmax<<<dim3(NHEADS, BATCH), 256>>>();

    // K5: attT hi = relu(V @ P^T)^T  2-term  (per b,h)
    gemm_f16<2, false, true, 2><<<dim3(2, 1, BATCH * NHEADS), 256>>>(
        vh, vl, ph, nullptr,
        nullptr, ath, nullptr,
        NPAD / 16, NPAD, NPAD,
        (long)DH * NPAD, (long)128 * NPAD, NHEADS,
        (long)NPIX * NPAD, 0L, (long)NPIX * DH,
        0, DH, NPIX, 0,
        nullptr, nullptr, nullptr, nullptr);

    // K6: out = BN(W_proj @ att)  2-term  (B = attT hi, k-contig)
    gemm_f16<0, true, false, 2><<<dim3(2, DIM / 128, BATCH), 256>>>(
        pwh, pwl, ath, nullptr,
        out, nullptr, nullptr,
        DH / 16, DH, DH,
        0L, 0L, 1,
        (long)NPIX * DH, (long)DIM * NPIX, 0L,
        NPIX, 0, NPIX, DIM,
        proj_g, proj_b, proj_m, proj_v);
}

// round 12
// speedup vs baseline: 1.5206x; 1.0212x over previous
#include <cuda_runtime.h>
#include <cuda_fp16.h>
#include <math.h>
#include <stdint.h>

// ---------------- constants ----------------
#define BATCH   128
#define DIM     384
#define RES     14
#define NPIX    196
#define KEY_DIM 32
#define NHEADS  12
#define NH_KD   384
#define DH      1536
#define HQKV    2304
#define BN_EPS  1e-5f
#define NPAD    208     // NPIX padded to mult of 16

// ---------------- scratch ----------------
__device__ float g_qkv [ (size_t)BATCH * 768 * NPIX ];            // q+k fp32 only
__device__ float g_qdw [ (size_t)BATCH * NH_KD * NPIX ];
__device__ float g_bias[ (size_t)NHEADS * NPIX * NPIX ];

__device__ __half g_qw_h[ HQKV * DIM ],  g_qw_l[ HQKV * DIM ];
__device__ __half g_pw_h[ DIM * DH ],    g_pw_l[ DIM * DH ];
__device__ __half g_xT_h[ (size_t)BATCH * NPIX * DIM ],  g_xT_l[ (size_t)BATCH * NPIX * DIM ];
__device__ __half g_v_h [ (size_t)BATCH * DH * NPAD ],   g_v_l [ (size_t)BATCH * DH * NPAD ];
__device__ __half g_p_h [ (size_t)BATCH * NHEADS * NPIX * NPAD ];   // hi plane only
__device__ __half g_at_h[ (size_t)BATCH * NPIX * DH ];              // hi plane only

// ---------------- helpers ----------------
__device__ __forceinline__ uint32_t smem_u32(const void* p) {
    uint32_t a;
    asm("{ .reg .u64 t; cvta.to.shared.u64 t, %1; cvt.u32.u64 %0, t; }"
        : "=r"(a) : "l"(p));
    return a;
}
#define LDSM4(r, addr) \
    asm volatile("ldmatrix.sync.aligned.m8n8.x4.shared.b16 {%0,%1,%2,%3}, [%4];" \
        : "=r"((r)[0]), "=r"((r)[1]), "=r"((r)[2]), "=r"((r)[3]) : "r"(addr))
#define MMA_F16(d, a, bb) \
    asm volatile("mma.sync.aligned.m16n8k16.row.col.f32.f16.f16.f32 " \
        "{%0,%1,%2,%3}, {%4,%5,%6,%7}, {%8,%9}, {%0,%1,%2,%3};" \
        : "+f"((d)[0]), "+f"((d)[1]), "+f"((d)[2]), "+f"((d)[3]) \
        : "r"((a)[0]), "r"((a)[1]), "r"((a)[2]), "r"((a)[3]), \
          "r"((bb)[0]), "r"((bb)[1]))
#define CP_ASYNC16(dst, src, sz) \
    asm volatile("cp.async.cg.shared.global [%0], [%1], 16, %2;" \
                 :: "r"(dst), "l"(src), "r"(sz))
#define CP_COMMIT() asm volatile("cp.async.commit_group;" ::: "memory")
#define CP_WAIT(n)  asm volatile("cp.async.wait_group %0;" :: "n"(n) : "memory")

__device__ __forceinline__ void split_f16(float v, __half& h, __half& l) {
    h = __float2half_rn(v);
    l = __float2half_rn(v - __half2float(h));
}

// ================= multistage fp16-plane GEMM =================
// C[m,n] = act(BN_m( sum_k A[m,k]*B[n,k] ))  -- k-contig fp16 planes.
// TERMS=3: hh + loA*hiB + hiA*loB (2 stages) ; TERMS=2: hh + loA*hiB (3 stages).
// A plane: 128 rows x KPA=40 halves (hi cols 0-15, lo cols 16-31).
// B plane: TERMS3 same combined layout; TERMS2 hi-only KPB=24.
// One __syncthreads per mainloop iteration (stage issued post-sync).
// OUTMODE: 0 = fp32 out; 1 = fp32 if m0<mSplit else fp16 h/l planes (pad zeroed);
//          2 = transposed fp16 HI plane only  C^T[n][zi*128+m].
template<int OUTMODE, bool HASBN, bool RELU, int TERMS>
__global__ void __launch_bounds__(256, 2)
gemm_f16(const __half* __restrict__ Ah, const __half* __restrict__ Al,
         const __half* __restrict__ Bh, const __half* __restrict__ Bl,
         float* __restrict__ Cf, __half* __restrict__ Ch, __half* __restrict__ Cl,
         int nchunks, int lda, int ldb,
         long aOuter, long aInner, int innerCnt,
         long bStride, long cfStride, long cpStride,
         int ldcF, int ldcP, int nrowsB, int mSplit,
         const float* __restrict__ bng, const float* __restrict__ bnb,
         const float* __restrict__ bnm, const float* __restrict__ bnv)
{
    constexpr int KPA = 40;                           // A combined hi|lo row
    constexpr int KPB = (TERMS == 3) ? 40 : 24;
    constexpr uint32_t A_BYTES = 128 * KPA * 2;       // 10240
    constexpr uint32_t B_BYTES = 128 * KPB * 2;       // 10240 / 6144
    constexpr uint32_t STAGE   = A_BYTES + B_BYTES;   // 20480 / 16384
    constexpr int NSTAGE = (TERMS == 3) ? 2 : 3;      // 40960 / 49152 bytes
    __shared__ __align__(16) __half smbuf[(NSTAGE * STAGE) / 2];

    const int tid  = threadIdx.x;
    const int wid  = tid >> 5;
    const int lane = tid & 31;
    const int warp_m = wid & 3;
    const int warp_n = wid >> 2;
    const int n0 = blockIdx.x * 128;
    const int m0 = blockIdx.y * 128;
    const int z  = blockIdx.z;
    const int zb = z / innerCnt, zi = z - zb * innerCnt;

    const __half* Agh = Ah + (size_t)zb * aOuter + (size_t)zi * aInner + (size_t)m0 * lda;
    const __half* Agl = Al + (size_t)zb * aOuter + (size_t)zi * aInner + (size_t)m0 * lda;
    const __half* Bgh = Bh + (size_t)z * bStride;
    const __half* Bgl = (TERMS == 3) ? (Bl + (size_t)z * bStride) : nullptr;

    const uint32_t smb = smem_u32(smbuf);

    const bool full = (n0 + warp_n * 64 + 64) <= nrowsB;
    int jlim = nrowsB - (n0 + warp_n * 64);
    jlim = jlim <= 0 ? 0 : ((jlim + 7) >> 3);
    if (jlim > 8) jlim = 8;

    auto stage = [&](int ch, int s) {
        const int k0 = ch * 16;
        const uint32_t sb = smb + (uint32_t)s * STAGE;
        // A: 512 x 16B pieces (hi + lo)
#pragma unroll
        for (int i = 0; i < 2; i++) {
            int idx = i * 256 + tid;
            int row = idx >> 2;
            int p   = idx & 3;                 // 0,1 = hi halves; 2,3 = lo halves
            const __half* src = (p < 2 ? Agh : Agl) + (size_t)row * lda + k0 + (p & 1) * 8;
            uint32_t dst = sb + (uint32_t)(row * KPA + p * 8) * 2;
            CP_ASYNC16(dst, src, 16u);
        }
        // B
        if (TERMS == 3) {
#pragma unroll
            for (int i = 0; i < 2; i++) {
                int idx = i * 256 + tid;
                int row = idx >> 2;
                int p   = idx & 3;
                int rowg = n0 + row;
                unsigned sz = 16u;
                if (rowg >= nrowsB) { rowg = 0; sz = 0u; }
                const __half* src = (p < 2 ? Bgh : Bgl) + (size_t)rowg * ldb + k0 + (p & 1) * 8;
                uint32_t dst = sb + A_BYTES + (uint32_t)(row * KPB + p * 8) * 2;
                CP_ASYNC16(dst, src, sz);
            }
        } else {
            int row = tid >> 1;
            int h   = tid & 1;
            int rowg = n0 + row;
            unsigned sz = 16u;
            if (rowg >= nrowsB) { rowg = 0; sz = 0u; }
            const __half* src = Bgh + (size_t)rowg * ldb + k0 + h * 8;
            uint32_t dst = sb + A_BYTES + (uint32_t)(row * KPB + h * 8) * 2;
            CP_ASYNC16(dst, src, sz);
        }
        CP_COMMIT();
    };

    float acc[2][8][4];
#pragma unroll
    for (int t = 0; t < 2; t++)
#pragma unroll
        for (int j = 0; j < 8; j++)
#pragma unroll
            for (int c = 0; c < 4; c++) acc[t][j][c] = 0.f;

    // prologue
    stage(0, 0);
    if (NSTAGE == 3) {
        if (nchunks > 1) stage(1, 1); else CP_COMMIT();
    }

    for (int ch = 0; ch < nchunks; ch++) {
        if (NSTAGE == 3) CP_WAIT(1); else CP_WAIT(0);
        __syncthreads();

        {   // stage next (post-sync: safe to overwrite chunk ch-1's buffer)
            int nx = ch + NSTAGE - 1;
            if (nx < nchunks) stage(nx, nx % NSTAGE);
            else CP_COMMIT();
        }

        const uint32_t base  = smb + (uint32_t)(ch % NSTAGE) * STAGE;
        const uint32_t aBase = base;
        const uint32_t bBase = base + A_BYTES;

        uint32_t a_hi[2][4], a_lo[2][4];
#pragma unroll
        for (int t = 0; t < 2; t++) {
            int row = warp_m * 32 + t * 16 + (lane & 15);
            int col = (lane >> 4) << 3;
            uint32_t off = (uint32_t)(row * KPA + col) * 2;
            LDSM4(a_hi[t], aBase + off);
            LDSM4(a_lo[t], aBase + off + 32);   // lo cols 16..31
        }
        int nrow = warp_n * 64 + (lane & 7) + ((lane >> 4) << 3);
        int bcol = ((lane >> 3) & 1) << 3;
        uint32_t boff = (uint32_t)(nrow * KPB + bcol) * 2;

        if (full) {
            uint32_t b[8][2];
#pragma unroll
            for (int j = 0; j < 4; j++) {
                uint32_t r[4];
                LDSM4(r, bBase + boff + (uint32_t)(j * 16 * KPB) * 2);
                b[2 * j][0] = r[0]; b[2 * j][1] = r[1];
                b[2 * j + 1][0] = r[2]; b[2 * j + 1][1] = r[3];
            }
#pragma unroll
            for (int t = 0; t < 2; t++)
#pragma unroll
                for (int j = 0; j < 8; j++) MMA_F16(acc[t][j], a_hi[t], b[j]);
#pragma unroll
            for (int t = 0; t < 2; t++)
#pragma unroll
                for (int j = 0; j < 8; j++) MMA_F16(acc[t][j], a_lo[t], b[j]);
            if (TERMS == 3) {
#pragma unroll
                for (int j = 0; j < 4; j++) {
                    uint32_t r[4];
                    LDSM4(r, bBase + boff + 32 + (uint32_t)(j * 16 * KPB) * 2);  // B-lo cols
                    b[2 * j][0] = r[0]; b[2 * j][1] = r[1];
                    b[2 * j + 1][0] = r[2]; b[2 * j + 1][1] = r[3];
                }
#pragma unroll
                for (int t = 0; t < 2; t++)
#pragma unroll
                    for (int j = 0; j < 8; j++) MMA_F16(acc[t][j], a_hi[t], b[j]);
            }
        } else if (jlim > 0) {
            uint32_t b2[2][2];
            {
                uint32_t r[4];
                LDSM4(r, bBase + boff);
                b2[0][0] = r[0]; b2[0][1] = r[1];
                b2[1][0] = r[2]; b2[1][1] = r[3];
            }
#pragma unroll
            for (int t = 0; t < 2; t++)
#pragma unroll
                for (int j = 0; j < 2; j++)
                    if (j < jlim) MMA_F16(acc[t][j], a_hi[t], b2[j]);
#pragma unroll
            for (int t = 0; t < 2; t++)
#pragma unroll
                for (int j = 0; j < 2; j++)
                    if (j < jlim) MMA_F16(acc[t][j], a_lo[t], b2[j]);
            if (TERMS == 3) {
                uint32_t r[4];
                LDSM4(r, bBase + boff + 32);
                b2[0][0] = r[0]; b2[0][1] = r[1];
                b2[1][0] = r[2]; b2[1][1] = r[3];
#pragma unroll
                for (int t = 0; t < 2; t++)
#pragma unroll
                    for (int j = 0; j < 2; j++)
                        if (j < jlim) MMA_F16(acc[t][j], a_hi[t], b2[j]);
            }
        }
    }

    // ---------------- epilogues ----------------
    if (OUTMODE == 0 || OUTMODE == 1) {
        const bool isF32 = (OUTMODE == 0) || (m0 < mSplit);
#pragma unroll
        for (int t = 0; t < 2; t++) {
            int r0 = m0 + warp_m * 32 + t * 16 + (lane >> 2);
            int r1 = r0 + 8;
            float s0 = 1.f, h0 = 0.f, s1 = 1.f, h1 = 0.f;
            if (HASBN) {
                float a = bng[r0] * rsqrtf(bnv[r0] + BN_EPS);
                s0 = a; h0 = bnb[r0] - bnm[r0] * a;
                float c = bng[r1] * rsqrtf(bnv[r1] + BN_EPS);
                s1 = c; h1 = bnb[r1] - bnm[r1] * c;
            }
#pragma unroll
            for (int j = 0; j < 8; j++) {
                int nn = n0 + warp_n * 64 + j * 8 + 2 * (lane & 3);
                float v0 = acc[t][j][0] * s0 + h0;
                float v1 = acc[t][j][1] * s0 + h0;
                float v2 = acc[t][j][2] * s1 + h1;
                float v3 = acc[t][j][3] * s1 + h1;
                if (RELU) {
                    v0 = fmaxf(v0, 0.f); v1 = fmaxf(v1, 0.f);
                    v2 = fmaxf(v2, 0.f); v3 = fmaxf(v3, 0.f);
                }
                if (isF32) {
                    if (nn < NPIX) {
                        *(float2*)(Cf + (size_t)z * cfStride + (size_t)r0 * ldcF + nn) = make_float2(v0, v1);
                        *(float2*)(Cf + (size_t)z * cfStride + (size_t)r1 * ldcF + nn) = make_float2(v2, v3);
                    }
                } else {
                    if (nn < NPAD) {
                        if (nn >= NPIX) { v0 = v1 = v2 = v3 = 0.f; }
                        __half ha, la, hb, lb;
                        size_t p0 = (size_t)z * cpStride + (size_t)(r0 - mSplit) * ldcP + nn;
                        size_t p1 = (size_t)z * cpStride + (size_t)(r1 - mSplit) * ldcP + nn;
                        split_f16(v0, ha, la); split_f16(v1, hb, lb);
                        *(__half2*)(Ch + p0) = __half2(ha, hb);
                        *(__half2*)(Cl + p0) = __half2(la, lb);
                        split_f16(v2, ha, la); split_f16(v3, hb, lb);
                        *(__half2*)(Ch + p1) = __half2(ha, hb);
                        *(__half2*)(Cl + p1) = __half2(la, lb);
                    }
                }
            }
        }
    } else {
        __half* ep = smbuf;   // [128 i][136 d]
        __syncthreads();
#pragma unroll
        for (int t = 0; t < 2; t++) {
            int d0 = warp_m * 32 + t * 16 + (lane >> 2);
            int d1 = d0 + 8;
#pragma unroll
            for (int j = 0; j < 8; j++) {
                int il = warp_n * 64 + j * 8 + 2 * (lane & 3);
                float v0 = acc[t][j][0], v1 = acc[t][j][1];
                float v2 = acc[t][j][2], v3 = acc[t][j][3];
                if (RELU) {
                    v0 = fmaxf(v0, 0.f); v1 = fmaxf(v1, 0.f);
                    v2 = fmaxf(v2, 0.f); v3 = fmaxf(v3, 0.f);
                }
                ep[il * 136 + d0]       = __float2half_rn(v0);
                ep[(il + 1) * 136 + d0] = __float2half_rn(v1);
                ep[il * 136 + d1]       = __float2half_rn(v2);
                ep[(il + 1) * 136 + d1] = __float2half_rn(v3);
            }
        }
        __syncthreads();
        __half* dst = Ch + (size_t)zb * cpStride + (size_t)zi * 128;
        for (int c2 = tid; c2 < 2048; c2 += 256) {
            int row = c2 >> 4, off = (c2 & 15) * 8;
            int i = n0 + row;
            if (i < NPIX) {
                uint4 val = *(uint4*)(ep + row * 136 + off);
                *(uint4*)(dst + (size_t)i * ldcP + off) = val;
            }
        }
    }
}

// ---------------- pre-convert kernels ----------------
__global__ void convert_weights(const float* __restrict__ qw, const float* __restrict__ pw)
{
    int i = blockIdx.x * 256 + threadIdx.x;
    if (i < HQKV * DIM) split_f16(qw[i], g_qw_h[i], g_qw_l[i]);
    if (i < DIM * DH)   split_f16(pw[i], g_pw_h[i], g_pw_l[i]);
}

__global__ void transpose_x(const float* __restrict__ x)
{
    __shared__ float t[32][33];
    int p0 = blockIdx.x * 32, c0 = blockIdx.y * 32, b = blockIdx.z;
    for (int r = threadIdx.y; r < 32; r += 8) {
        int p = p0 + threadIdx.x;
        t[r][threadIdx.x] = (p < NPIX) ? x[((size_t)b * DIM + c0 + r) * NPIX + p] : 0.f;
    }
    __syncthreads();
    for (int r = threadIdx.y; r < 32; r += 8) {
        int p = p0 + r, c = c0 + threadIdx.x;
        if (p < NPIX) {
            size_t o = ((size_t)b * NPIX + p) * DIM + c;
            split_f16(t[threadIdx.x][r], g_xT_h[o], g_xT_l[o]);
        }
    }
}

// ---------------- dwconv + BN: 4 channels per block --------------------------
__global__ void __launch_bounds__(224, 8)
dwconv_bn(const float* __restrict__ w,
          const float* __restrict__ bng,
          const float* __restrict__ bnb,
          const float* __restrict__ bnm,
          const float* __restrict__ bnv)
{
    const int c0 = blockIdx.x * 4;
    const int b  = blockIdx.y;
    __shared__ float t[4][200];
    __shared__ float wgt[4][9];
    __shared__ float sBN[4][2];

    const float* src = g_qkv + (size_t)b * 768 * NPIX + (size_t)c0 * NPIX;
    int tid = threadIdx.x;
    for (int e = tid; e < 4 * NPIX; e += 224) {
        int ch = e / NPIX, p = e - ch * NPIX;
        t[ch][p] = src[ch * NPIX + p];
    }
    if (tid < 36) wgt[tid / 9][tid % 9] = w[c0 * 9 + tid];
    if (tid < 4) {
        int c = c0 + tid;
        float s = bng[c] * rsqrtf(bnv[c] + BN_EPS);
        sBN[tid][0] = s;
        sBN[tid][1] = bnb[c] - bnm[c] * s;
    }
    __syncthreads();

    if (tid < NPIX) {
        int y = tid / RES, x = tid - y * RES;
#pragma unroll
        for (int ch = 0; ch < 4; ch++) {
            float acc = 0.f;
#pragma unroll
            for (int ky = 0; ky < 3; ky++) {
                int yy = y + ky - 1;
                if (yy < 0 || yy >= RES) continue;
#pragma unroll
                for (int kx = 0; kx < 3; kx++) {
                    int xx = x + kx - 1;
                    if (xx < 0 || xx >= RES) continue;
                    acc += t[ch][yy * RES + xx] * wgt[ch][ky * 3 + kx];
                }
            }
            g_qdw[((size_t)b * NH_KD + c0 + ch) * NPIX + tid] = acc * sBN[ch][0] + sBN[ch][1];
        }
    }
}

// ---------------- bias gather ----------------
__global__ void bias_gather(const float* __restrict__ ab, const int* __restrict__ idxs)
{
    int idx = blockIdx.x * 256 + threadIdx.x;
    if (idx >= NHEADS * NPIX * NPIX) return;
    int h  = idx / (NPIX * NPIX);
    int ij = idx % (NPIX * NPIX);
    g_bias[idx] = ab[h * NPIX + idxs[ij]];
}

// ---------------- softmax: 4 rows/warp (low regs, high occ) -----------------
__global__ void attn_softmax(void)
{
    const int h = blockIdx.x;
    const int b = blockIdx.y;
    __shared__ float k_s[32 * 224];

    const float* qg = g_qdw + (size_t)b * NH_KD * NPIX + (size_t)h * KEY_DIM * NPIX;
    const float* kg = g_qkv + (size_t)b * 768 * NPIX + (size_t)(NH_KD + h * KEY_DIM) * NPIX;

    for (int idx = threadIdx.x; idx < 32 * 224; idx += 256) {
        int d = idx / 224, j = idx % 224;
        k_s[idx] = (j < NPIX) ? kg[d * NPIX + j] : 0.f;
    }
    __syncthreads();

    const int w    = threadIdx.x >> 5;
    const int lane = threadIdx.x & 31;
    const float* bh = g_bias + (size_t)h * NPIX * NPIX;
    const size_t zoff = ((size_t)b * NHEADS + h) * NPIX * NPAD;
    const float scale = 0.17677669529663687f;

    for (int i0 = w * 4; i0 < NPIX; i0 += 32) {
        float q_reg[4];
#pragma unroll
        for (int r = 0; r < 4; r++) {
            int i = i0 + r;
            q_reg[r] = (i < NPIX) ? qg[(size_t)lane * NPIX + i] : 0.f;
        }

        float s[4][7];
#pragma unroll
        for (int r = 0; r < 4; r++)
#pragma unroll
            for (int m = 0; m < 7; m++) s[r][m] = 0.f;

        for (int d = 0; d < 32; d++) {
            float qv[4];
#pragma unroll
            for (int r = 0; r < 4; r++)
                qv[r] = __shfl_sync(0xffffffffu, q_reg[r], d);
#pragma unroll
            for (int m = 0; m < 7; m++) {
                float kv = k_s[d * 224 + lane + m * 32];
#pragma unroll
                for (int r = 0; r < 4; r++) s[r][m] += qv[r] * kv;
            }
        }

#pragma unroll
        for (int r = 0; r < 4; r++) {
            int i = i0 + r;
            if (i >= NPIX) break;
            float sv[7];
            float mx = -1e30f;
#pragma unroll
            for (int m = 0; m < 7; m++) {
                int j = lane + m * 32;
                float val = (j < NPIX) ? s[r][m] * scale + bh[(size_t)i * NPIX + j]
                                       : -1e30f;
                sv[m] = val;
                mx = fmaxf(mx, val);
            }
#pragma unroll
            for (int off = 16; off; off >>= 1)
                mx = fmaxf(mx, __shfl_xor_sync(0xffffffffu, mx, off));
            float sum = 0.f;
#pragma unroll
            for (int m = 0; m < 7; m++) {
                sv[m] = __expf(sv[m] - mx);
                sum += sv[m];
            }
#pragma unroll
            for (int off = 16; off; off >>= 1)
                sum += __shfl_xor_sync(0xffffffffu, sum, off);
            float inv = 1.f / sum;
#pragma unroll
            for (int m = 0; m < 7; m++) {
                int j = lane + m * 32;
                if (j < NPIX) {
                    g_p_h[zoff + (size_t)i * NPAD + j] = __float2half_rn(sv[m] * inv);
                } else if (j < NPAD) {
                    g_p_h[zoff + (size_t)i * NPAD + j] = __float2half_rn(0.f);
                }
            }
        }
    }
}

// ---------------- launch ----------------------------------------------------
extern "C" void kernel_launch(void* const* d_in, const int* in_sizes, int n_in,
                              void* d_out, int out_size)
{
    const float* x      = (const float*)d_in[0];
    const float* qkv_w  = (const float*)d_in[1];
    const float* qkv_g  = (const float*)d_in[2];
    const float* qkv_b  = (const float*)d_in[3];
    const float* qkv_m  = (const float*)d_in[4];
    const float* qkv_v  = (const float*)d_in[5];
    const float* dw_w   = (const float*)d_in[6];
    const float* dw_g   = (const float*)d_in[7];
    const float* dw_b   = (const float*)d_in[8];
    const float* dw_m   = (const float*)d_in[9];
    const float* dw_v   = (const float*)d_in[10];
    const float* proj_w = (const float*)d_in[11];
    const float* proj_g = (const float*)d_in[12];
    const float* proj_b = (const float*)d_in[13];
    const float* proj_m = (const float*)d_in[14];
    const float* proj_v = (const float*)d_in[15];
    const float* ab     = (const float*)d_in[16];
    const int*   bidx   = (const int*)d_in[17];
    float* out = (float*)d_out;

    float* qkvf;  cudaGetSymbolAddress((void**)&qkvf,  g_qkv);
    __half *qwh, *qwl, *pwh, *pwl, *xth, *xtl, *vh, *vl, *ph, *ath;
    cudaGetSymbolAddress((void**)&qwh, g_qw_h);  cudaGetSymbolAddress((void**)&qwl, g_qw_l);
    cudaGetSymbolAddress((void**)&pwh, g_pw_h);  cudaGetSymbolAddress((void**)&pwl, g_pw_l);
    cudaGetSymbolAddress((void**)&xth, g_xT_h);  cudaGetSymbolAddress((void**)&xtl, g_xT_l);
    cudaGetSymbolAddress((void**)&vh,  g_v_h);   cudaGetSymbolAddress((void**)&vl,  g_v_l);
    cudaGetSymbolAddress((void**)&ph,  g_p_h);
    cudaGetSymbolAddress((void**)&ath, g_at_h);

    // P0: convert weights + transpose/convert x
    convert_weights<<<(HQKV * DIM + 255) / 256, 256>>>(qkv_w, proj_w);
    transpose_x<<<dim3(7, 12, BATCH), dim3(32, 8)>>>(x);

    // K1a: q,k rows = BN(W_qkv[0:768] @ x)  3-term -> fp32
    gemm_f16<0, true, false, 3><<<dim3(2, 768 / 128, BATCH), 256>>>(
        qwh, qwl, xth, xtl,
        qkvf, nullptr, nullptr,
        DIM / 16, DIM, DIM,
        0L, 0L, 1,
        (long)NPIX * DIM, (long)768 * NPIX, 0L,
        NPIX, 0, NPIX, 0,
        qkv_g, qkv_b, qkv_m, qkv_v);

    // K1b: V rows = BN(W_qkv[768:2304] @ x)  2-term -> fp16 h/l planes
    gemm_f16<1, true, false, 2><<<dim3(2, DH / 128, BATCH), 256>>>(
        qwh + (size_t)768 * DIM, qwl + (size_t)768 * DIM, xth, nullptr,
        nullptr, vh, vl,
        DIM / 16, DIM, DIM,
        0L, 0L, 1,
        (long)NPIX * DIM, 0L, (long)DH * NPAD,
        0, NPAD, NPIX, 0,
        qkv_g + 768, qkv_b + 768, qkv_m + 768, qkv_v + 768);

    // K2: q <- BN(dwconv3x3(q))  (4 channels per block)
    dwconv_bn<<<dim3(NH_KD / 4, BATCH), 224>>>(dw_w, dw_g, dw_b, dw_m, dw_v);

    // K3: bias gather
    {
        int total = NHEADS * NPIX * NPIX;
        bias_gather<<<(total + 255) / 256, 256>>>(ab, bidx);
    }
    // K4: softmax -> P hi plane
    attn_softmax<<<dim3(NHEADS, BATCH), 256>>>();

    // K5: attT hi = relu(V @ P^T)^T  2-term  (per b,h)
    gemm_f16<2, false, true, 2><<<dim3(2, 1, BATCH * NHEADS), 256>>>(
        vh, vl, ph, nullptr,
        nullptr, ath, nullptr,
        NPAD / 16, NPAD, NPAD,
        (long)DH * NPAD, (long)128 * NPAD, NHEADS,
        (long)NPIX * NPAD, 0L, (long)NPIX * DH,
        0, DH, NPIX, 0,
        nullptr, nullptr, nullptr, nullptr);

    // K6: out = BN(W_proj @ att)  2-term  (B = attT hi, k-contig)
    gemm_f16<0, true, false, 2><<<dim3(2, DIM / 128, BATCH), 256>>>(
        pwh, pwl, ath, nullptr,
        out, nullptr, nullptr,
        DH / 16, DH, DH,
        0L, 0L, 1,
        (long)NPIX * DH, (long)DIM * NPIX, 0L,
        NPIX, 0, NPIX, DIM,
        proj_g, proj_b, proj_m, proj_v);
}

// round 13
// speedup vs baseline: 1.7304x; 1.1379x over previous
#include <cuda_runtime.h>
#include <cuda_fp16.h>
#include <math.h>
#include <stdint.h>

// ---------------- constants ----------------
#define BATCH   128
#define DIM     384
#define RES     14
#define NPIX    196
#define KEY_DIM 32
#define NHEADS  12
#define NH_KD   384
#define DH      1536
#define HQKV    2304
#define BN_EPS  1e-5f
#define NPAD    208     // NPIX padded to mult of 16

// ---------------- scratch ----------------
__device__ float g_qkv [ (size_t)BATCH * 768 * NPIX ];            // q+k fp32 only
__device__ float g_qdw [ (size_t)BATCH * NH_KD * NPIX ];
__device__ float g_bias[ (size_t)NHEADS * NPIX * NPIX ];

__device__ __half g_qw_h[ HQKV * DIM ],  g_qw_l[ HQKV * DIM ];
__device__ __half g_pw_h[ DIM * DH ],    g_pw_l[ DIM * DH ];
__device__ __half g_xT_h[ (size_t)BATCH * NPIX * DIM ],  g_xT_l[ (size_t)BATCH * NPIX * DIM ];
__device__ __half g_v_h [ (size_t)BATCH * DH * NPAD ],   g_v_l [ (size_t)BATCH * DH * NPAD ];
__device__ __half g_p_h [ (size_t)BATCH * NHEADS * NPIX * NPAD ];   // hi plane only
__device__ __half g_at_h[ (size_t)BATCH * NPIX * DH ];              // hi plane only

// ---------------- helpers ----------------
__device__ __forceinline__ uint32_t smem_u32(const void* p) {
    uint32_t a;
    asm("{ .reg .u64 t; cvta.to.shared.u64 t, %1; cvt.u32.u64 %0, t; }"
        : "=r"(a) : "l"(p));
    return a;
}
#define LDSM4(r, addr) \
    asm volatile("ldmatrix.sync.aligned.m8n8.x4.shared.b16 {%0,%1,%2,%3}, [%4];" \
        : "=r"((r)[0]), "=r"((r)[1]), "=r"((r)[2]), "=r"((r)[3]) : "r"(addr))
#define MMA_F16(d, a, bb) \
    asm volatile("mma.sync.aligned.m16n8k16.row.col.f32.f16.f16.f32 " \
        "{%0,%1,%2,%3}, {%4,%5,%6,%7}, {%8,%9}, {%0,%1,%2,%3};" \
        : "+f"((d)[0]), "+f"((d)[1]), "+f"((d)[2]), "+f"((d)[3]) \
        : "r"((a)[0]), "r"((a)[1]), "r"((a)[2]), "r"((a)[3]), \
          "r"((bb)[0]), "r"((bb)[1]))
#define CP_ASYNC16(dst, src, sz) \
    asm volatile("cp.async.cg.shared.global [%0], [%1], 16, %2;" \
                 :: "r"(dst), "l"(src), "r"(sz))
#define CP_COMMIT() asm volatile("cp.async.commit_group;" ::: "memory")
#define CP_WAIT(n)  asm volatile("cp.async.wait_group %0;" :: "n"(n) : "memory")

__device__ __forceinline__ void split_f16(float v, __half& h, __half& l) {
    h = __float2half_rn(v);
    l = __float2half_rn(v - __half2float(h));
}

// ================= multistage fp16-plane GEMM =================
// C[m,n] = act(BN_m( sum_k A[m,k]*B[n,k] ))  -- k-contig fp16 planes.
// TERMS=3: hh + loA*hiB + hiA*loB (2 stages)
// TERMS=2: hh + loA*hiB           (3 stages)
// TERMS=1: hh                     (4 stages, plain fp16)
// One __syncthreads per mainloop iteration (stage issued post-sync).
// OUTMODE: 0 = fp32 out; 1 = fp32 if m0<mSplit else fp16 h/l planes (pad zeroed);
//          2 = transposed fp16 HI plane only  C^T[n][zi*128+m].
template<int OUTMODE, bool HASBN, bool RELU, int TERMS>
__global__ void __launch_bounds__(256, 2)
gemm_f16(const __half* __restrict__ Ah, const __half* __restrict__ Al,
         const __half* __restrict__ Bh, const __half* __restrict__ Bl,
         float* __restrict__ Cf, __half* __restrict__ Ch, __half* __restrict__ Cl,
         int nchunks, int lda, int ldb,
         long aOuter, long aInner, int innerCnt,
         long bStride, long cfStride, long cpStride,
         int ldcF, int ldcP, int nrowsB, int mSplit,
         const float* __restrict__ bng, const float* __restrict__ bnb,
         const float* __restrict__ bnm, const float* __restrict__ bnv)
{
    constexpr int KPA = (TERMS >= 2) ? 40 : 24;       // A: hi|lo combined or hi only
    constexpr int KPB = (TERMS == 3) ? 40 : 24;
    constexpr uint32_t A_BYTES = 128 * KPA * 2;
    constexpr uint32_t B_BYTES = 128 * KPB * 2;
    constexpr uint32_t STAGE   = A_BYTES + B_BYTES;   // 20480 / 16384 / 12288
    constexpr int NSTAGE = (TERMS == 3) ? 2 : (TERMS == 2 ? 3 : 4);
    __shared__ __align__(16) __half smbuf[(NSTAGE * STAGE) / 2];

    const int tid  = threadIdx.x;
    const int wid  = tid >> 5;
    const int lane = tid & 31;
    const int warp_m = wid & 3;
    const int warp_n = wid >> 2;
    const int n0 = blockIdx.x * 128;
    const int m0 = blockIdx.y * 128;
    const int z  = blockIdx.z;
    const int zb = z / innerCnt, zi = z - zb * innerCnt;

    const __half* Agh = Ah + (size_t)zb * aOuter + (size_t)zi * aInner + (size_t)m0 * lda;
    const __half* Agl = (TERMS >= 2) ? (Al + (size_t)zb * aOuter + (size_t)zi * aInner + (size_t)m0 * lda) : nullptr;
    const __half* Bgh = Bh + (size_t)z * bStride;
    const __half* Bgl = (TERMS == 3) ? (Bl + (size_t)z * bStride) : nullptr;

    const uint32_t smb = smem_u32(smbuf);

    const bool full = (n0 + warp_n * 64 + 64) <= nrowsB;
    int jlim = nrowsB - (n0 + warp_n * 64);
    jlim = jlim <= 0 ? 0 : ((jlim + 7) >> 3);
    if (jlim > 8) jlim = 8;

    auto stage = [&](int ch, int s) {
        const int k0 = ch * 16;
        const uint32_t sb = smb + (uint32_t)s * STAGE;
        // A
        if (TERMS >= 2) {
#pragma unroll
            for (int i = 0; i < 2; i++) {
                int idx = i * 256 + tid;
                int row = idx >> 2;
                int p   = idx & 3;                 // 0,1 = hi halves; 2,3 = lo halves
                const __half* src = (p < 2 ? Agh : Agl) + (size_t)row * lda + k0 + (p & 1) * 8;
                uint32_t dst = sb + (uint32_t)(row * KPA + p * 8) * 2;
                CP_ASYNC16(dst, src, 16u);
            }
        } else {
            int row = tid >> 1;
            int h   = tid & 1;
            const __half* src = Agh + (size_t)row * lda + k0 + h * 8;
            uint32_t dst = sb + (uint32_t)(row * KPA + h * 8) * 2;
            CP_ASYNC16(dst, src, 16u);
        }
        // B
        if (TERMS == 3) {
#pragma unroll
            for (int i = 0; i < 2; i++) {
                int idx = i * 256 + tid;
                int row = idx >> 2;
                int p   = idx & 3;
                int rowg = n0 + row;
                unsigned sz = 16u;
                if (rowg >= nrowsB) { rowg = 0; sz = 0u; }
                const __half* src = (p < 2 ? Bgh : Bgl) + (size_t)rowg * ldb + k0 + (p & 1) * 8;
                uint32_t dst = sb + A_BYTES + (uint32_t)(row * KPB + p * 8) * 2;
                CP_ASYNC16(dst, src, sz);
            }
        } else {
            int row = tid >> 1;
            int h   = tid & 1;
            int rowg = n0 + row;
            unsigned sz = 16u;
            if (rowg >= nrowsB) { rowg = 0; sz = 0u; }
            const __half* src = Bgh + (size_t)rowg * ldb + k0 + h * 8;
            uint32_t dst = sb + A_BYTES + (uint32_t)(row * KPB + h * 8) * 2;
            CP_ASYNC16(dst, src, sz);
        }
        CP_COMMIT();
    };

    float acc[2][8][4];
#pragma unroll
    for (int t = 0; t < 2; t++)
#pragma unroll
        for (int j = 0; j < 8; j++)
#pragma unroll
            for (int c = 0; c < 4; c++) acc[t][j][c] = 0.f;

    // prologue: stage first NSTAGE-1 chunks
    stage(0, 0);
#pragma unroll
    for (int s = 1; s < NSTAGE - 1; s++) {
        if (s < nchunks) stage(s, s);
        else CP_COMMIT();
    }

    for (int ch = 0; ch < nchunks; ch++) {
        CP_WAIT(NSTAGE - 2);
        __syncthreads();

        {   // stage next (post-sync: safe to overwrite oldest buffer)
            int nx = ch + NSTAGE - 1;
            if (nx < nchunks) stage(nx, nx % NSTAGE);
            else CP_COMMIT();
        }

        const uint32_t base  = smb + (uint32_t)(ch % NSTAGE) * STAGE;
        const uint32_t aBase = base;
        const uint32_t bBase = base + A_BYTES;

        uint32_t a_hi[2][4], a_lo[2][4];
#pragma unroll
        for (int t = 0; t < 2; t++) {
            int row = warp_m * 32 + t * 16 + (lane & 15);
            int col = (lane >> 4) << 3;
            uint32_t off = (uint32_t)(row * KPA + col) * 2;
            LDSM4(a_hi[t], aBase + off);
            if (TERMS >= 2) LDSM4(a_lo[t], aBase + off + 32);   // lo cols 16..31
        }
        int nrow = warp_n * 64 + (lane & 7) + ((lane >> 4) << 3);
        int bcol = ((lane >> 3) & 1) << 3;
        uint32_t boff = (uint32_t)(nrow * KPB + bcol) * 2;

        if (full) {
            uint32_t b[8][2];
#pragma unroll
            for (int j = 0; j < 4; j++) {
                uint32_t r[4];
                LDSM4(r, bBase + boff + (uint32_t)(j * 16 * KPB) * 2);
                b[2 * j][0] = r[0]; b[2 * j][1] = r[1];
                b[2 * j + 1][0] = r[2]; b[2 * j + 1][1] = r[3];
            }
#pragma unroll
            for (int t = 0; t < 2; t++)
#pragma unroll
                for (int j = 0; j < 8; j++) MMA_F16(acc[t][j], a_hi[t], b[j]);
            if (TERMS >= 2) {
#pragma unroll
                for (int t = 0; t < 2; t++)
#pragma unroll
                    for (int j = 0; j < 8; j++) MMA_F16(acc[t][j], a_lo[t], b[j]);
            }
            if (TERMS == 3) {
#pragma unroll
                for (int j = 0; j < 4; j++) {
                    uint32_t r[4];
                    LDSM4(r, bBase + boff + 32 + (uint32_t)(j * 16 * KPB) * 2);  // B-lo cols
                    b[2 * j][0] = r[0]; b[2 * j][1] = r[1];
                    b[2 * j + 1][0] = r[2]; b[2 * j + 1][1] = r[3];
                }
#pragma unroll
                for (int t = 0; t < 2; t++)
#pragma unroll
                    for (int j = 0; j < 8; j++) MMA_F16(acc[t][j], a_hi[t], b[j]);
            }
        } else if (jlim > 0) {
            uint32_t b2[2][2];
            {
                uint32_t r[4];
                LDSM4(r, bBase + boff);
                b2[0][0] = r[0]; b2[0][1] = r[1];
                b2[1][0] = r[2]; b2[1][1] = r[3];
            }
#pragma unroll
            for (int t = 0; t < 2; t++)
#pragma unroll
                for (int j = 0; j < 2; j++)
                    if (j < jlim) MMA_F16(acc[t][j], a_hi[t], b2[j]);
            if (TERMS >= 2) {
#pragma unroll
                for (int t = 0; t < 2; t++)
#pragma unroll
                    for (int j = 0; j < 2; j++)
                        if (j < jlim) MMA_F16(acc[t][j], a_lo[t], b2[j]);
            }
            if (TERMS == 3) {
                uint32_t r[4];
                LDSM4(r, bBase + boff + 32);
                b2[0][0] = r[0]; b2[0][1] = r[1];
                b2[1][0] = r[2]; b2[1][1] = r[3];
#pragma unroll
                for (int t = 0; t < 2; t++)
#pragma unroll
                    for (int j = 0; j < 2; j++)
                        if (j < jlim) MMA_F16(acc[t][j], a_hi[t], b2[j]);
            }
        }
    }

    // ---------------- epilogues ----------------
    if (OUTMODE == 0 || OUTMODE == 1) {
        const bool isF32 = (OUTMODE == 0) || (m0 < mSplit);
#pragma unroll
        for (int t = 0; t < 2; t++) {
            int r0 = m0 + warp_m * 32 + t * 16 + (lane >> 2);
            int r1 = r0 + 8;
            float s0 = 1.f, h0 = 0.f, s1 = 1.f, h1 = 0.f;
            if (HASBN) {
                float a = bng[r0] * rsqrtf(bnv[r0] + BN_EPS);
                s0 = a; h0 = bnb[r0] - bnm[r0] * a;
                float c = bng[r1] * rsqrtf(bnv[r1] + BN_EPS);
                s1 = c; h1 = bnb[r1] - bnm[r1] * c;
            }
#pragma unroll
            for (int j = 0; j < 8; j++) {
                int nn = n0 + warp_n * 64 + j * 8 + 2 * (lane & 3);
                float v0 = acc[t][j][0] * s0 + h0;
                float v1 = acc[t][j][1] * s0 + h0;
                float v2 = acc[t][j][2] * s1 + h1;
                float v3 = acc[t][j][3] * s1 + h1;
                if (RELU) {
                    v0 = fmaxf(v0, 0.f); v1 = fmaxf(v1, 0.f);
                    v2 = fmaxf(v2, 0.f); v3 = fmaxf(v3, 0.f);
                }
                if (isF32) {
                    if (nn < NPIX) {
                        *(float2*)(Cf + (size_t)z * cfStride + (size_t)r0 * ldcF + nn) = make_float2(v0, v1);
                        *(float2*)(Cf + (size_t)z * cfStride + (size_t)r1 * ldcF + nn) = make_float2(v2, v3);
                    }
                } else {
                    if (nn < NPAD) {
                        if (nn >= NPIX) { v0 = v1 = v2 = v3 = 0.f; }
                        __half ha, la, hb, lb;
                        size_t p0 = (size_t)z * cpStride + (size_t)(r0 - mSplit) * ldcP + nn;
                        size_t p1 = (size_t)z * cpStride + (size_t)(r1 - mSplit) * ldcP + nn;
                        split_f16(v0, ha, la); split_f16(v1, hb, lb);
                        *(__half2*)(Ch + p0) = __half2(ha, hb);
                        *(__half2*)(Cl + p0) = __half2(la, lb);
                        split_f16(v2, ha, la); split_f16(v3, hb, lb);
                        *(__half2*)(Ch + p1) = __half2(ha, hb);
                        *(__half2*)(Cl + p1) = __half2(la, lb);
                    }
                }
            }
        }
    } else {
        __half* ep = smbuf;   // [128 i][136 d]
        __syncthreads();
#pragma unroll
        for (int t = 0; t < 2; t++) {
            int d0 = warp_m * 32 + t * 16 + (lane >> 2);
            int d1 = d0 + 8;
#pragma unroll
            for (int j = 0; j < 8; j++) {
                int il = warp_n * 64 + j * 8 + 2 * (lane & 3);
                float v0 = acc[t][j][0], v1 = acc[t][j][1];
                float v2 = acc[t][j][2], v3 = acc[t][j][3];
                if (RELU) {
                    v0 = fmaxf(v0, 0.f); v1 = fmaxf(v1, 0.f);
                    v2 = fmaxf(v2, 0.f); v3 = fmaxf(v3, 0.f);
                }
                ep[il * 136 + d0]       = __float2half_rn(v0);
                ep[(il + 1) * 136 + d0] = __float2half_rn(v1);
                ep[il * 136 + d1]       = __float2half_rn(v2);
                ep[(il + 1) * 136 + d1] = __float2half_rn(v3);
            }
        }
        __syncthreads();
        __half* dst = Ch + (size_t)zb * cpStride + (size_t)zi * 128;
        for (int c2 = tid; c2 < 2048; c2 += 256) {
            int row = c2 >> 4, off = (c2 & 15) * 8;
            int i = n0 + row;
            if (i < NPIX) {
                uint4 val = *(uint4*)(ep + row * 136 + off);
                *(uint4*)(dst + (size_t)i * ldcP + off) = val;
            }
        }
    }
}

// ---------------- pre-convert kernels ----------------
__global__ void convert_weights(const float* __restrict__ qw, const float* __restrict__ pw)
{
    int i = blockIdx.x * 256 + threadIdx.x;
    if (i < HQKV * DIM) split_f16(qw[i], g_qw_h[i], g_qw_l[i]);
    if (i < DIM * DH)   split_f16(pw[i], g_pw_h[i], g_pw_l[i]);
}

__global__ void transpose_x(const float* __restrict__ x)
{
    __shared__ float t[32][33];
    int p0 = blockIdx.x * 32, c0 = blockIdx.y * 32, b = blockIdx.z;
    for (int r = threadIdx.y; r < 32; r += 8) {
        int p = p0 + threadIdx.x;
        t[r][threadIdx.x] = (p < NPIX) ? x[((size_t)b * DIM + c0 + r) * NPIX + p] : 0.f;
    }
    __syncthreads();
    for (int r = threadIdx.y; r < 32; r += 8) {
        int p = p0 + r, c = c0 + threadIdx.x;
        if (p < NPIX) {
            size_t o = ((size_t)b * NPIX + p) * DIM + c;
            split_f16(t[threadIdx.x][r], g_xT_h[o], g_xT_l[o]);
        }
    }
}

// ---------------- dwconv + BN: 4 channels per block --------------------------
__global__ void __launch_bounds__(224, 8)
dwconv_bn(const float* __restrict__ w,
          const float* __restrict__ bng,
          const float* __restrict__ bnb,
          const float* __restrict__ bnm,
          const float* __restrict__ bnv)
{
    const int c0 = blockIdx.x * 4;
    const int b  = blockIdx.y;
    __shared__ float t[4][200];
    __shared__ float wgt[4][9];
    __shared__ float sBN[4][2];

    const float* src = g_qkv + (size_t)b * 768 * NPIX + (size_t)c0 * NPIX;
    int tid = threadIdx.x;
    for (int e = tid; e < 4 * NPIX; e += 224) {
        int ch = e / NPIX, p = e - ch * NPIX;
        t[ch][p] = src[ch * NPIX + p];
    }
    if (tid < 36) wgt[tid / 9][tid % 9] = w[c0 * 9 + tid];
    if (tid < 4) {
        int c = c0 + tid;
        float s = bng[c] * rsqrtf(bnv[c] + BN_EPS);
        sBN[tid][0] = s;
        sBN[tid][1] = bnb[c] - bnm[c] * s;
    }
    __syncthreads();

    if (tid < NPIX) {
        int y = tid / RES, x = tid - y * RES;
#pragma unroll
        for (int ch = 0; ch < 4; ch++) {
            float acc = 0.f;
#pragma unroll
            for (int ky = 0; ky < 3; ky++) {
                int yy = y + ky - 1;
                if (yy < 0 || yy >= RES) continue;
#pragma unroll
                for (int kx = 0; kx < 3; kx++) {
                    int xx = x + kx - 1;
                    if (xx < 0 || xx >= RES) continue;
                    acc += t[ch][yy * RES + xx] * wgt[ch][ky * 3 + kx];
                }
            }
            g_qdw[((size_t)b * NH_KD + c0 + ch) * NPIX + tid] = acc * sBN[ch][0] + sBN[ch][1];
        }
    }
}

// ---------------- bias gather ----------------
__global__ void bias_gather(const float* __restrict__ ab, const int* __restrict__ idxs)
{
    int idx = blockIdx.x * 256 + threadIdx.x;
    if (idx >= NHEADS * NPIX * NPIX) return;
    int h  = idx / (NPIX * NPIX);
    int ij = idx % (NPIX * NPIX);
    g_bias[idx] = ab[h * NPIX + idxs[ij]];
}

// ---------------- softmax: 4 rows/warp (low regs, high occ) -----------------
__global__ void attn_softmax(void)
{
    const int h = blockIdx.x;
    const int b = blockIdx.y;
    __shared__ float k_s[32 * 224];

    const float* qg = g_qdw + (size_t)b * NH_KD * NPIX + (size_t)h * KEY_DIM * NPIX;
    const float* kg = g_qkv + (size_t)b * 768 * NPIX + (size_t)(NH_KD + h * KEY_DIM) * NPIX;

    for (int idx = threadIdx.x; idx < 32 * 224; idx += 256) {
        int d = idx / 224, j = idx % 224;
        k_s[idx] = (j < NPIX) ? kg[d * NPIX + j] : 0.f;
    }
    __syncthreads();

    const int w    = threadIdx.x >> 5;
    const int lane = threadIdx.x & 31;
    const float* bh = g_bias + (size_t)h * NPIX * NPIX;
    const size_t zoff = ((size_t)b * NHEADS + h) * NPIX * NPAD;
    const float scale = 0.17677669529663687f;

    for (int i0 = w * 4; i0 < NPIX; i0 += 32) {
        float q_reg[4];
#pragma unroll
        for (int r = 0; r < 4; r++) {
            int i = i0 + r;
            q_reg[r] = (i < NPIX) ? qg[(size_t)lane * NPIX + i] : 0.f;
        }

        float s[4][7];
#pragma unroll
        for (int r = 0; r < 4; r++)
#pragma unroll
            for (int m = 0; m < 7; m++) s[r][m] = 0.f;

        for (int d = 0; d < 32; d++) {
            float qv[4];
#pragma unroll
            for (int r = 0; r < 4; r++)
                qv[r] = __shfl_sync(0xffffffffu, q_reg[r], d);
#pragma unroll
            for (int m = 0; m < 7; m++) {
                float kv = k_s[d * 224 + lane + m * 32];
#pragma unroll
                for (int r = 0; r < 4; r++) s[r][m] += qv[r] * kv;
            }
        }

#pragma unroll
        for (int r = 0; r < 4; r++) {
            int i = i0 + r;
            if (i >= NPIX) break;
            float sv[7];
            float mx = -1e30f;
#pragma unroll
            for (int m = 0; m < 7; m++) {
                int j = lane + m * 32;
                float val = (j < NPIX) ? s[r][m] * scale + bh[(size_t)i * NPIX + j]
                                       : -1e30f;
                sv[m] = val;
                mx = fmaxf(mx, val);
            }
#pragma unroll
            for (int off = 16; off; off >>= 1)
                mx = fmaxf(mx, __shfl_xor_sync(0xffffffffu, mx, off));
            float sum = 0.f;
#pragma unroll
            for (int m = 0; m < 7; m++) {
                sv[m] = __expf(sv[m] - mx);
                sum += sv[m];
            }
#pragma unroll
            for (int off = 16; off; off >>= 1)
                sum += __shfl_xor_sync(0xffffffffu, sum, off);
            float inv = 1.f / sum;
#pragma unroll
            for (int m = 0; m < 7; m++) {
                int j = lane + m * 32;
                if (j < NPIX) {
                    g_p_h[zoff + (size_t)i * NPAD + j] = __float2half_rn(sv[m] * inv);
                } else if (j < NPAD) {
                    g_p_h[zoff + (size_t)i * NPAD + j] = __float2half_rn(0.f);
                }
            }
        }
    }
}

// ---------------- launch ----------------------------------------------------
extern "C" void kernel_launch(void* const* d_in, const int* in_sizes, int n_in,
                              void* d_out, int out_size)
{
    const float* x      = (const float*)d_in[0];
    const float* qkv_w  = (const float*)d_in[1];
    const float* qkv_g  = (const float*)d_in[2];
    const float* qkv_b  = (const float*)d_in[3];
    const float* qkv_m  = (const float*)d_in[4];
    const float* qkv_v  = (const float*)d_in[5];
    const float* dw_w   = (const float*)d_in[6];
    const float* dw_g   = (const float*)d_in[7];
    const float* dw_b   = (const float*)d_in[8];
    const float* dw_m   = (const float*)d_in[9];
    const float* dw_v   = (const float*)d_in[10];
    const float* proj_w = (const float*)d_in[11];
    const float* proj_g = (const float*)d_in[12];
    const float* proj_b = (const float*)d_in[13];
    const float* proj_m = (const float*)d_in[14];
    const float* proj_v = (const float*)d_in[15];
    const float* ab     = (const float*)d_in[16];
    const int*   bidx   = (const int*)d_in[17];
    float* out = (float*)d_out;

    float* qkvf;  cudaGetSymbolAddress((void**)&qkvf,  g_qkv);
    __half *qwh, *qwl, *pwh, *pwl, *xth, *xtl, *vh, *vl, *ph, *ath;
    cudaGetSymbolAddress((void**)&qwh, g_qw_h);  cudaGetSymbolAddress((void**)&qwl, g_qw_l);
    cudaGetSymbolAddress((void**)&pwh, g_pw_h);  cudaGetSymbolAddress((void**)&pwl, g_pw_l);
    cudaGetSymbolAddress((void**)&xth, g_xT_h);  cudaGetSymbolAddress((void**)&xtl, g_xT_l);
    cudaGetSymbolAddress((void**)&vh,  g_v_h);   cudaGetSymbolAddress((void**)&vl,  g_v_l);
    cudaGetSymbolAddress((void**)&ph,  g_p_h);
    cudaGetSymbolAddress((void**)&ath, g_at_h);

    // P0: convert weights + transpose/convert x
    convert_weights<<<(HQKV * DIM + 255) / 256, 256>>>(qkv_w, proj_w);
    transpose_x<<<dim3(7, 12, BATCH), dim3(32, 8)>>>(x);

    // K1a: q,k rows = BN(W_qkv[0:768] @ x)  3-term -> fp32
    gemm_f16<0, true, false, 3><<<dim3(2, 768 / 128, BATCH), 256>>>(
        qwh, qwl, xth, xtl,
        qkvf, nullptr, nullptr,
        DIM / 16, DIM, DIM,
        0L, 0L, 1,
        (long)NPIX * DIM, (long)768 * NPIX, 0L,
        NPIX, 0, NPIX, 0,
        qkv_g, qkv_b, qkv_m, qkv_v);

    // K1b: V rows = BN(W_qkv[768:2304] @ x)  2-term -> fp16 h/l planes
    gemm_f16<1, true, false, 2><<<dim3(2, DH / 128, BATCH), 256>>>(
        qwh + (size_t)768 * DIM, qwl + (size_t)768 * DIM, xth, nullptr,
        nullptr, vh, vl,
        DIM / 16, DIM, DIM,
        0L, 0L, 1,
        (long)NPIX * DIM, 0L, (long)DH * NPAD,
        0, NPAD, NPIX, 0,
        qkv_g + 768, qkv_b + 768, qkv_m + 768, qkv_v + 768);

    // K2: q <- BN(dwconv3x3(q))  (4 channels per block)
    dwconv_bn<<<dim3(NH_KD / 4, BATCH), 224>>>(dw_w, dw_g, dw_b, dw_m, dw_v);

    // K3: bias gather
    {
        int total = NHEADS * NPIX * NPIX;
        bias_gather<<<(total + 255) / 256, 256>>>(ab, bidx);
    }
    // K4: softmax -> P hi plane
    attn_softmax<<<dim3(NHEADS, BATCH), 256>>>();

    // K5: attT hi = relu(V_hi @ P^T)^T  1-term fp16  (per b,h)
    gemm_f16<2, false, true, 1><<<dim3(2, 1, BATCH * NHEADS), 256>>>(
        vh, nullptr, ph, nullptr,
        nullptr, ath, nullptr,
        NPAD / 16, NPAD, NPAD,
        (long)DH * NPAD, (long)128 * NPAD, NHEADS,
        (long)NPIX * NPAD, 0L, (long)NPIX * DH,
        0, DH, NPIX, 0,
        nullptr, nullptr, nullptr, nullptr);

    // K6: out = BN(W_proj_hi @ att)  1-term fp16  (B = attT hi, k-contig)
    gemm_f16<0, true, false, 1><<<dim3(2, DIM / 128, BATCH), 256>>>(
        pwh, nullptr, ath, nullptr,
        out, nullptr, nullptr,
        DH / 16, DH, DH,
        0L, 0L, 1,
        (long)NPIX * DH, (long)DIM * NPIX, 0L,
        NPIX, 0, NPIX, DIM,
        proj_g, proj_b, proj_m, proj_v);
}

// round 14
// speedup vs baseline: 1.8943x; 1.0948x over previous
#include <cuda_runtime.h>
#include <cuda_fp16.h>
#include <math.h>
#include <stdint.h>

// ---------------- constants ----------------
#define BATCH   128
#define DIM     384
#define RES     14
#define NPIX    196
#define KEY_DIM 32
#define NHEADS  12
#define NH_KD   384
#define DH      1536
#define HQKV    2304
#define BN_EPS  1e-5f
#define NPAD    208     // NPIX padded to mult of 16

// ---------------- scratch ----------------
__device__ float g_qkv [ (size_t)BATCH * 768 * NPIX ];            // q+k fp32 only
__device__ float g_qdw [ (size_t)BATCH * NH_KD * NPIX ];
__device__ float g_bias[ (size_t)NHEADS * NPIX * NPIX ];

__device__ __half g_qw_h[ HQKV * DIM ],  g_qw_l[ HQKV * DIM ];
__device__ __half g_pw_h[ DIM * DH ];
__device__ __half g_xT_h[ (size_t)BATCH * NPIX * DIM ],  g_xT_l[ (size_t)BATCH * NPIX * DIM ];
__device__ __half g_v_h [ (size_t)BATCH * DH * NPAD ];              // hi plane only
__device__ __half g_p_h [ (size_t)BATCH * NHEADS * NPIX * NPAD ];   // hi plane only
__device__ __half g_at_h[ (size_t)BATCH * NPIX * DH ];              // hi plane only

// ---------------- helpers ----------------
__device__ __forceinline__ uint32_t smem_u32(const void* p) {
    uint32_t a;
    asm("{ .reg .u64 t; cvta.to.shared.u64 t, %1; cvt.u32.u64 %0, t; }"
        : "=r"(a) : "l"(p));
    return a;
}
#define LDSM4(r, addr) \
    asm volatile("ldmatrix.sync.aligned.m8n8.x4.shared.b16 {%0,%1,%2,%3}, [%4];" \
        : "=r"((r)[0]), "=r"((r)[1]), "=r"((r)[2]), "=r"((r)[3]) : "r"(addr))
#define MMA_F16(d, a, bb) \
    asm volatile("mma.sync.aligned.m16n8k16.row.col.f32.f16.f16.f32 " \
        "{%0,%1,%2,%3}, {%4,%5,%6,%7}, {%8,%9}, {%0,%1,%2,%3};" \
        : "+f"((d)[0]), "+f"((d)[1]), "+f"((d)[2]), "+f"((d)[3]) \
        : "r"((a)[0]), "r"((a)[1]), "r"((a)[2]), "r"((a)[3]), \
          "r"((bb)[0]), "r"((bb)[1]))
#define CP_ASYNC16(dst, src, sz) \
    asm volatile("cp.async.cg.shared.global [%0], [%1], 16, %2;" \
                 :: "r"(dst), "l"(src), "r"(sz))
#define CP_COMMIT() asm volatile("cp.async.commit_group;" ::: "memory")
#define CP_WAIT(n)  asm volatile("cp.async.wait_group %0;" :: "n"(n) : "memory")

__device__ __forceinline__ void split_f16(float v, __half& h, __half& l) {
    h = __float2half_rn(v);
    l = __float2half_rn(v - __half2float(h));
}

// ================= multistage fp16-plane GEMM =================
// C[m,n] = act(BN_m( sum_k A[m,k]*B[n,k] ))  -- k-contig fp16 planes.
// TERMS=3: hh + loA*hiB + hiA*loB (2 stages)
// TERMS=2: hh + loA*hiB           (3 stages)
// TERMS=1: hh                     (4 stages, plain fp16)
// One __syncthreads per mainloop iteration (stage issued post-sync).
// OUTMODE: 0 = fp32 out;
//          2 = transposed fp16 HI plane only  C^T[n][zi*128+m];
//          3 = fp16 HI plane only (pad cols zeroed).
template<int OUTMODE, bool HASBN, bool RELU, int TERMS>
__global__ void __launch_bounds__(256, 2)
gemm_f16(const __half* __restrict__ Ah, const __half* __restrict__ Al,
         const __half* __restrict__ Bh, const __half* __restrict__ Bl,
         float* __restrict__ Cf, __half* __restrict__ Ch,
         int nchunks, int lda, int ldb,
         long aOuter, long aInner, int innerCnt,
         long bStride, long cfStride, long cpStride,
         int ldcF, int ldcP, int nrowsB,
         const float* __restrict__ bng, const float* __restrict__ bnb,
         const float* __restrict__ bnm, const float* __restrict__ bnv)
{
    constexpr int KPA = (TERMS >= 2) ? 40 : 24;       // A: hi|lo combined or hi only
    constexpr int KPB = (TERMS == 3) ? 40 : 24;
    constexpr uint32_t A_BYTES = 128 * KPA * 2;
    constexpr uint32_t B_BYTES = 128 * KPB * 2;
    constexpr uint32_t STAGE   = A_BYTES + B_BYTES;   // 20480 / 16384 / 12288
    constexpr int NSTAGE = (TERMS == 3) ? 2 : (TERMS == 2 ? 3 : 4);
    __shared__ __align__(16) __half smbuf[(NSTAGE * STAGE) / 2];

    const int tid  = threadIdx.x;
    const int wid  = tid >> 5;
    const int lane = tid & 31;
    const int warp_m = wid & 3;
    const int warp_n = wid >> 2;
    const int n0 = blockIdx.x * 128;
    const int m0 = blockIdx.y * 128;
    const int z  = blockIdx.z;
    const int zb = z / innerCnt, zi = z - zb * innerCnt;

    const __half* Agh = Ah + (size_t)zb * aOuter + (size_t)zi * aInner + (size_t)m0 * lda;
    const __half* Agl = (TERMS >= 2) ? (Al + (size_t)zb * aOuter + (size_t)zi * aInner + (size_t)m0 * lda) : nullptr;
    const __half* Bgh = Bh + (size_t)z * bStride;
    const __half* Bgl = (TERMS == 3) ? (Bl + (size_t)z * bStride) : nullptr;

    const uint32_t smb = smem_u32(smbuf);

    const bool full = (n0 + warp_n * 64 + 64) <= nrowsB;
    int jlim = nrowsB - (n0 + warp_n * 64);
    jlim = jlim <= 0 ? 0 : ((jlim + 7) >> 3);
    if (jlim > 8) jlim = 8;

    auto stage = [&](int ch, int s) {
        const int k0 = ch * 16;
        const uint32_t sb = smb + (uint32_t)s * STAGE;
        // A
        if (TERMS >= 2) {
#pragma unroll
            for (int i = 0; i < 2; i++) {
                int idx = i * 256 + tid;
                int row = idx >> 2;
                int p   = idx & 3;                 // 0,1 = hi halves; 2,3 = lo halves
                const __half* src = (p < 2 ? Agh : Agl) + (size_t)row * lda + k0 + (p & 1) * 8;
                uint32_t dst = sb + (uint32_t)(row * KPA + p * 8) * 2;
                CP_ASYNC16(dst, src, 16u);
            }
        } else {
            int row = tid >> 1;
            int h   = tid & 1;
            const __half* src = Agh + (size_t)row * lda + k0 + h * 8;
            uint32_t dst = sb + (uint32_t)(row * KPA + h * 8) * 2;
            CP_ASYNC16(dst, src, 16u);
        }
        // B
        if (TERMS == 3) {
#pragma unroll
            for (int i = 0; i < 2; i++) {
                int idx = i * 256 + tid;
                int row = idx >> 2;
                int p   = idx & 3;
                int rowg = n0 + row;
                unsigned sz = 16u;
                if (rowg >= nrowsB) { rowg = 0; sz = 0u; }
                const __half* src = (p < 2 ? Bgh : Bgl) + (size_t)rowg * ldb + k0 + (p & 1) * 8;
                uint32_t dst = sb + A_BYTES + (uint32_t)(row * KPB + p * 8) * 2;
                CP_ASYNC16(dst, src, sz);
            }
        } else {
            int row = tid >> 1;
            int h   = tid & 1;
            int rowg = n0 + row;
            unsigned sz = 16u;
            if (rowg >= nrowsB) { rowg = 0; sz = 0u; }
            const __half* src = Bgh + (size_t)rowg * ldb + k0 + h * 8;
            uint32_t dst = sb + A_BYTES + (uint32_t)(row * KPB + h * 8) * 2;
            CP_ASYNC16(dst, src, sz);
        }
        CP_COMMIT();
    };

    float acc[2][8][4];
#pragma unroll
    for (int t = 0; t < 2; t++)
#pragma unroll
        for (int j = 0; j < 8; j++)
#pragma unroll
            for (int c = 0; c < 4; c++) acc[t][j][c] = 0.f;

    // prologue: stage first NSTAGE-1 chunks
    stage(0, 0);
#pragma unroll
    for (int s = 1; s < NSTAGE - 1; s++) {
        if (s < nchunks) stage(s, s);
        else CP_COMMIT();
    }

    for (int ch = 0; ch < nchunks; ch++) {
        CP_WAIT(NSTAGE - 2);
        __syncthreads();

        {   // stage next (post-sync: safe to overwrite oldest buffer)
            int nx = ch + NSTAGE - 1;
            if (nx < nchunks) stage(nx, nx % NSTAGE);
            else CP_COMMIT();
        }

        const uint32_t base  = smb + (uint32_t)(ch % NSTAGE) * STAGE;
        const uint32_t aBase = base;
        const uint32_t bBase = base + A_BYTES;

        uint32_t a_hi[2][4], a_lo[2][4];
#pragma unroll
        for (int t = 0; t < 2; t++) {
            int row = warp_m * 32 + t * 16 + (lane & 15);
            int col = (lane >> 4) << 3;
            uint32_t off = (uint32_t)(row * KPA + col) * 2;
            LDSM4(a_hi[t], aBase + off);
            if (TERMS >= 2) LDSM4(a_lo[t], aBase + off + 32);   // lo cols 16..31
        }
        int nrow = warp_n * 64 + (lane & 7) + ((lane >> 4) << 3);
        int bcol = ((lane >> 3) & 1) << 3;
        uint32_t boff = (uint32_t)(nrow * KPB + bcol) * 2;

        if (full) {
            uint32_t b[8][2];
#pragma unroll
            for (int j = 0; j < 4; j++) {
                uint32_t r[4];
                LDSM4(r, bBase + boff + (uint32_t)(j * 16 * KPB) * 2);
                b[2 * j][0] = r[0]; b[2 * j][1] = r[1];
                b[2 * j + 1][0] = r[2]; b[2 * j + 1][1] = r[3];
            }
#pragma unroll
            for (int t = 0; t < 2; t++)
#pragma unroll
                for (int j = 0; j < 8; j++) MMA_F16(acc[t][j], a_hi[t], b[j]);
            if (TERMS >= 2) {
#pragma unroll
                for (int t = 0; t < 2; t++)
#pragma unroll
                    for (int j = 0; j < 8; j++) MMA_F16(acc[t][j], a_lo[t], b[j]);
            }
            if (TERMS == 3) {
#pragma unroll
                for (int j = 0; j < 4; j++) {
                    uint32_t r[4];
                    LDSM4(r, bBase + boff + 32 + (uint32_t)(j * 16 * KPB) * 2);  // B-lo cols
                    b[2 * j][0] = r[0]; b[2 * j][1] = r[1];
                    b[2 * j + 1][0] = r[2]; b[2 * j + 1][1] = r[3];
                }
#pragma unroll
                for (int t = 0; t < 2; t++)
#pragma unroll
                    for (int j = 0; j < 8; j++) MMA_F16(acc[t][j], a_hi[t], b[j]);
            }
        } else if (jlim > 0) {
            uint32_t b2[2][2];
            {
                uint32_t r[4];
                LDSM4(r, bBase + boff);
                b2[0][0] = r[0]; b2[0][1] = r[1];
                b2[1][0] = r[2]; b2[1][1] = r[3];
            }
#pragma unroll
            for (int t = 0; t < 2; t++)
#pragma unroll
                for (int j = 0; j < 2; j++)
                    if (j < jlim) MMA_F16(acc[t][j], a_hi[t], b2[j]);
            if (TERMS >= 2) {
#pragma unroll
                for (int t = 0; t < 2; t++)
#pragma unroll
                    for (int j = 0; j < 2; j++)
                        if (j < jlim) MMA_F16(acc[t][j], a_lo[t], b2[j]);
            }
            if (TERMS == 3) {
                uint32_t r[4];
                LDSM4(r, bBase + boff + 32);
                b2[0][0] = r[0]; b2[0][1] = r[1];
                b2[1][0] = r[2]; b2[1][1] = r[3];
#pragma unroll
                for (int t = 0; t < 2; t++)
#pragma unroll
                    for (int j = 0; j < 2; j++)
                        if (j < jlim) MMA_F16(acc[t][j], a_hi[t], b2[j]);
            }
        }
    }

    // ---------------- epilogues ----------------
    if (OUTMODE == 0 || OUTMODE == 3) {
#pragma unroll
        for (int t = 0; t < 2; t++) {
            int r0 = m0 + warp_m * 32 + t * 16 + (lane >> 2);
            int r1 = r0 + 8;
            float s0 = 1.f, h0 = 0.f, s1 = 1.f, h1 = 0.f;
            if (HASBN) {
                float a = bng[r0] * rsqrtf(bnv[r0] + BN_EPS);
                s0 = a; h0 = bnb[r0] - bnm[r0] * a;
                float c = bng[r1] * rsqrtf(bnv[r1] + BN_EPS);
                s1 = c; h1 = bnb[r1] - bnm[r1] * c;
            }
#pragma unroll
            for (int j = 0; j < 8; j++) {
                int nn = n0 + warp_n * 64 + j * 8 + 2 * (lane & 3);
                float v0 = acc[t][j][0] * s0 + h0;
                float v1 = acc[t][j][1] * s0 + h0;
                float v2 = acc[t][j][2] * s1 + h1;
                float v3 = acc[t][j][3] * s1 + h1;
                if (RELU) {
                    v0 = fmaxf(v0, 0.f); v1 = fmaxf(v1, 0.f);
                    v2 = fmaxf(v2, 0.f); v3 = fmaxf(v3, 0.f);
                }
                if (OUTMODE == 0) {
                    if (nn < NPIX) {
                        *(float2*)(Cf + (size_t)z * cfStride + (size_t)r0 * ldcF + nn) = make_float2(v0, v1);
                        *(float2*)(Cf + (size_t)z * cfStride + (size_t)r1 * ldcF + nn) = make_float2(v2, v3);
                    }
                } else {
                    if (nn < NPAD) {
                        if (nn >= NPIX) { v0 = v1 = v2 = v3 = 0.f; }
                        size_t p0 = (size_t)z * cpStride + (size_t)r0 * ldcP + nn;
                        size_t p1 = (size_t)z * cpStride + (size_t)r1 * ldcP + nn;
                        *(__half2*)(Ch + p0) = __half2(__float2half_rn(v0), __float2half_rn(v1));
                        *(__half2*)(Ch + p1) = __half2(__float2half_rn(v2), __float2half_rn(v3));
                    }
                }
            }
        }
    } else {
        // OUTMODE 2: transposed HI-plane output via smem (reuse stage buffer)
        __half* ep = smbuf;   // [128 i][136 d]
        __syncthreads();
#pragma unroll
        for (int t = 0; t < 2; t++) {
            int d0 = warp_m * 32 + t * 16 + (lane >> 2);
            int d1 = d0 + 8;
#pragma unroll
            for (int j = 0; j < 8; j++) {
                int il = warp_n * 64 + j * 8 + 2 * (lane & 3);
                float v0 = acc[t][j][0], v1 = acc[t][j][1];
                float v2 = acc[t][j][2], v3 = acc[t][j][3];
                if (RELU) {
                    v0 = fmaxf(v0, 0.f); v1 = fmaxf(v1, 0.f);
                    v2 = fmaxf(v2, 0.f); v3 = fmaxf(v3, 0.f);
                }
                ep[il * 136 + d0]       = __float2half_rn(v0);
                ep[(il + 1) * 136 + d0] = __float2half_rn(v1);
                ep[il * 136 + d1]       = __float2half_rn(v2);
                ep[(il + 1) * 136 + d1] = __float2half_rn(v3);
            }
        }
        __syncthreads();
        __half* dst = Ch + (size_t)zb * cpStride + (size_t)zi * 128;
        for (int c2 = tid; c2 < 2048; c2 += 256) {
            int row = c2 >> 4, off = (c2 & 15) * 8;
            int i = n0 + row;
            if (i < NPIX) {
                uint4 val = *(uint4*)(ep + row * 136 + off);
                *(uint4*)(dst + (size_t)i * ldcP + off) = val;
            }
        }
    }
}

// ---------------- pre-convert kernels ----------------
__global__ void convert_weights(const float* __restrict__ qw, const float* __restrict__ pw)
{
    int i = blockIdx.x * 256 + threadIdx.x;
    if (i < HQKV * DIM) split_f16(qw[i], g_qw_h[i], g_qw_l[i]);
    if (i < DIM * DH)   g_pw_h[i] = __float2half_rn(pw[i]);
}

__global__ void transpose_x(const float* __restrict__ x)
{
    __shared__ float t[32][33];
    int p0 = blockIdx.x * 32, c0 = blockIdx.y * 32, b = blockIdx.z;
    for (int r = threadIdx.y; r < 32; r += 8) {
        int p = p0 + threadIdx.x;
        t[r][threadIdx.x] = (p < NPIX) ? x[((size_t)b * DIM + c0 + r) * NPIX + p] : 0.f;
    }
    __syncthreads();
    for (int r = threadIdx.y; r < 32; r += 8) {
        int p = p0 + r, c = c0 + threadIdx.x;
        if (p < NPIX) {
            size_t o = ((size_t)b * NPIX + p) * DIM + c;
            split_f16(t[threadIdx.x][r], g_xT_h[o], g_xT_l[o]);
        }
    }
}

// ---------------- dwconv + BN: 4 channels per block --------------------------
__global__ void __launch_bounds__(224, 8)
dwconv_bn(const float* __restrict__ w,
          const float* __restrict__ bng,
          const float* __restrict__ bnb,
          const float* __restrict__ bnm,
          const float* __restrict__ bnv)
{
    const int c0 = blockIdx.x * 4;
    const int b  = blockIdx.y;
    __shared__ float t[4][200];
    __shared__ float wgt[4][9];
    __shared__ float sBN[4][2];

    const float* src = g_qkv + (size_t)b * 768 * NPIX + (size_t)c0 * NPIX;
    int tid = threadIdx.x;
    for (int e = tid; e < 4 * NPIX; e += 224) {
        int ch = e / NPIX, p = e - ch * NPIX;
        t[ch][p] = src[ch * NPIX + p];
    }
    if (tid < 36) wgt[tid / 9][tid % 9] = w[c0 * 9 + tid];
    if (tid < 4) {
        int c = c0 + tid;
        float s = bng[c] * rsqrtf(bnv[c] + BN_EPS);
        sBN[tid][0] = s;
        sBN[tid][1] = bnb[c] - bnm[c] * s;
    }
    __syncthreads();

    if (tid < NPIX) {
        int y = tid / RES, x = tid - y * RES;
#pragma unroll
        for (int ch = 0; ch < 4; ch++) {
            float acc = 0.f;
#pragma unroll
            for (int ky = 0; ky < 3; ky++) {
                int yy = y + ky - 1;
                if (yy < 0 || yy >= RES) continue;
#pragma unroll
                for (int kx = 0; kx < 3; kx++) {
                    int xx = x + kx - 1;
                    if (xx < 0 || xx >= RES) continue;
                    acc += t[ch][yy * RES + xx] * wgt[ch][ky * 3 + kx];
                }
            }
            g_qdw[((size_t)b * NH_KD + c0 + ch) * NPIX + tid] = acc * sBN[ch][0] + sBN[ch][1];
        }
    }
}

// ---------------- bias gather ----------------
__global__ void bias_gather(const float* __restrict__ ab, const int* __restrict__ idxs)
{
    int idx = blockIdx.x * 256 + threadIdx.x;
    if (idx >= NHEADS * NPIX * NPIX) return;
    int h  = idx / (NPIX * NPIX);
    int ij = idx % (NPIX * NPIX);
    g_bias[idx] = ab[h * NPIX + idxs[ij]];
}

// ---------------- softmax: 4 rows/warp (low regs, high occ) -----------------
__global__ void attn_softmax(void)
{
    const int h = blockIdx.x;
    const int b = blockIdx.y;
    __shared__ float k_s[32 * 224];

    const float* qg = g_qdw + (size_t)b * NH_KD * NPIX + (size_t)h * KEY_DIM * NPIX;
    const float* kg = g_qkv + (size_t)b * 768 * NPIX + (size_t)(NH_KD + h * KEY_DIM) * NPIX;

    for (int idx = threadIdx.x; idx < 32 * 224; idx += 256) {
        int d = idx / 224, j = idx % 224;
        k_s[idx] = (j < NPIX) ? kg[d * NPIX + j] : 0.f;
    }
    __syncthreads();

    const int w    = threadIdx.x >> 5;
    const int lane = threadIdx.x & 31;
    const float* bh = g_bias + (size_t)h * NPIX * NPIX;
    const size_t zoff = ((size_t)b * NHEADS + h) * NPIX * NPAD;
    const float scale = 0.17677669529663687f;

    for (int i0 = w * 4; i0 < NPIX; i0 += 32) {
        float q_reg[4];
#pragma unroll
        for (int r = 0; r < 4; r++) {
            int i = i0 + r;
            q_reg[r] = (i < NPIX) ? qg[(size_t)lane * NPIX + i] : 0.f;
        }

        float s[4][7];
#pragma unroll
        for (int r = 0; r < 4; r++)
#pragma unroll
            for (int m = 0; m < 7; m++) s[r][m] = 0.f;

        for (int d = 0; d < 32; d++) {
            float qv[4];
#pragma unroll
            for (int r = 0; r < 4; r++)
                qv[r] = __shfl_sync(0xffffffffu, q_reg[r], d);
#pragma unroll
            for (int m = 0; m < 7; m++) {
                float kv = k_s[d * 224 + lane + m * 32];
#pragma unroll
                for (int r = 0; r < 4; r++) s[r][m] += qv[r] * kv;
            }
        }

#pragma unroll
        for (int r = 0; r < 4; r++) {
            int i = i0 + r;
            if (i >= NPIX) break;
            float sv[7];
            float mx = -1e30f;
#pragma unroll
            for (int m = 0; m < 7; m++) {
                int j = lane + m * 32;
                float val = (j < NPIX) ? s[r][m] * scale + bh[(size_t)i * NPIX + j]
                                       : -1e30f;
                sv[m] = val;
                mx = fmaxf(mx, val);
            }
#pragma unroll
            for (int off = 16; off; off >>= 1)
                mx = fmaxf(mx, __shfl_xor_sync(0xffffffffu, mx, off));
            float sum = 0.f;
#pragma unroll
            for (int m = 0; m < 7; m++) {
                sv[m] = __expf(sv[m] - mx);
                sum += sv[m];
            }
#pragma unroll
            for (int off = 16; off; off >>= 1)
                sum += __shfl_xor_sync(0xffffffffu, sum, off);
            float inv = 1.f / sum;
#pragma unroll
            for (int m = 0; m < 7; m++) {
                int j = lane + m * 32;
                if (j < NPIX) {
                    g_p_h[zoff + (size_t)i * NPAD + j] = __float2half_rn(sv[m] * inv);
                } else if (j < NPAD) {
                    g_p_h[zoff + (size_t)i * NPAD + j] = __float2half_rn(0.f);
                }
            }
        }
    }
}

// ---------------- launch ----------------------------------------------------
extern "C" void kernel_launch(void* const* d_in, const int* in_sizes, int n_in,
                              void* d_out, int out_size)
{
    const float* x      = (const float*)d_in[0];
    const float* qkv_w  = (const float*)d_in[1];
    const float* qkv_g  = (const float*)d_in[2];
    const float* qkv_b  = (const float*)d_in[3];
    const float* qkv_m  = (const float*)d_in[4];
    const float* qkv_v  = (const float*)d_in[5];
    const float* dw_w   = (const float*)d_in[6];
    const float* dw_g   = (const float*)d_in[7];
    const float* dw_b   = (const float*)d_in[8];
    const float* dw_m   = (const float*)d_in[9];
    const float* dw_v   = (const float*)d_in[10];
    const float* proj_w = (const float*)d_in[11];
    const float* proj_g = (const float*)d_in[12];
    const float* proj_b = (const float*)d_in[13];
    const float* proj_m = (const float*)d_in[14];
    const float* proj_v = (const float*)d_in[15];
    const float* ab     = (const float*)d_in[16];
    const int*   bidx   = (const int*)d_in[17];
    float* out = (float*)d_out;

    float* qkvf;  cudaGetSymbolAddress((void**)&qkvf,  g_qkv);
    __half *qwh, *qwl, *pwh, *xth, *xtl, *vh, *ph, *ath;
    cudaGetSymbolAddress((void**)&qwh, g_qw_h);  cudaGetSymbolAddress((void**)&qwl, g_qw_l);
    cudaGetSymbolAddress((void**)&pwh, g_pw_h);
    cudaGetSymbolAddress((void**)&xth, g_xT_h);  cudaGetSymbolAddress((void**)&xtl, g_xT_l);
    cudaGetSymbolAddress((void**)&vh,  g_v_h);
    cudaGetSymbolAddress((void**)&ph,  g_p_h);
    cudaGetSymbolAddress((void**)&ath, g_at_h);

    // P0: convert weights + transpose/convert x
    convert_weights<<<(HQKV * DIM + 255) / 256, 256>>>(qkv_w, proj_w);
    transpose_x<<<dim3(7, 12, BATCH), dim3(32, 8)>>>(x);

    // K1a: q,k rows = BN(W_qkv[0:768] @ x)  3-term -> fp32
    gemm_f16<0, true, false, 3><<<dim3(2, 768 / 128, BATCH), 256>>>(
        qwh, qwl, xth, xtl,
        qkvf, nullptr,
        DIM / 16, DIM, DIM,
        0L, 0L, 1,
        (long)NPIX * DIM, (long)768 * NPIX, 0L,
        NPIX, 0, NPIX,
        qkv_g, qkv_b, qkv_m, qkv_v);

    // K1b: V rows = BN(W_qkv_hi[768:2304] @ x_hi)  1-term -> fp16 hi plane
    gemm_f16<3, true, false, 1><<<dim3(2, DH / 128, BATCH), 256>>>(
        qwh + (size_t)768 * DIM, nullptr, xth, nullptr,
        nullptr, vh,
        DIM / 16, DIM, DIM,
        0L, 0L, 1,
        (long)NPIX * DIM, 0L, (long)DH * NPAD,
        0, NPAD, NPIX,
        qkv_g + 768, qkv_b + 768, qkv_m + 768, qkv_v + 768);

    // K2: q <- BN(dwconv3x3(q))  (4 channels per block)
    dwconv_bn<<<dim3(NH_KD / 4, BATCH), 224>>>(dw_w, dw_g, dw_b, dw_m, dw_v);

    // K3: bias gather
    {
        int total = NHEADS * NPIX * NPIX;
        bias_gather<<<(total + 255) / 256, 256>>>(ab, bidx);
    }
    // K4: softmax -> P hi plane
    attn_softmax<<<dim3(NHEADS, BATCH), 256>>>();

    // K5: attT hi = relu(V_hi @ P^T)^T  1-term fp16  (per b,h)
    gemm_f16<2, false, true, 1><<<dim3(2, 1, BATCH * NHEADS), 256>>>(
        vh, nullptr, ph, nullptr,
        nullptr, ath,
        NPAD / 16, NPAD, NPAD,
        (long)DH * NPAD, (long)128 * NPAD, NHEADS,
        (long)NPIX * NPAD, 0L, (long)NPIX * DH,
        0, DH, NPIX,
        nullptr, nullptr, nullptr, nullptr);

    // K6: out = BN(W_proj_hi @ att)  1-term fp16  (B = attT hi, k-contig)
    gemm_f16<0, true, false, 1><<<dim3(2, DIM / 128, BATCH), 256>>>(
        pwh, nullptr, ath, nullptr,
        out, nullptr,
        DH / 16, DH, DH,
        0L, 0L, 1,
        (long)NPIX * DH, (long)DIM * NPIX, 0L,
        NPIX, 0, NPIX,
        proj_g, proj_b, proj_m, proj_v);
}

// round 15
// speedup vs baseline: 1.9661x; 1.0379x over previous
#include <cuda_runtime.h>
#include <cuda_fp16.h>
#include <math.h>
#include <stdint.h>

// ---------------- constants ----------------
#define BATCH   128
#define DIM     384
#define RES     14
#define NPIX    196
#define KEY_DIM 32
#define NHEADS  12
#define NH_KD   384
#define DH      1536
#define HQKV    2304
#define BN_EPS  1e-5f
#define NPAD    224     // NPIX padded to mult of 32

// ---------------- scratch ----------------
__device__ float g_qkv [ (size_t)BATCH * 768 * NPIX ];            // q+k fp32 only
__device__ float g_qdw [ (size_t)BATCH * NH_KD * NPIX ];

__device__ __half g_qw_h[ HQKV * DIM ],  g_qw_l[ HQKV * DIM ];
__device__ __half g_pw_h[ DIM * DH ];
__device__ __half g_xT_h[ (size_t)BATCH * NPIX * DIM ],  g_xT_l[ (size_t)BATCH * NPIX * DIM ];
__device__ __half g_v_h [ (size_t)BATCH * DH * NPAD ];              // hi plane only
__device__ __half g_p_h [ (size_t)BATCH * NHEADS * NPIX * NPAD ];   // hi plane only
__device__ __half g_at_h[ (size_t)BATCH * NPIX * DH ];              // hi plane only

// ---------------- helpers ----------------
__device__ __forceinline__ uint32_t smem_u32(const void* p) {
    uint32_t a;
    asm("{ .reg .u64 t; cvta.to.shared.u64 t, %1; cvt.u32.u64 %0, t; }"
        : "=r"(a) : "l"(p));
    return a;
}
#define LDSM4(r, addr) \
    asm volatile("ldmatrix.sync.aligned.m8n8.x4.shared.b16 {%0,%1,%2,%3}, [%4];" \
        : "=r"((r)[0]), "=r"((r)[1]), "=r"((r)[2]), "=r"((r)[3]) : "r"(addr))
#define MMA_F16(d, a, bb) \
    asm volatile("mma.sync.aligned.m16n8k16.row.col.f32.f16.f16.f32 " \
        "{%0,%1,%2,%3}, {%4,%5,%6,%7}, {%8,%9}, {%0,%1,%2,%3};" \
        : "+f"((d)[0]), "+f"((d)[1]), "+f"((d)[2]), "+f"((d)[3]) \
        : "r"((a)[0]), "r"((a)[1]), "r"((a)[2]), "r"((a)[3]), \
          "r"((bb)[0]), "r"((bb)[1]))
#define CP_ASYNC16(dst, src, sz) \
    asm volatile("cp.async.cg.shared.global [%0], [%1], 16, %2;" \
                 :: "r"(dst), "l"(src), "r"(sz))
#define CP_COMMIT() asm volatile("cp.async.commit_group;" ::: "memory")
#define CP_WAIT(n)  asm volatile("cp.async.wait_group %0;" :: "n"(n) : "memory")

__device__ __forceinline__ void split_f16(float v, __half& h, __half& l) {
    h = __float2half_rn(v);
    l = __float2half_rn(v - __half2float(h));
}

// ================= multistage fp16-plane GEMM =================
// C[m,n] = act(BN_m( sum_k A[m,k]*B[n,k] ))  -- k-contig fp16 planes.
// TERMS=3: hh + loA*hiB + hiA*loB, K-chunk 16, 2 stages (40 KB)
// TERMS=1: hh only,                K-chunk 32, 2 stages (40 KB)
// One __syncthreads per mainloop iteration (stage issued post-sync).
// OUTMODE: 0 = fp32 out;
//          2 = transposed fp16 HI plane only  C^T[n][zi*128+m];
//          3 = fp16 HI plane only (pad cols zeroed).
template<int OUTMODE, bool HASBN, bool RELU, int TERMS>
__global__ void __launch_bounds__(256, 2)
gemm_f16(const __half* __restrict__ Ah, const __half* __restrict__ Al,
         const __half* __restrict__ Bh, const __half* __restrict__ Bl,
         float* __restrict__ Cf, __half* __restrict__ Ch,
         int nchunks, int lda, int ldb,
         long aOuter, long aInner, int innerCnt,
         long bStride, long cfStride, long cpStride,
         int ldcF, int ldcP, int nrowsB,
         const float* __restrict__ bng, const float* __restrict__ bnb,
         const float* __restrict__ bnm, const float* __restrict__ bnv)
{
    constexpr int KSTEPS = (TERMS == 1) ? 2 : 1;      // k16 steps per chunk
    constexpr int KPA = 40;                            // 32 data (hi|lo or k32) + 8 pad
    constexpr int KPB = (TERMS == 3) ? 40 : ((TERMS == 1) ? 40 : 24);
    constexpr uint32_t A_BYTES = 128 * KPA * 2;        // 10240
    constexpr uint32_t B_BYTES = 128 * KPB * 2;
    constexpr uint32_t STAGE   = A_BYTES + B_BYTES;    // 20480
    constexpr int NSTAGE = 2;
    __shared__ __align__(16) __half smbuf[(NSTAGE * STAGE) / 2];

    const int tid  = threadIdx.x;
    const int wid  = tid >> 5;
    const int lane = tid & 31;
    const int warp_m = wid & 3;
    const int warp_n = wid >> 2;
    const int n0 = blockIdx.x * 128;
    const int m0 = blockIdx.y * 128;
    const int z  = blockIdx.z;
    const int zb = z / innerCnt, zi = z - zb * innerCnt;

    const __half* Agh = Ah + (size_t)zb * aOuter + (size_t)zi * aInner + (size_t)m0 * lda;
    const __half* Agl = (TERMS >= 2) ? (Al + (size_t)zb * aOuter + (size_t)zi * aInner + (size_t)m0 * lda) : nullptr;
    const __half* Bgh = Bh + (size_t)z * bStride;
    const __half* Bgl = (TERMS == 3) ? (Bl + (size_t)z * bStride) : nullptr;

    const uint32_t smb = smem_u32(smbuf);

    const bool full = (n0 + warp_n * 64 + 64) <= nrowsB;
    int jlim = nrowsB - (n0 + warp_n * 64);
    jlim = jlim <= 0 ? 0 : ((jlim + 7) >> 3);
    if (jlim > 8) jlim = 8;

    // KCHUNK = 16*KSTEPS
    auto stage = [&](int ch, int s) {
        const int k0 = ch * 16 * KSTEPS;
        const uint32_t sb = smb + (uint32_t)s * STAGE;
        // A: 512 16B pieces. TERMS>=2: p<2 hi (cols 0-15), p>=2 lo (cols 16-31).
        //    TERMS==1: p = quarter of 32 k-cols.
#pragma unroll
        for (int i = 0; i < 2; i++) {
            int idx = i * 256 + tid;
            int row = idx >> 2;
            int p   = idx & 3;
            const __half* src;
            if (TERMS >= 2)
                src = (p < 2 ? Agh : Agl) + (size_t)row * lda + k0 + (p & 1) * 8;
            else
                src = Agh + (size_t)row * lda + k0 + p * 8;
            uint32_t dst = sb + (uint32_t)(row * KPA + p * 8) * 2;
            CP_ASYNC16(dst, src, 16u);
        }
        // B
        if (TERMS == 3) {
#pragma unroll
            for (int i = 0; i < 2; i++) {
                int idx = i * 256 + tid;
                int row = idx >> 2;
                int p   = idx & 3;
                int rowg = n0 + row;
                unsigned sz = 16u;
                if (rowg >= nrowsB) { rowg = 0; sz = 0u; }
                const __half* src = (p < 2 ? Bgh : Bgl) + (size_t)rowg * ldb + k0 + (p & 1) * 8;
                uint32_t dst = sb + A_BYTES + (uint32_t)(row * KPB + p * 8) * 2;
                CP_ASYNC16(dst, src, sz);
            }
        } else {  // TERMS==1: 32 k-cols hi
#pragma unroll
            for (int i = 0; i < 2; i++) {
                int idx = i * 256 + tid;
                int row = idx >> 2;
                int p   = idx & 3;
                int rowg = n0 + row;
                unsigned sz = 16u;
                if (rowg >= nrowsB) { rowg = 0; sz = 0u; }
                const __half* src = Bgh + (size_t)rowg * ldb + k0 + p * 8;
                uint32_t dst = sb + A_BYTES + (uint32_t)(row * KPB + p * 8) * 2;
                CP_ASYNC16(dst, src, sz);
            }
        }
        CP_COMMIT();
    };

    float acc[2][8][4];
#pragma unroll
    for (int t = 0; t < 2; t++)
#pragma unroll
        for (int j = 0; j < 8; j++)
#pragma unroll
            for (int c = 0; c < 4; c++) acc[t][j][c] = 0.f;

    stage(0, 0);

    for (int ch = 0; ch < nchunks; ch++) {
        CP_WAIT(0);
        __syncthreads();

        {   // stage next (post-sync)
            int nx = ch + 1;
            if (nx < nchunks) stage(nx, nx & 1);
            else CP_COMMIT();
        }

        const uint32_t base  = smb + (uint32_t)(ch & 1) * STAGE;
        const uint32_t aBase = base;
        const uint32_t bBase = base + A_BYTES;

#pragma unroll
        for (int ks = 0; ks < KSTEPS; ks++) {
            const int kel = ks * 16;
            uint32_t a_hi[2][4], a_lo[2][4];
#pragma unroll
            for (int t = 0; t < 2; t++) {
                int row = warp_m * 32 + t * 16 + (lane & 15);
                int col = kel + ((lane >> 4) << 3);
                uint32_t off = (uint32_t)(row * KPA + col) * 2;
                LDSM4(a_hi[t], aBase + off);
                if (TERMS >= 2) LDSM4(a_lo[t], aBase + off + 32);
            }
            int nrow = warp_n * 64 + (lane & 7) + ((lane >> 4) << 3);
            int bcol = kel + (((lane >> 3) & 1) << 3);
            uint32_t boff = (uint32_t)(nrow * KPB + bcol) * 2;

            if (full) {
                uint32_t b[8][2];
#pragma unroll
                for (int j = 0; j < 4; j++) {
                    uint32_t r[4];
                    LDSM4(r, bBase + boff + (uint32_t)(j * 16 * KPB) * 2);
                    b[2 * j][0] = r[0]; b[2 * j][1] = r[1];
                    b[2 * j + 1][0] = r[2]; b[2 * j + 1][1] = r[3];
                }
#pragma unroll
                for (int t = 0; t < 2; t++)
#pragma unroll
                    for (int j = 0; j < 8; j++) MMA_F16(acc[t][j], a_hi[t], b[j]);
                if (TERMS >= 2) {
#pragma unroll
                    for (int t = 0; t < 2; t++)
#pragma unroll
                        for (int j = 0; j < 8; j++) MMA_F16(acc[t][j], a_lo[t], b[j]);
                }
                if (TERMS == 3) {
#pragma unroll
                    for (int j = 0; j < 4; j++) {
                        uint32_t r[4];
                        LDSM4(r, bBase + boff + 32 + (uint32_t)(j * 16 * KPB) * 2);
                        b[2 * j][0] = r[0]; b[2 * j][1] = r[1];
                        b[2 * j + 1][0] = r[2]; b[2 * j + 1][1] = r[3];
                    }
#pragma unroll
                    for (int t = 0; t < 2; t++)
#pragma unroll
                        for (int j = 0; j < 8; j++) MMA_F16(acc[t][j], a_hi[t], b[j]);
                }
            } else if (jlim > 0) {
                uint32_t b2[2][2];
                {
                    uint32_t r[4];
                    LDSM4(r, bBase + boff);
                    b2[0][0] = r[0]; b2[0][1] = r[1];
                    b2[1][0] = r[2]; b2[1][1] = r[3];
                }
#pragma unroll
                for (int t = 0; t < 2; t++)
#pragma unroll
                    for (int j = 0; j < 2; j++)
                        if (j < jlim) MMA_F16(acc[t][j], a_hi[t], b2[j]);
                if (TERMS >= 2) {
#pragma unroll
                    for (int t = 0; t < 2; t++)
#pragma unroll
                        for (int j = 0; j < 2; j++)
                            if (j < jlim) MMA_F16(acc[t][j], a_lo[t], b2[j]);
                }
                if (TERMS == 3) {
                    uint32_t r[4];
                    LDSM4(r, bBase + boff + 32);
                    b2[0][0] = r[0]; b2[0][1] = r[1];
                    b2[1][0] = r[2]; b2[1][1] = r[3];
#pragma unroll
                    for (int t = 0; t < 2; t++)
#pragma unroll
                        for (int j = 0; j < 2; j++)
                            if (j < jlim) MMA_F16(acc[t][j], a_hi[t], b2[j]);
                }
            }
        }
    }

    // ---------------- epilogues ----------------
    if (OUTMODE == 0 || OUTMODE == 3) {
#pragma unroll
        for (int t = 0; t < 2; t++) {
            int r0 = m0 + warp_m * 32 + t * 16 + (lane >> 2);
            int r1 = r0 + 8;
            float s0 = 1.f, h0 = 0.f, s1 = 1.f, h1 = 0.f;
            if (HASBN) {
                float a = bng[r0] * rsqrtf(bnv[r0] + BN_EPS);
                s0 = a; h0 = bnb[r0] - bnm[r0] * a;
                float c = bng[r1] * rsqrtf(bnv[r1] + BN_EPS);
                s1 = c; h1 = bnb[r1] - bnm[r1] * c;
            }
#pragma unroll
            for (int j = 0; j < 8; j++) {
                int nn = n0 + warp_n * 64 + j * 8 + 2 * (lane & 3);
                float v0 = acc[t][j][0] * s0 + h0;
                float v1 = acc[t][j][1] * s0 + h0;
                float v2 = acc[t][j][2] * s1 + h1;
                float v3 = acc[t][j][3] * s1 + h1;
                if (RELU) {
                    v0 = fmaxf(v0, 0.f); v1 = fmaxf(v1, 0.f);
                    v2 = fmaxf(v2, 0.f); v3 = fmaxf(v3, 0.f);
                }
                if (OUTMODE == 0) {
                    if (nn < NPIX) {
                        *(float2*)(Cf + (size_t)z * cfStride + (size_t)r0 * ldcF + nn) = make_float2(v0, v1);
                        *(float2*)(Cf + (size_t)z * cfStride + (size_t)r1 * ldcF + nn) = make_float2(v2, v3);
                    }
                } else {
                    if (nn < NPAD) {
                        if (nn >= NPIX) { v0 = v1 = v2 = v3 = 0.f; }
                        size_t p0 = (size_t)z * cpStride + (size_t)r0 * ldcP + nn;
                        size_t p1 = (size_t)z * cpStride + (size_t)r1 * ldcP + nn;
                        *(__half2*)(Ch + p0) = __half2(__float2half_rn(v0), __float2half_rn(v1));
                        *(__half2*)(Ch + p1) = __half2(__float2half_rn(v2), __float2half_rn(v3));
                    }
                }
            }
        }
    } else {
        // OUTMODE 2: transposed HI-plane output via smem (reuse stage buffer)
        __half* ep = smbuf;   // [128 i][136 d]
        __syncthreads();
#pragma unroll
        for (int t = 0; t < 2; t++) {
            int d0 = warp_m * 32 + t * 16 + (lane >> 2);
            int d1 = d0 + 8;
#pragma unroll
            for (int j = 0; j < 8; j++) {
                int il = warp_n * 64 + j * 8 + 2 * (lane & 3);
                float v0 = acc[t][j][0], v1 = acc[t][j][1];
                float v2 = acc[t][j][2], v3 = acc[t][j][3];
                if (RELU) {
                    v0 = fmaxf(v0, 0.f); v1 = fmaxf(v1, 0.f);
                    v2 = fmaxf(v2, 0.f); v3 = fmaxf(v3, 0.f);
                }
                ep[il * 136 + d0]       = __float2half_rn(v0);
                ep[(il + 1) * 136 + d0] = __float2half_rn(v1);
                ep[il * 136 + d1]       = __float2half_rn(v2);
                ep[(il + 1) * 136 + d1] = __float2half_rn(v3);
            }
        }
        __syncthreads();
        __half* dst = Ch + (size_t)zb * cpStride + (size_t)zi * 128;
        for (int c2 = tid; c2 < 2048; c2 += 256) {
            int row = c2 >> 4, off = (c2 & 15) * 8;
            int i = n0 + row;
            if (i < NPIX) {
                uint4 val = *(uint4*)(ep + row * 136 + off);
                *(uint4*)(dst + (size_t)i * ldcP + off) = val;
            }
        }
    }
}

// ---------------- pre-convert kernels ----------------
__global__ void convert_weights(const float* __restrict__ qw, const float* __restrict__ pw)
{
    int i = blockIdx.x * 256 + threadIdx.x;
    if (i < HQKV * DIM) split_f16(qw[i], g_qw_h[i], g_qw_l[i]);
    if (i < DIM * DH)   g_pw_h[i] = __float2half_rn(pw[i]);
}

__global__ void transpose_x(const float* __restrict__ x)
{
    __shared__ float t[32][33];
    int p0 = blockIdx.x * 32, c0 = blockIdx.y * 32, b = blockIdx.z;
    for (int r = threadIdx.y; r < 32; r += 8) {
        int p = p0 + threadIdx.x;
        t[r][threadIdx.x] = (p < NPIX) ? x[((size_t)b * DIM + c0 + r) * NPIX + p] : 0.f;
    }
    __syncthreads();
    for (int r = threadIdx.y; r < 32; r += 8) {
        int p = p0 + r, c = c0 + threadIdx.x;
        if (p < NPIX) {
            size_t o = ((size_t)b * NPIX + p) * DIM + c;
            split_f16(t[threadIdx.x][r], g_xT_h[o], g_xT_l[o]);
        }
    }
}

// ---------------- dwconv + BN: 4 channels per block --------------------------
__global__ void __launch_bounds__(224, 8)
dwconv_bn(const float* __restrict__ w,
          const float* __restrict__ bng,
          const float* __restrict__ bnb,
          const float* __restrict__ bnm,
          const float* __restrict__ bnv)
{
    const int c0 = blockIdx.x * 4;
    const int b  = blockIdx.y;
    __shared__ float t[4][200];
    __shared__ float wgt[4][9];
    __shared__ float sBN[4][2];

    const float* src = g_qkv + (size_t)b * 768 * NPIX + (size_t)c0 * NPIX;
    int tid = threadIdx.x;
    for (int e = tid; e < 4 * NPIX; e += 224) {
        int ch = e / NPIX, p = e - ch * NPIX;
        t[ch][p] = src[ch * NPIX + p];
    }
    if (tid < 36) wgt[tid / 9][tid % 9] = w[c0 * 9 + tid];
    if (tid < 4) {
        int c = c0 + tid;
        float s = bng[c] * rsqrtf(bnv[c] + BN_EPS);
        sBN[tid][0] = s;
        sBN[tid][1] = bnb[c] - bnm[c] * s;
    }
    __syncthreads();

    if (tid < NPIX) {
        int y = tid / RES, x = tid - y * RES;
#pragma unroll
        for (int ch = 0; ch < 4; ch++) {
            float acc = 0.f;
#pragma unroll
            for (int ky = 0; ky < 3; ky++) {
                int yy = y + ky - 1;
                if (yy < 0 || yy >= RES) continue;
#pragma unroll
                for (int kx = 0; kx < 3; kx++) {
                    int xx = x + kx - 1;
                    if (xx < 0 || xx >= RES) continue;
                    acc += t[ch][yy * RES + xx] * wgt[ch][ky * 3 + kx];
                }
            }
            g_qdw[((size_t)b * NH_KD + c0 + ch) * NPIX + tid] = acc * sBN[ch][0] + sBN[ch][1];
        }
    }
}

// ---------------- softmax (fused bias gather): P fp16 hi plane --------------
__global__ void attn_softmax(const float* __restrict__ ab, const int* __restrict__ idxs)
{
    const int h = blockIdx.x;
    const int b = blockIdx.y;
    __shared__ float k_s[32 * 224];
    __shared__ float ab_s[NPIX];

    const float* qg = g_qdw + (size_t)b * NH_KD * NPIX + (size_t)h * KEY_DIM * NPIX;
    const float* kg = g_qkv + (size_t)b * 768 * NPIX + (size_t)(NH_KD + h * KEY_DIM) * NPIX;

    for (int idx = threadIdx.x; idx < 32 * 224; idx += 256) {
        int d = idx / 224, j = idx % 224;
        k_s[idx] = (j < NPIX) ? kg[d * NPIX + j] : 0.f;
    }
    if (threadIdx.x < NPIX) ab_s[threadIdx.x] = ab[h * NPIX + threadIdx.x];
    __syncthreads();

    const int w    = threadIdx.x >> 5;
    const int lane = threadIdx.x & 31;
    const size_t zoff = ((size_t)b * NHEADS + h) * NPIX * NPAD;
    const float scale = 0.17677669529663687f;

    for (int i0 = w * 4; i0 < NPIX; i0 += 32) {
        float q_reg[4];
#pragma unroll
        for (int r = 0; r < 4; r++) {
            int i = i0 + r;
            q_reg[r] = (i < NPIX) ? qg[(size_t)lane * NPIX + i] : 0.f;
        }

        float s[4][7];
#pragma unroll
        for (int r = 0; r < 4; r++)
#pragma unroll
            for (int m = 0; m < 7; m++) s[r][m] = 0.f;

        for (int d = 0; d < 32; d++) {
            float qv[4];
#pragma unroll
            for (int r = 0; r < 4; r++)
                qv[r] = __shfl_sync(0xffffffffu, q_reg[r], d);
#pragma unroll
            for (int m = 0; m < 7; m++) {
                float kv = k_s[d * 224 + lane + m * 32];
#pragma unroll
                for (int r = 0; r < 4; r++) s[r][m] += qv[r] * kv;
            }
        }

#pragma unroll
        for (int r = 0; r < 4; r++) {
            int i = i0 + r;
            if (i >= NPIX) break;
            float sv[7];
            float mx = -1e30f;
#pragma unroll
            for (int m = 0; m < 7; m++) {
                int j = lane + m * 32;
                float val;
                if (j < NPIX) {
                    int bi = idxs[(size_t)i * NPIX + j];
                    val = s[r][m] * scale + ab_s[bi];
                } else val = -1e30f;
                sv[m] = val;
                mx = fmaxf(mx, val);
            }
#pragma unroll
            for (int off = 16; off; off >>= 1)
                mx = fmaxf(mx, __shfl_xor_sync(0xffffffffu, mx, off));
            float sum = 0.f;
#pragma unroll
            for (int m = 0; m < 7; m++) {
                sv[m] = __expf(sv[m] - mx);
                sum += sv[m];
            }
#pragma unroll
            for (int off = 16; off; off >>= 1)
                sum += __shfl_xor_sync(0xffffffffu, sum, off);
            float inv = 1.f / sum;
#pragma unroll
            for (int m = 0; m < 7; m++) {
                int j = lane + m * 32;
                if (j < NPIX) {
                    g_p_h[zoff + (size_t)i * NPAD + j] = __float2half_rn(sv[m] * inv);
                } else if (j < NPAD) {
                    g_p_h[zoff + (size_t)i * NPAD + j] = __float2half_rn(0.f);
                }
            }
        }
    }
}

// ---------------- launch ----------------------------------------------------
extern "C" void kernel_launch(void* const* d_in, const int* in_sizes, int n_in,
                              void* d_out, int out_size)
{
    const float* x      = (const float*)d_in[0];
    const float* qkv_w  = (const float*)d_in[1];
    const float* qkv_g  = (const float*)d_in[2];
    const float* qkv_b  = (const float*)d_in[3];
    const float* qkv_m  = (const float*)d_in[4];
    const float* qkv_v  = (const float*)d_in[5];
    const float* dw_w   = (const float*)d_in[6];
    const float* dw_g   = (const float*)d_in[7];
    const float* dw_b   = (const float*)d_in[8];
    const float* dw_m   = (const float*)d_in[9];
    const float* dw_v   = (const float*)d_in[10];
    const float* proj_w = (const float*)d_in[11];
    const float* proj_g = (const float*)d_in[12];
    const float* proj_b = (const float*)d_in[13];
    const float* proj_m = (const float*)d_in[14];
    const float* proj_v = (const float*)d_in[15];
    const float* ab     = (const float*)d_in[16];
    const int*   bidx   = (const int*)d_in[17];
    float* out = (float*)d_out;

    float* qkvf;  cudaGetSymbolAddress((void**)&qkvf,  g_qkv);
    __half *qwh, *qwl, *pwh, *xth, *xtl, *vh, *ph, *ath;
    cudaGetSymbolAddress((void**)&qwh, g_qw_h);  cudaGetSymbolAddress((void**)&qwl, g_qw_l);
    cudaGetSymbolAddress((void**)&pwh, g_pw_h);
    cudaGetSymbolAddress((void**)&xth, g_xT_h);  cudaGetSymbolAddress((void**)&xtl, g_xT_l);
    cudaGetSymbolAddress((void**)&vh,  g_v_h);
    cudaGetSymbolAddress((void**)&ph,  g_p_h);
    cudaGetSymbolAddress((void**)&ath, g_at_h);

    // P0: convert weights + transpose/convert x
    convert_weights<<<(HQKV * DIM + 255) / 256, 256>>>(qkv_w, proj_w);
    transpose_x<<<dim3(7, 12, BATCH), dim3(32, 8)>>>(x);

    // K1a: q,k rows = BN(W_qkv[0:768] @ x)  3-term -> fp32   (K-chunk 16, 24 chunks)
    gemm_f16<0, true, false, 3><<<dim3(2, 768 / 128, BATCH), 256>>>(
        qwh, qwl, xth, xtl,
        qkvf, nullptr,
        DIM / 16, DIM, DIM,
        0L, 0L, 1,
        (long)NPIX * DIM, (long)768 * NPIX, 0L,
        NPIX, 0, NPIX,
        qkv_g, qkv_b, qkv_m, qkv_v);

    // K1b: V rows = BN(W_qkv_hi @ x_hi)  1-term -> fp16 hi   (K-chunk 32, 12 chunks)
    gemm_f16<3, true, false, 1><<<dim3(2, DH / 128, BATCH), 256>>>(
        qwh + (size_t)768 * DIM, nullptr, xth, nullptr,
        nullptr, vh,
        DIM / 32, DIM, DIM,
        0L, 0L, 1,
        (long)NPIX * DIM, 0L, (long)DH * NPAD,
        0, NPAD, NPIX,
        qkv_g + 768, qkv_b + 768, qkv_m + 768, qkv_v + 768);

    // K2: q <- BN(dwconv3x3(q))  (4 channels per block)
    dwconv_bn<<<dim3(NH_KD / 4, BATCH), 224>>>(dw_w, dw_g, dw_b, dw_m, dw_v);

    // K4: softmax (fused bias) -> P hi plane
    attn_softmax<<<dim3(NHEADS, BATCH), 256>>>(ab, bidx);

    // K5: attT hi = relu(V_hi @ P^T)^T  1-term  (K-chunk 32, 7 chunks)
    gemm_f16<2, false, true, 1><<<dim3(2, 1, BATCH * NHEADS), 256>>>(
        vh, nullptr, ph, nullptr,
        nullptr, ath,
        NPAD / 32, NPAD, NPAD,
        (long)DH * NPAD, (long)128 * NPAD, NHEADS,
        (long)NPIX * NPAD, 0L, (long)NPIX * DH,
        0, DH, NPIX,
        nullptr, nullptr, nullptr, nullptr);

    // K6: out = BN(W_proj_hi @ att)  1-term  (K-chunk 32, 48 chunks)
    gemm_f16<0, true, false, 1><<<dim3(2, DIM / 128, BATCH), 256>>>(
        pwh, nullptr, ath, nullptr,
        out, nullptr,
        DH / 32, DH, DH,
        0L, 0L, 1,
        (long)NPIX * DH, (long)DIM * NPIX, 0L,
        NPIX, 0, NPIX,
        proj_g, proj_b, proj_m, proj_v);
}

// round 16
// speedup vs baseline: 1.9666x; 1.0002x over previous
#include <cuda_runtime.h>
#include <cuda_fp16.h>
#include <math.h>
#include <stdint.h>

// ---------------- constants ----------------
#define BATCH   128
#define DIM     384
#define RES     14
#define NPIX    196
#define KEY_DIM 32
#define NHEADS  12
#define NH_KD   384
#define DH      1536
#define HQKV    2304
#define BN_EPS  1e-5f
#define NPAD    224     // NPIX padded to mult of 32

// ---------------- scratch ----------------
__device__ float g_qkv [ (size_t)BATCH * 768 * NPIX ];            // q+k fp32 only
__device__ float g_qdw [ (size_t)BATCH * NH_KD * NPIX ];

__device__ __half g_qw_h[ HQKV * DIM ],  g_qw_l[ HQKV * DIM ];
__device__ __half g_pw_h[ DIM * DH ];
__device__ __half g_xT_h[ (size_t)BATCH * NPIX * DIM ],  g_xT_l[ (size_t)BATCH * NPIX * DIM ];
__device__ __half g_v_h [ (size_t)BATCH * DH * NPAD ];              // hi plane only
__device__ __half g_p_h [ (size_t)BATCH * NHEADS * NPIX * NPAD ];   // hi plane only
__device__ __half g_at_h[ (size_t)BATCH * NPIX * DH ];              // hi plane only

// ---------------- helpers ----------------
__device__ __forceinline__ uint32_t smem_u32(const void* p) {
    uint32_t a;
    asm("{ .reg .u64 t; cvta.to.shared.u64 t, %1; cvt.u32.u64 %0, t; }"
        : "=r"(a) : "l"(p));
    return a;
}
#define LDSM4(r, addr) \
    asm volatile("ldmatrix.sync.aligned.m8n8.x4.shared.b16 {%0,%1,%2,%3}, [%4];" \
        : "=r"((r)[0]), "=r"((r)[1]), "=r"((r)[2]), "=r"((r)[3]) : "r"(addr))
#define MMA_F16(d, a, bb) \
    asm volatile("mma.sync.aligned.m16n8k16.row.col.f32.f16.f16.f32 " \
        "{%0,%1,%2,%3}, {%4,%5,%6,%7}, {%8,%9}, {%0,%1,%2,%3};" \
        : "+f"((d)[0]), "+f"((d)[1]), "+f"((d)[2]), "+f"((d)[3]) \
        : "r"((a)[0]), "r"((a)[1]), "r"((a)[2]), "r"((a)[3]), \
          "r"((bb)[0]), "r"((bb)[1]))
#define CP_ASYNC16(dst, src, sz) \
    asm volatile("cp.async.cg.shared.global [%0], [%1], 16, %2;" \
                 :: "r"(dst), "l"(src), "r"(sz))
#define CP_COMMIT() asm volatile("cp.async.commit_group;" ::: "memory")
#define CP_WAIT(n)  asm volatile("cp.async.wait_group %0;" :: "n"(n) : "memory")

__device__ __forceinline__ void split_f16(float v, __half& h, __half& l) {
    h = __float2half_rn(v);
    l = __float2half_rn(v - __half2float(h));
}

// ================= multistage fp16-plane GEMM (unchanged from R15) ==========
template<int OUTMODE, bool HASBN, bool RELU, int TERMS>
__global__ void __launch_bounds__(256, 2)
gemm_f16(const __half* __restrict__ Ah, const __half* __restrict__ Al,
         const __half* __restrict__ Bh, const __half* __restrict__ Bl,
         float* __restrict__ Cf, __half* __restrict__ Ch,
         int nchunks, int lda, int ldb,
         long aOuter, long aInner, int innerCnt,
         long bStride, long cfStride, long cpStride,
         int ldcF, int ldcP, int nrowsB,
         const float* __restrict__ bng, const float* __restrict__ bnb,
         const float* __restrict__ bnm, const float* __restrict__ bnv)
{
    constexpr int KSTEPS = (TERMS == 1) ? 2 : 1;
    constexpr int KPA = 40;
    constexpr int KPB = 40;
    constexpr uint32_t A_BYTES = 128 * KPA * 2;
    constexpr uint32_t B_BYTES = 128 * KPB * 2;
    constexpr uint32_t STAGE   = A_BYTES + B_BYTES;
    constexpr int NSTAGE = 2;
    __shared__ __align__(16) __half smbuf[(NSTAGE * STAGE) / 2];

    const int tid  = threadIdx.x;
    const int wid  = tid >> 5;
    const int lane = tid & 31;
    const int warp_m = wid & 3;
    const int warp_n = wid >> 2;
    const int n0 = blockIdx.x * 128;
    const int m0 = blockIdx.y * 128;
    const int z  = blockIdx.z;
    const int zb = z / innerCnt, zi = z - zb * innerCnt;

    const __half* Agh = Ah + (size_t)zb * aOuter + (size_t)zi * aInner + (size_t)m0 * lda;
    const __half* Agl = (TERMS >= 2) ? (Al + (size_t)zb * aOuter + (size_t)zi * aInner + (size_t)m0 * lda) : nullptr;
    const __half* Bgh = Bh + (size_t)z * bStride;
    const __half* Bgl = (TERMS == 3) ? (Bl + (size_t)z * bStride) : nullptr;

    const uint32_t smb = smem_u32(smbuf);

    const bool full = (n0 + warp_n * 64 + 64) <= nrowsB;
    int jlim = nrowsB - (n0 + warp_n * 64);
    jlim = jlim <= 0 ? 0 : ((jlim + 7) >> 3);
    if (jlim > 8) jlim = 8;

    auto stage = [&](int ch, int s) {
        const int k0 = ch * 16 * KSTEPS;
        const uint32_t sb = smb + (uint32_t)s * STAGE;
#pragma unroll
        for (int i = 0; i < 2; i++) {
            int idx = i * 256 + tid;
            int row = idx >> 2;
            int p   = idx & 3;
            const __half* src;
            if (TERMS >= 2)
                src = (p < 2 ? Agh : Agl) + (size_t)row * lda + k0 + (p & 1) * 8;
            else
                src = Agh + (size_t)row * lda + k0 + p * 8;
            uint32_t dst = sb + (uint32_t)(row * KPA + p * 8) * 2;
            CP_ASYNC16(dst, src, 16u);
        }
        if (TERMS == 3) {
#pragma unroll
            for (int i = 0; i < 2; i++) {
                int idx = i * 256 + tid;
                int row = idx >> 2;
                int p   = idx & 3;
                int rowg = n0 + row;
                unsigned sz = 16u;
                if (rowg >= nrowsB) { rowg = 0; sz = 0u; }
                const __half* src = (p < 2 ? Bgh : Bgl) + (size_t)rowg * ldb + k0 + (p & 1) * 8;
                uint32_t dst = sb + A_BYTES + (uint32_t)(row * KPB + p * 8) * 2;
                CP_ASYNC16(dst, src, sz);
            }
        } else {
#pragma unroll
            for (int i = 0; i < 2; i++) {
                int idx = i * 256 + tid;
                int row = idx >> 2;
                int p   = idx & 3;
                int rowg = n0 + row;
                unsigned sz = 16u;
                if (rowg >= nrowsB) { rowg = 0; sz = 0u; }
                const __half* src = Bgh + (size_t)rowg * ldb + k0 + p * 8;
                uint32_t dst = sb + A_BYTES + (uint32_t)(row * KPB + p * 8) * 2;
                CP_ASYNC16(dst, src, sz);
            }
        }
        CP_COMMIT();
    };

    float acc[2][8][4];
#pragma unroll
    for (int t = 0; t < 2; t++)
#pragma unroll
        for (int j = 0; j < 8; j++)
#pragma unroll
            for (int c = 0; c < 4; c++) acc[t][j][c] = 0.f;

    stage(0, 0);

    for (int ch = 0; ch < nchunks; ch++) {
        CP_WAIT(0);
        __syncthreads();

        {
            int nx = ch + 1;
            if (nx < nchunks) stage(nx, nx & 1);
            else CP_COMMIT();
        }

        const uint32_t base  = smb + (uint32_t)(ch & 1) * STAGE;
        const uint32_t aBase = base;
        const uint32_t bBase = base + A_BYTES;

#pragma unroll
        for (int ks = 0; ks < KSTEPS; ks++) {
            const int kel = ks * 16;
            uint32_t a_hi[2][4], a_lo[2][4];
#pragma unroll
            for (int t = 0; t < 2; t++) {
                int row = warp_m * 32 + t * 16 + (lane & 15);
                int col = kel + ((lane >> 4) << 3);
                uint32_t off = (uint32_t)(row * KPA + col) * 2;
                LDSM4(a_hi[t], aBase + off);
                if (TERMS >= 2) LDSM4(a_lo[t], aBase + off + 32);
            }
            int nrow = warp_n * 64 + (lane & 7) + ((lane >> 4) << 3);
            int bcol = kel + (((lane >> 3) & 1) << 3);
            uint32_t boff = (uint32_t)(nrow * KPB + bcol) * 2;

            if (full) {
                uint32_t b[8][2];
#pragma unroll
                for (int j = 0; j < 4; j++) {
                    uint32_t r[4];
                    LDSM4(r, bBase + boff + (uint32_t)(j * 16 * KPB) * 2);
                    b[2 * j][0] = r[0]; b[2 * j][1] = r[1];
                    b[2 * j + 1][0] = r[2]; b[2 * j + 1][1] = r[3];
                }
#pragma unroll
                for (int t = 0; t < 2; t++)
#pragma unroll
                    for (int j = 0; j < 8; j++) MMA_F16(acc[t][j], a_hi[t], b[j]);
                if (TERMS >= 2) {
#pragma unroll
                    for (int t = 0; t < 2; t++)
#pragma unroll
                        for (int j = 0; j < 8; j++) MMA_F16(acc[t][j], a_lo[t], b[j]);
                }
                if (TERMS == 3) {
#pragma unroll
                    for (int j = 0; j < 4; j++) {
                        uint32_t r[4];
                        LDSM4(r, bBase + boff + 32 + (uint32_t)(j * 16 * KPB) * 2);
                        b[2 * j][0] = r[0]; b[2 * j][1] = r[1];
                        b[2 * j + 1][0] = r[2]; b[2 * j + 1][1] = r[3];
                    }
#pragma unroll
                    for (int t = 0; t < 2; t++)
#pragma unroll
                        for (int j = 0; j < 8; j++) MMA_F16(acc[t][j], a_hi[t], b[j]);
                }
            } else if (jlim > 0) {
                uint32_t b2[2][2];
                {
                    uint32_t r[4];
                    LDSM4(r, bBase + boff);
                    b2[0][0] = r[0]; b2[0][1] = r[1];
                    b2[1][0] = r[2]; b2[1][1] = r[3];
                }
#pragma unroll
                for (int t = 0; t < 2; t++)
#pragma unroll
                    for (int j = 0; j < 2; j++)
                        if (j < jlim) MMA_F16(acc[t][j], a_hi[t], b2[j]);
                if (TERMS >= 2) {
#pragma unroll
                    for (int t = 0; t < 2; t++)
#pragma unroll
                        for (int j = 0; j < 2; j++)
                            if (j < jlim) MMA_F16(acc[t][j], a_lo[t], b2[j]);
                }
                if (TERMS == 3) {
                    uint32_t r[4];
                    LDSM4(r, bBase + boff + 32);
                    b2[0][0] = r[0]; b2[0][1] = r[1];
                    b2[1][0] = r[2]; b2[1][1] = r[3];
#pragma unroll
                    for (int t = 0; t < 2; t++)
#pragma unroll
                        for (int j = 0; j < 2; j++)
                            if (j < jlim) MMA_F16(acc[t][j], a_hi[t], b2[j]);
                }
            }
        }
    }

    // ---------------- epilogues ----------------
    if (OUTMODE == 0 || OUTMODE == 3) {
#pragma unroll
        for (int t = 0; t < 2; t++) {
            int r0 = m0 + warp_m * 32 + t * 16 + (lane >> 2);
            int r1 = r0 + 8;
            float s0 = 1.f, h0 = 0.f, s1 = 1.f, h1 = 0.f;
            if (HASBN) {
                float a = bng[r0] * rsqrtf(bnv[r0] + BN_EPS);
                s0 = a; h0 = bnb[r0] - bnm[r0] * a;
                float c = bng[r1] * rsqrtf(bnv[r1] + BN_EPS);
                s1 = c; h1 = bnb[r1] - bnm[r1] * c;
            }
#pragma unroll
            for (int j = 0; j < 8; j++) {
                int nn = n0 + warp_n * 64 + j * 8 + 2 * (lane & 3);
                float v0 = acc[t][j][0] * s0 + h0;
                float v1 = acc[t][j][1] * s0 + h0;
                float v2 = acc[t][j][2] * s1 + h1;
                float v3 = acc[t][j][3] * s1 + h1;
                if (RELU) {
                    v0 = fmaxf(v0, 0.f); v1 = fmaxf(v1, 0.f);
                    v2 = fmaxf(v2, 0.f); v3 = fmaxf(v3, 0.f);
                }
                if (OUTMODE == 0) {
                    if (nn < NPIX) {
                        *(float2*)(Cf + (size_t)z * cfStride + (size_t)r0 * ldcF + nn) = make_float2(v0, v1);
                        *(float2*)(Cf + (size_t)z * cfStride + (size_t)r1 * ldcF + nn) = make_float2(v2, v3);
                    }
                } else {
                    if (nn < NPAD) {
                        if (nn >= NPIX) { v0 = v1 = v2 = v3 = 0.f; }
                        size_t p0 = (size_t)z * cpStride + (size_t)r0 * ldcP + nn;
                        size_t p1 = (size_t)z * cpStride + (size_t)r1 * ldcP + nn;
                        *(__half2*)(Ch + p0) = __half2(__float2half_rn(v0), __float2half_rn(v1));
                        *(__half2*)(Ch + p1) = __half2(__float2half_rn(v2), __float2half_rn(v3));
                    }
                }
            }
        }
    } else {
        __half* ep = smbuf;   // [128 i][136 d]
        __syncthreads();
#pragma unroll
        for (int t = 0; t < 2; t++) {
            int d0 = warp_m * 32 + t * 16 + (lane >> 2);
            int d1 = d0 + 8;
#pragma unroll
            for (int j = 0; j < 8; j++) {
                int il = warp_n * 64 + j * 8 + 2 * (lane & 3);
                float v0 = acc[t][j][0], v1 = acc[t][j][1];
                float v2 = acc[t][j][2], v3 = acc[t][j][3];
                if (RELU) {
                    v0 = fmaxf(v0, 0.f); v1 = fmaxf(v1, 0.f);
                    v2 = fmaxf(v2, 0.f); v3 = fmaxf(v3, 0.f);
                }
                ep[il * 136 + d0]       = __float2half_rn(v0);
                ep[(il + 1) * 136 + d0] = __float2half_rn(v1);
                ep[il * 136 + d1]       = __float2half_rn(v2);
                ep[(il + 1) * 136 + d1] = __float2half_rn(v3);
            }
        }
        __syncthreads();
        __half* dst = Ch + (size_t)zb * cpStride + (size_t)zi * 128;
        for (int c2 = tid; c2 < 2048; c2 += 256) {
            int row = c2 >> 4, off = (c2 & 15) * 8;
            int i = n0 + row;
            if (i < NPIX) {
                uint4 val = *(uint4*)(ep + row * 136 + off);
                *(uint4*)(dst + (size_t)i * ldcP + off) = val;
            }
        }
    }
}

// ---------------- pre-convert kernels ----------------
__global__ void convert_weights(const float* __restrict__ qw, const float* __restrict__ pw)
{
    int i = blockIdx.x * 256 + threadIdx.x;
    if (i < HQKV * DIM) split_f16(qw[i], g_qw_h[i], g_qw_l[i]);
    if (i < DIM * DH)   g_pw_h[i] = __float2half_rn(pw[i]);
}

// transpose x: [B, DIM, NPIX] -> xT hi/lo [B, NPIX, DIM], half2 stores.
// tile: 32 pixels x 64 channels; block (32,8).
__global__ void transpose_x(const float* __restrict__ x)
{
    __shared__ float t[64][33];
    int p0 = blockIdx.x * 32, c0 = blockIdx.y * 64, b = blockIdx.z;
    int tx = threadIdx.x, ty = threadIdx.y;
    for (int r = ty; r < 64; r += 8) {
        int p = p0 + tx;
        t[r][tx] = (p < NPIX) ? x[((size_t)b * DIM + c0 + r) * NPIX + p] : 0.f;
    }
    __syncthreads();
    for (int r = ty; r < 32; r += 8) {
        int p = p0 + r;
        if (p < NPIX) {
            float v0 = t[2 * tx][r], v1 = t[2 * tx + 1][r];
            __half h0, l0, h1, l1;
            split_f16(v0, h0, l0);
            split_f16(v1, h1, l1);
            size_t o = ((size_t)b * NPIX + p) * DIM + c0 + 2 * tx;
            *(__half2*)(g_xT_h + o) = __half2(h0, h1);
            *(__half2*)(g_xT_l + o) = __half2(l0, l1);
        }
    }
}

// ---------------- dwconv + BN: 4 channels per block --------------------------
__global__ void __launch_bounds__(224, 8)
dwconv_bn(const float* __restrict__ w,
          const float* __restrict__ bng,
          const float* __restrict__ bnb,
          const float* __restrict__ bnm,
          const float* __restrict__ bnv)
{
    const int c0 = blockIdx.x * 4;
    const int b  = blockIdx.y;
    __shared__ float t[4][200];
    __shared__ float wgt[4][9];
    __shared__ float sBN[4][2];

    const float* src = g_qkv + (size_t)b * 768 * NPIX + (size_t)c0 * NPIX;
    int tid = threadIdx.x;
    for (int e = tid; e < 4 * NPIX; e += 224) {
        int ch = e / NPIX, p = e - ch * NPIX;
        t[ch][p] = src[ch * NPIX + p];
    }
    if (tid < 36) wgt[tid / 9][tid % 9] = w[c0 * 9 + tid];
    if (tid < 4) {
        int c = c0 + tid;
        float s = bng[c] * rsqrtf(bnv[c] + BN_EPS);
        sBN[tid][0] = s;
        sBN[tid][1] = bnb[c] - bnm[c] * s;
    }
    __syncthreads();

    if (tid < NPIX) {
        int y = tid / RES, x = tid - y * RES;
#pragma unroll
        for (int ch = 0; ch < 4; ch++) {
            float acc = 0.f;
#pragma unroll
            for (int ky = 0; ky < 3; ky++) {
                int yy = y + ky - 1;
                if (yy < 0 || yy >= RES) continue;
#pragma unroll
                for (int kx = 0; kx < 3; kx++) {
                    int xx = x + kx - 1;
                    if (xx < 0 || xx >= RES) continue;
                    acc += t[ch][yy * RES + xx] * wgt[ch][ky * 3 + kx];
                }
            }
            g_qdw[((size_t)b * NH_KD + c0 + ch) * NPIX + tid] = acc * sBN[ch][0] + sBN[ch][1];
        }
    }
}

// ---------------- softmax (fused bias, row-split x2): P fp16 hi plane -------
__global__ void attn_softmax(const float* __restrict__ ab, const int* __restrict__ idxs)
{
    const int h  = blockIdx.x;
    const int b  = blockIdx.y;
    const int zi = blockIdx.z;          // 0 or 1: rows [98*zi, 98*zi+98)
    __shared__ float k_s[32 * 224];
    __shared__ float ab_s[NPIX];

    const float* qg = g_qdw + (size_t)b * NH_KD * NPIX + (size_t)h * KEY_DIM * NPIX;
    const float* kg = g_qkv + (size_t)b * 768 * NPIX + (size_t)(NH_KD + h * KEY_DIM) * NPIX;

    for (int idx = threadIdx.x; idx < 32 * 224; idx += 256) {
        int d = idx / 224, j = idx % 224;
        k_s[idx] = (j < NPIX) ? kg[d * NPIX + j] : 0.f;
    }
    if (threadIdx.x < NPIX) ab_s[threadIdx.x] = ab[h * NPIX + threadIdx.x];
    __syncthreads();

    const int w    = threadIdx.x >> 5;
    const int lane = threadIdx.x & 31;
    const size_t zoff = ((size_t)b * NHEADS + h) * NPIX * NPAD;
    const float scale = 0.17677669529663687f;
    const int ibase = 98 * zi;
    const int iend  = ibase + 98;       // 98*2 = 196 exactly

    for (int i0 = ibase + w * 4; i0 < iend; i0 += 32) {
        float q_reg[4];
#pragma unroll
        for (int r = 0; r < 4; r++) {
            int i = i0 + r;
            q_reg[r] = (i < iend) ? qg[(size_t)lane * NPIX + i] : 0.f;
        }

        float s[4][7];
#pragma unroll
        for (int r = 0; r < 4; r++)
#pragma unroll
            for (int m = 0; m < 7; m++) s[r][m] = 0.f;

        for (int d = 0; d < 32; d++) {
            float qv[4];
#pragma unroll
            for (int r = 0; r < 4; r++)
                qv[r] = __shfl_sync(0xffffffffu, q_reg[r], d);
#pragma unroll
            for (int m = 0; m < 7; m++) {
                float kv = k_s[d * 224 + lane + m * 32];
#pragma unroll
                for (int r = 0; r < 4; r++) s[r][m] += qv[r] * kv;
            }
        }

#pragma unroll
        for (int r = 0; r < 4; r++) {
            int i = i0 + r;
            if (i >= iend) break;
            float sv[7];
            float mx = -1e30f;
#pragma unroll
            for (int m = 0; m < 7; m++) {
                int j = lane + m * 32;
                float val;
                if (j < NPIX) {
                    int bi = idxs[(size_t)i * NPIX + j];
                    val = s[r][m] * scale + ab_s[bi];
                } else val = -1e30f;
                sv[m] = val;
                mx = fmaxf(mx, val);
            }
#pragma unroll
            for (int off = 16; off; off >>= 1)
                mx = fmaxf(mx, __shfl_xor_sync(0xffffffffu, mx, off));
            float sum = 0.f;
#pragma unroll
            for (int m = 0; m < 7; m++) {
                sv[m] = __expf(sv[m] - mx);
                sum += sv[m];
            }
#pragma unroll
            for (int off = 16; off; off >>= 1)
                sum += __shfl_xor_sync(0xffffffffu, sum, off);
            float inv = 1.f / sum;
#pragma unroll
            for (int m = 0; m < 7; m++) {
                int j = lane + m * 32;
                if (j < NPIX) {
                    g_p_h[zoff + (size_t)i * NPAD + j] = __float2half_rn(sv[m] * inv);
                } else if (j < NPAD) {
                    g_p_h[zoff + (size_t)i * NPAD + j] = __float2half_rn(0.f);
                }
            }
        }
    }
}

// ---------------- launch ----------------------------------------------------
extern "C" void kernel_launch(void* const* d_in, const int* in_sizes, int n_in,
                              void* d_out, int out_size)
{
    const float* x      = (const float*)d_in[0];
    const float* qkv_w  = (const float*)d_in[1];
    const float* qkv_g  = (const float*)d_in[2];
    const float* qkv_b  = (const float*)d_in[3];
    const float* qkv_m  = (const float*)d_in[4];
    const float* qkv_v  = (const float*)d_in[5];
    const float* dw_w   = (const float*)d_in[6];
    const float* dw_g   = (const float*)d_in[7];
    const float* dw_b   = (const float*)d_in[8];
    const float* dw_m   = (const float*)d_in[9];
    const float* dw_v   = (const float*)d_in[10];
    const float* proj_w = (const float*)d_in[11];
    const float* proj_g = (const float*)d_in[12];
    const float* proj_b = (const float*)d_in[13];
    const float* proj_m = (const float*)d_in[14];
    const float* proj_v = (const float*)d_in[15];
    const float* ab     = (const float*)d_in[16];
    const int*   bidx   = (const int*)d_in[17];
    float* out = (float*)d_out;

    float* qkvf;  cudaGetSymbolAddress((void**)&qkvf,  g_qkv);
    __half *qwh, *qwl, *pwh, *xth, *xtl, *vh, *ph, *ath;
    cudaGetSymbolAddress((void**)&qwh, g_qw_h);  cudaGetSymbolAddress((void**)&qwl, g_qw_l);
    cudaGetSymbolAddress((void**)&pwh, g_pw_h);
    cudaGetSymbolAddress((void**)&xth, g_xT_h);  cudaGetSymbolAddress((void**)&xtl, g_xT_l);
    cudaGetSymbolAddress((void**)&vh,  g_v_h);
    cudaGetSymbolAddress((void**)&ph,  g_p_h);
    cudaGetSymbolAddress((void**)&ath, g_at_h);

    // P0: convert weights + transpose/convert x
    convert_weights<<<(HQKV * DIM + 255) / 256, 256>>>(qkv_w, proj_w);
    transpose_x<<<dim3(7, 6, BATCH), dim3(32, 8)>>>(x);

    // K1a: q,k rows = BN(W_qkv[0:768] @ x)  3-term -> fp32   (K-chunk 16)
    gemm_f16<0, true, false, 3><<<dim3(2, 768 / 128, BATCH), 256>>>(
        qwh, qwl, xth, xtl,
        qkvf, nullptr,
        DIM / 16, DIM, DIM,
        0L, 0L, 1,
        (long)NPIX * DIM, (long)768 * NPIX, 0L,
        NPIX, 0, NPIX,
        qkv_g, qkv_b, qkv_m, qkv_v);

    // K1b: V rows = BN(W_qkv_hi @ x_hi)  1-term -> fp16 hi   (K-chunk 32)
    gemm_f16<3, true, false, 1><<<dim3(2, DH / 128, BATCH), 256>>>(
        qwh + (size_t)768 * DIM, nullptr, xth, nullptr,
        nullptr, vh,
        DIM / 32, DIM, DIM,
        0L, 0L, 1,
        (long)NPIX * DIM, 0L, (long)DH * NPAD,
        0, NPAD, NPIX,
        qkv_g + 768, qkv_b + 768, qkv_m + 768, qkv_v + 768);

    // K2: q <- BN(dwconv3x3(q))  (4 channels per block)
    dwconv_bn<<<dim3(NH_KD / 4, BATCH), 224>>>(dw_w, dw_g, dw_b, dw_m, dw_v);

    // K4: softmax (fused bias, 2-way row split) -> P hi plane
    attn_softmax<<<dim3(NHEADS, BATCH, 2), 256>>>(ab, bidx);

    // K5: attT hi = relu(V_hi @ P^T)^T  1-term  (K-chunk 32)
    gemm_f16<2, false, true, 1><<<dim3(2, 1, BATCH * NHEADS), 256>>>(
        vh, nullptr, ph, nullptr,
        nullptr, ath,
        NPAD / 32, NPAD, NPAD,
        (long)DH * NPAD, (long)128 * NPAD, NHEADS,
        (long)NPIX * NPAD, 0L, (long)NPIX * DH,
        0, DH, NPIX,
        nullptr, nullptr, nullptr, nullptr);

    // K6: out = BN(W_proj_hi @ att)  1-term  (K-chunk 32)
    gemm_f16<0, true, false, 1><<<dim3(2, DIM / 128, BATCH), 256>>>(
        pwh, nullptr, ath, nullptr,
        out, nullptr,
        DH / 32, DH, DH,
        0L, 0L, 1,
        (long)NPIX * DH, (long)DIM * NPIX, 0L,
        NPIX, 0, NPIX,
        proj_g, proj_b, proj_m, proj_v);
}